// round 12
// baseline (speedup 1.0000x reference)
#include <cuda_runtime.h>
#include <cuda_bf16.h>
#include <cuda_fp16.h>
#include <math.h>

#define NB 16
#define NPRED 25200
#define NCLS 80
#define KDET 300
#define NP 128
#define NINST (NB*KDET)
#define ST_CH 1152
#define KTOT 1152

typedef unsigned long long u64;
typedef unsigned int u32;
typedef __nv_bfloat16 bf16;

__device__ __forceinline__ void ffma2(u64& acc, u64 a, u64 b){
    asm("fma.rn.f32x2 %0, %1, %2, %3;" : "=l"(acc) : "l"(a), "l"(b), "l"(acc));
}
__device__ __forceinline__ u64 bcast2(float x){
    u64 r;
    asm("mov.b64 %0, {%1, %1};" : "=l"(r) : "r"(__float_as_uint(x)));
    return r;
}
__device__ __forceinline__ float2 unpack2(u64 v){
    float2 f;
    asm("mov.b64 {%0, %1}, %2;" : "=f"(f.x), "=f"(f.y) : "l"(v));
    return f;
}
__device__ __forceinline__ u32 s2u(const void* p){
    u32 a; asm("{ .reg .u64 t; cvta.to.shared.u64 t, %1; cvt.u32.u64 %0, t; }" : "=r"(a) : "l"(p));
    return a;
}
__device__ __forceinline__ void cpa16(u32 dst, const void* src){
    asm volatile("cp.async.cg.shared.global [%0], [%1], 16;" :: "r"(dst), "l"(src));
}
#define CP_COMMIT() asm volatile("cp.async.commit_group;" ::: "memory")
#define CP_WAIT0()  asm volatile("cp.async.wait_group 0;" ::: "memory")

__device__ __forceinline__ void ldsm_x4(u32* r, u32 addr){
    asm volatile("ldmatrix.sync.aligned.m8n8.x4.shared.b16 {%0,%1,%2,%3}, [%4];"
        : "=r"(r[0]), "=r"(r[1]), "=r"(r[2]), "=r"(r[3]) : "r"(addr));
}

// ---------------- device scratch ----------------
__device__ float g_score[NB*NPRED];
__device__ int   g_cls[NB*NPRED];
__device__ int   g_topidx[NINST];
__device__ float g_tops[NINST];
__device__ float g_boxes[NINST*4];
__device__ float g_det[NINST*6];
__device__ float g_ct[NINST*2];
__device__ float g_half[NINST*2];
__device__ float g_clsf[NINST];
__device__ int   g_valid[NINST];
__device__ float g_up[(size_t)NB*128*160*160];
__device__ __half g_cfh[(size_t)NB*160*160*64];   // channel-last f16 features
__device__ float g_pts[NINST*NP*2];
__device__ float g_off[NINST*2*NP];
__device__ float g_hbuf[(size_t)NINST*64*NP];
__device__ bf16  g_states[(size_t)NINST*ST_CH*NP];   // [inst][ch][p]
__device__ bf16  g_fuse[(size_t)NINST*256*NP];
__device__ bf16  g_whb[128*KTOT];      // head W [o][k=t*128+c]
__device__ bf16  g_wrb[7*128*KTOT];    // res  W [l][o][k=t*128+c]
__device__ bf16  g_wfb[256*KTOT];      // fuse W [o][k]
__device__ float g_wp1t[256*64];       // p1 W [k][o]

// ---------------- weight transposition ----------------
__global__ void k_wtrans(const float* __restrict__ wh, const float* __restrict__ wr,
                         const float* __restrict__ wf, const float* __restrict__ wp1)
{
    int i = blockIdx.x*blockDim.x + threadIdx.x;
    const int n1 = 128*KTOT;
    const int n2 = 7*128*KTOT;
    const int n3 = 256*KTOT;
    const int n4 = 256*64;
    if (i < n1){
        int o = i / KTOT, k = i % KTOT, t = k >> 7, c = k & 127;
        g_whb[i] = __float2bfloat16(c < 66 ? wh[(o*66 + c)*9 + t] : 0.f);
        return;
    }
    i -= n1;
    if (i < n2){
        int l = i / (128*KTOT), r = i % (128*KTOT);
        int o = r / KTOT, k = r % KTOT, t = k >> 7, c = k & 127;
        g_wrb[i] = __float2bfloat16(wr[(((size_t)l*128 + o)*128 + c)*9 + t]);
        return;
    }
    i -= n2;
    if (i < n3){
        int o = i / KTOT, k = i % KTOT;
        float v = 0.f;
        if (k < 66) v = wf[o*1090 + k];
        else if (k >= 128) v = wf[o*1090 + k - 62];
        g_wfb[i] = __float2bfloat16(v);
        return;
    }
    i -= n3;
    if (i < n4){
        int o = i & 63, k = i >> 6;
        g_wp1t[i] = wp1[o*256 + k];
    }
}

// ---------------- stage 1: scores ----------------
__global__ void k_scores(const float* __restrict__ pred){
    int i = blockIdx.x*blockDim.x + threadIdx.x;
    if (i >= NB*NPRED) return;
    const float* r = pred + (size_t)i*85;
    float obj = r[4];
    float best = -1e30f; int bc = 0;
    for (int c = 0; c < NCLS; c++){
        float s = obj * r[5+c];
        if (s > best){ best = s; bc = c; }
    }
    g_score[i] = (best > 0.2f) ? best : 0.0f;
    g_cls[i] = bc;
}

// ---------------- stage 2: stable top-300 ----------------
__global__ void __launch_bounds__(1024) k_topk(){
    extern __shared__ unsigned long long smk[];
    unsigned long long* keys = smk;
    unsigned long long* l1   = smk + 25600;
    __shared__ unsigned long long red[32];
    int b = blockIdx.x, tid = threadIdx.x;
    for (int i = tid; i < 25600; i += 1024){
        unsigned long long k = 0ULL;
        if (i < NPRED){
            unsigned u = __float_as_uint(g_score[b*NPRED + i]);
            k = ((unsigned long long)u << 32) | (unsigned)(~i);
        }
        keys[i] = k;
    }
    __syncthreads();
    if (tid < 800){
        unsigned long long m = 0ULL;
        for (int j = 0; j < 32; j++){ unsigned long long v = keys[tid*32 + j]; if (v > m) m = v; }
        l1[tid] = m;
    }
    __syncthreads();
    for (int it = 0; it < KDET; it++){
        unsigned long long v = (tid < 800) ? l1[tid] : 0ULL;
        #pragma unroll
        for (int o = 16; o > 0; o >>= 1){
            unsigned long long t2 = __shfl_down_sync(0xffffffffu, v, o);
            if (t2 > v) v = t2;
        }
        if ((tid & 31) == 0) red[tid >> 5] = v;
        __syncthreads();
        if (tid < 32){
            v = red[tid];
            #pragma unroll
            for (int o = 16; o > 0; o >>= 1){
                unsigned long long t2 = __shfl_down_sync(0xffffffffu, v, o);
                if (t2 > v) v = t2;
            }
            if (tid == 0) red[0] = v;
        }
        __syncthreads();
        unsigned long long w = red[0];
        int idx = (int)(~(unsigned)w);
        if (tid < 32){
            int ch = idx >> 5;
            if (tid == 0) keys[idx] = 0ULL;
            __syncwarp();
            unsigned long long kv = keys[ch*32 + tid];
            #pragma unroll
            for (int o = 16; o > 0; o >>= 1){
                unsigned long long t2 = __shfl_down_sync(0xffffffffu, kv, o);
                if (t2 > kv) kv = t2;
            }
            if (tid == 0){
                l1[ch] = kv;
                g_topidx[b*KDET + it] = idx;
                g_tops[b*KDET + it] = __uint_as_float((unsigned)(w >> 32));
            }
        }
        __syncthreads();
    }
}

// ---------------- stage 3 ----------------
__global__ void k_prep(const float* __restrict__ pred){
    int i = blockIdx.x*blockDim.x + threadIdx.x;
    if (i >= NINST) return;
    int b = i / KDET;
    int src = g_topidx[i];
    const float* r = pred + ((size_t)b*NPRED + src)*85;
    float cx = r[0], cy = r[1], w = r[2], h = r[3];
    float hw = w*0.5f, hh = h*0.5f;
    float x1 = cx - hw, y1 = cy - hh, x2 = cx + hw, y2 = cy + hh;
    g_boxes[4*i+0] = x1; g_boxes[4*i+1] = y1; g_boxes[4*i+2] = x2; g_boxes[4*i+3] = y2;
    float cf = (float)g_cls[b*NPRED + src];
    g_clsf[i] = cf;
    float sc = g_tops[i];
    g_det[6*i+0] = x1; g_det[6*i+1] = y1; g_det[6*i+2] = x2; g_det[6*i+3] = y2;
    g_det[6*i+4] = sc; g_det[6*i+5] = cf;
    float b0 = x1*0.25f, b1 = y1*0.25f, b2 = x2*0.25f, b3 = y2*0.25f;
    g_ct[2*i+0] = (b0 + b2)*0.5f;
    g_ct[2*i+1] = (b1 + b3)*0.5f;
    g_half[2*i+0] = fmaxf((b2 - b0)*0.5f, 1e-3f);
    g_half[2*i+1] = fmaxf((b3 - b1)*0.5f, 1e-3f);
}

// ---------------- stage 4: NMS ----------------
__global__ void k_nms(){
    __shared__ float bx[KDET][4];
    __shared__ float ar[KDET];
    __shared__ float sc[KDET];
    __shared__ int keep[KDET];
    int b = blockIdx.x, tid = threadIdx.x;
    for (int i = tid; i < KDET; i += 256){
        int g = b*KDET + i;
        float off = g_clsf[g]*4096.0f;
        float x1 = g_boxes[4*g+0] + off, y1 = g_boxes[4*g+1] + off;
        float x2 = g_boxes[4*g+2] + off, y2 = g_boxes[4*g+3] + off;
        bx[i][0] = x1; bx[i][1] = y1; bx[i][2] = x2; bx[i][3] = y2;
        ar[i] = (x2 - x1)*(y2 - y1);
        sc[i] = g_tops[g];
        keep[i] = 1;
    }
    __syncthreads();
    for (int i = 0; i < KDET; i++){
        if (keep[i]){
            float ax1 = bx[i][0], ay1 = bx[i][1], ax2 = bx[i][2], ay2 = bx[i][3], aa = ar[i];
            for (int j = i + 1 + tid; j < KDET; j += 256){
                float iw = fminf(ax2, bx[j][2]) - fmaxf(ax1, bx[j][0]);
                float ih = fminf(ay2, bx[j][3]) - fmaxf(ay1, bx[j][1]);
                iw = fmaxf(iw, 0.f); ih = fmaxf(ih, 0.f);
                float inter = iw*ih;
                float iou = inter / (aa + ar[j] - inter + 1e-9f);
                if (iou > 0.3f) keep[j] = 0;
            }
        }
        __syncthreads();
    }
    for (int i = tid; i < KDET; i += 256)
        g_valid[b*KDET + i] = (keep[i] && (sc[i] > 0.2f)) ? 1 : 0;
}

// ---------------- stage 5: upsample ----------------
__global__ void k_up(const float* __restrict__ feat){
    long long idx = (long long)blockIdx.x*256 + threadIdx.x;
    if (idx >= (long long)NB*128*160*160) return;
    int ox = (int)(idx % 160); long long r = idx/160;
    int oy = (int)(r % 160); r /= 160;
    int c = (int)(r % 128); int b = (int)(r/128);
    int iy = oy >> 1, ix = ox >> 1;
    int ya, yb; float wya, wyb;
    if (oy & 1){ ya = iy; yb = iy+1; wya = 0.75f; wyb = 0.25f; }
    else       { ya = iy-1; yb = iy; wya = 0.25f; wyb = 0.75f; }
    int xa, xb; float wxa, wxb;
    if (ox & 1){ xa = ix; xb = ix+1; wxa = 0.75f; wxb = 0.25f; }
    else       { xa = ix-1; xb = ix; wxa = 0.25f; wxb = 0.75f; }
    ya = max(0, min(79, ya)); yb = max(0, min(79, yb));
    xa = max(0, min(79, xa)); xb = max(0, min(79, xb));
    const float* f = feat + ((size_t)b*128 + c)*6400;
    float v = wya*(wxa*f[ya*80+xa] + wxb*f[ya*80+xb])
            + wyb*(wxa*f[yb*80+xa] + wxb*f[yb*80+xb]);
    g_up[idx] = v;
}

// ---------------- stage 6: 3x3 conv + SiLU -> channel-last f16 ----------------
__global__ void __launch_bounds__(512) k_conv3(const float* __restrict__ Wc, const float* __restrict__ Bc){
    __shared__ float Xs[16][10][10];
    __shared__ float Ws[64][16][9];
    int b = blockIdx.y;
    int tile = blockIdx.x;
    int ty0 = (tile/20)*8, tx0 = (tile%20)*8;
    int tid = threadIdx.x;
    int px = tid & 7, py = (tid >> 3) & 7, og = tid >> 6;
    float acc[8];
    #pragma unroll
    for (int i = 0; i < 8; i++) acc[i] = 0.f;
    for (int c0 = 0; c0 < 128; c0 += 16){
        __syncthreads();
        for (int i = tid; i < 1600; i += 512){
            int c = i/100, r = i%100, yy = r/10, xx = r%10;
            int gy = ty0 - 1 + yy, gx = tx0 - 1 + xx;
            float v = 0.f;
            if (gy >= 0 && gy < 160 && gx >= 0 && gx < 160)
                v = g_up[(((size_t)b*128 + c0 + c)*160 + gy)*160 + gx];
            Xs[c][yy][xx] = v;
        }
        for (int i = tid; i < 9216; i += 512){
            int o = i/144, r = i%144, c = r/9, t = r%9;
            Ws[o][c][t] = Wc[(o*128 + c0 + c)*9 + t];
        }
        __syncthreads();
        for (int c = 0; c < 16; c++){
            #pragma unroll
            for (int t = 0; t < 9; t++){
                float xv = Xs[c][py + t/3][px + t%3];
                #pragma unroll
                for (int i = 0; i < 8; i++)
                    acc[i] += Ws[og*8 + i][c][t]*xv;
            }
        }
    }
    int oy = ty0 + py, ox = tx0 + px;
    __half hv[8];
    #pragma unroll
    for (int i = 0; i < 8; i++){
        int o = og*8 + i;
        float v = acc[i] + Bc[o];
        v = v / (1.f + expf(-v));
        hv[i] = __float2half(v);
    }
    *(uint4*)(g_cfh + (((size_t)b*160 + oy)*160 + ox)*64 + og*8) = *(uint4*)hv;
}

// ---------------- stage 7/8 ----------------
__global__ void k_initpts(){
    int i = blockIdx.x*blockDim.x + threadIdx.x;
    if (i >= NINST*NP) return;
    int inst = i >> 7, p = i & 127;
    float th = (float)p * 0.049087385212340517f;
    g_pts[i*2+0] = g_ct[inst*2+0] + g_half[inst*2+0]*cosf(th);
    g_pts[i*2+1] = g_ct[inst*2+1] + g_half[inst*2+1]*sinf(th);
}

__global__ void k_sample(){
    int inst = blockIdx.x;
    int p = threadIdx.x;
    int b = inst / KDET;
    float px = g_pts[(inst*NP + p)*2 + 0], py = g_pts[(inst*NP + p)*2 + 1];
    float x = fminf(fmaxf(px, 0.f), 159.f);
    float y = fminf(fmaxf(py, 0.f), 159.f);
    float x0f = fminf(fmaxf(floorf(x), 0.f), 158.f);
    float y0f = fminf(fmaxf(floorf(y), 0.f), 158.f);
    int x0 = (int)x0f, y0 = (int)y0f;
    float dx = x - x0f, dy = y - y0f;
    float w00 = (1.f-dx)*(1.f-dy), w10 = dx*(1.f-dy), w01 = (1.f-dx)*dy, w11 = dx*dy;
    const __half* f = g_cfh + (size_t)b*25600*64;
    size_t base = (size_t)(y0*160 + x0)*64;
    const uint4* c00 = (const uint4*)(f + base);
    const uint4* c01 = (const uint4*)(f + base + 64);
    const uint4* c10 = (const uint4*)(f + base + 160*64);
    const uint4* c11 = (const uint4*)(f + base + 160*64 + 64);
    bf16* Z = g_states + (size_t)inst*ST_CH*NP;
    #pragma unroll
    for (int q = 0; q < 8; q++){
        uint4 a = c00[q], bq = c01[q], cq = c10[q], dq = c11[q];
        const __half2* ah = (const __half2*)&a;
        const __half2* bh = (const __half2*)&bq;
        const __half2* ch = (const __half2*)&cq;
        const __half2* dh = (const __half2*)&dq;
        #pragma unroll
        for (int j = 0; j < 4; j++){
            float2 fa = __half22float2(ah[j]);
            float2 fb = __half22float2(bh[j]);
            float2 fc = __half22float2(ch[j]);
            float2 fd = __half22float2(dh[j]);
            float v0 = fa.x*w00 + fb.x*w10 + fc.x*w01 + fd.x*w11;
            float v1 = fa.y*w00 + fb.y*w10 + fc.y*w01 + fd.y*w11;
            int c = q*8 + j*2;
            Z[c*NP + p]     = __float2bfloat16(v0);
            Z[(c+1)*NP + p] = __float2bfloat16(v1);
        }
    }
    float cx = g_ct[inst*2+0], cy = g_ct[inst*2+1];
    float hx = g_half[inst*2+0], hy = g_half[inst*2+1];
    Z[64*NP + p] = __float2bfloat16((px - cx)/hx);
    Z[65*NP + p] = __float2bfloat16((py - cy)/hy);
    bf16 z0 = __float2bfloat16(0.f);
    for (int c = 66; c < 128; c++) Z[c*NP + p] = z0;
}

// ---------------- bf16 warp-MMA ----------------
__device__ __forceinline__ void mma16816(float* d, const u32* a, const u32* b){
    asm volatile("mma.sync.aligned.m16n8k16.row.col.f32.bf16.bf16.f32 "
        "{%0,%1,%2,%3}, {%4,%5,%6,%7}, {%8,%9}, {%0,%1,%2,%3};"
        : "+f"(d[0]), "+f"(d[1]), "+f"(d[2]), "+f"(d[3])
        : "r"(a[0]), "r"(a[1]), "r"(a[2]), "r"(a[3]), "r"(b[0]), "r"(b[1]));
}

// ---- fused snake stack: 2 instances per CTA, shared W staging ----
// smem: Xt0, Xt1, Wb0, Wb1 each 128*136 bf16 -> 139264 B
__global__ void __launch_bounds__(512, 1) k_snake(
    const bf16* __restrict__ Wh, const bf16* __restrict__ Wr,
    const float* __restrict__ bh, const float* __restrict__ br,
    bf16* __restrict__ Sbase)
{
    extern __shared__ bf16 sm[];
    bf16* Wb0 = sm + 2*128*136;
    bf16* Wb1 = sm + 3*128*136;
    int tid = threadIdx.x, warp = tid >> 5, lane = tid & 31;
    int isub = tid >> 8;                  // instance sub-index 0/1
    int tid256 = tid & 255;
    int lw = warp & 7;                    // warp index within instance group
    int wm = lw >> 1, wn = lw & 1, qr = lane >> 2, qc = lane & 3;
    int laneRow = lane & 15, laneHi = lane >> 4;
    int inst = blockIdx.x*2 + isub;
    bf16* Sg = Sbase + (size_t)inst*(ST_CH*NP);
    bf16* Xt = sm + (size_t)isub*128*136;

    // prefetch layer0 tap0 W (all 512 threads)
    #pragma unroll
    for (int q = 0; q < 4; q++){
        int idx = q*512 + tid;
        int row = idx >> 4, seg = idx & 15;
        cpa16(s2u(Wb0 + row*136 + seg*8), Wh + (size_t)row*KTOT + seg*8);
    }
    CP_COMMIT();
    // build Xt[p][c] from this instance's states ch 0..127
    {
        int ph = tid256 & 63, cc = tid256 >> 6;
        #pragma unroll
        for (int cb = 0; cb < 128; cb += 4){
            int c = cb + cc;
            u32 v = *(const u32*)(Sg + c*NP + ph*2);
            Xt[(2*ph)*136 + c]   = ((bf16*)&v)[0];
            Xt[(2*ph+1)*136 + c] = ((bf16*)&v)[1];
        }
    }
    u32 xtb = s2u(Xt);
    u32 aW0 = s2u(Wb0) + (u32)((wm*32 + laneRow)*272 + laneHi*16);
    u32 aW1 = s2u(Wb1) + (u32)((wm*32 + laneRow)*272 + laneHi*16);
    const int DILS[8] = {1,1,1,1,2,2,4,4};

    #pragma unroll 1
    for (int l = 0; l < 8; l++){
        int dil = DILS[l];
        int offs[9];
        #pragma unroll
        for (int t = 0; t < 9; t++) offs[t] = (dil*(t-4) + 128) & 127;
        float acc[2][8][4];
        #pragma unroll
        for (int i = 0; i < 2; i++)
            #pragma unroll
            for (int j = 0; j < 8; j++)
                #pragma unroll
                for (int q = 0; q < 4; q++) acc[i][j][q] = 0.f;

        #pragma unroll 1
        for (int t = 0; t < 9; t++){
            CP_WAIT0();
            __syncthreads();
            int g = l*9 + t;
            if (g < 71){
                int gn = g + 1, ln = gn/9, tn = gn - ln*9;
                const bf16* src = (ln ? (Wr + (size_t)(ln-1)*128*KTOT) : Wh) + tn*128;
                bf16* dstb = (gn & 1) ? Wb1 : Wb0;
                #pragma unroll
                for (int q = 0; q < 4; q++){
                    int idx = q*512 + tid;
                    int row = idx >> 4, seg = idx & 15;
                    cpa16(s2u(dstb + row*136 + seg*8), src + (size_t)row*KTOT + seg*8);
                }
                CP_COMMIT();
            }
            u32 aA = (g & 1) ? aW1 : aW0;
            u32 bAddr[4];
            #pragma unroll
            for (int jj = 0; jj < 4; jj++){
                int row = (wn*64 + jj*16 + laneRow + offs[t]) & 127;
                bAddr[jj] = xtb + (u32)(row*272 + laneHi*16);
            }
            #pragma unroll
            for (int cq2 = 0; cq2 < 8; cq2++){
                u32 koff = (u32)(cq2*32);
                u32 A0[4], A1[4], B[4][4];
                ldsm_x4(A0, aA + koff);
                ldsm_x4(A1, aA + 16*272 + koff);
                #pragma unroll
                for (int jj = 0; jj < 4; jj++) ldsm_x4(B[jj], bAddr[jj] + koff);
                #pragma unroll
                for (int jj = 0; jj < 4; jj++){
                    u32 b0[2] = { B[jj][0], B[jj][2] };
                    u32 b1[2] = { B[jj][1], B[jj][3] };
                    mma16816(acc[0][2*jj],   A0, b0);
                    mma16816(acc[0][2*jj+1], A0, b1);
                    mma16816(acc[1][2*jj],   A1, b0);
                    mma16816(acc[1][2*jj+1], A1, b1);
                }
            }
        }
        // ---- epilogue ----
        __syncthreads();
        const float* bl = l ? (br + (l-1)*128) : bh;
        const bf16* Xin = Sg + (size_t)(128*l)*NP;
        bf16* Yg = Sg + (size_t)(128*(l+1))*NP;
        #pragma unroll
        for (int i = 0; i < 2; i++){
            #pragma unroll
            for (int j = 0; j < 8; j++){
                int row = wm*32 + i*16 + qr;
                int col = wn*64 + j*8 + qc*2;
                #pragma unroll
                for (int h = 0; h < 2; h++){
                    int rr = row + h*8;
                    float b0 = bl[rr];
                    float v0 = acc[i][j][2*h+0] + b0; v0 = v0 > 0.f ? v0 : 0.f;
                    float v1 = acc[i][j][2*h+1] + b0; v1 = v1 > 0.f ? v1 : 0.f;
                    if (l > 0){
                        u32 xv = *(const u32*)(Xin + rr*NP + col);
                        v0 += __bfloat162float(((bf16*)&xv)[0]);
                        v1 += __bfloat162float(((bf16*)&xv)[1]);
                    }
                    bf16 h0 = __float2bfloat16(v0), h1 = __float2bfloat16(v1);
                    u32 pk = ((u32)*(unsigned short*)&h1 << 16) | (u32)*(unsigned short*)&h0;
                    *(u32*)(Yg + rr*NP + col) = pk;
                    Xt[col*136 + rr]     = h0;
                    Xt[(col+1)*136 + rr] = h1;
                }
            }
        }
    }
}

// ---- fuse GEMM: states(1152ch) -> 256ch, ldmatrix-fed, W+B double-buffered ----
__global__ void __launch_bounds__(256, 2) k_mma_fuse(
    const bf16* __restrict__ W, const float* __restrict__ bias,
    const bf16* __restrict__ Xbase, bf16* __restrict__ Ybase)
{
    extern __shared__ bf16 sm[];
    bf16* Wb[2] = { sm, sm + 128*72 };
    bf16* Bb[2] = { sm + 2*128*72, sm + 3*128*72 };
    int inst = blockIdx.x, mblk = blockIdx.y;
    const bf16* Xg = Xbase + (size_t)inst*(ST_CH*NP);
    bf16* Yg = Ybase + (size_t)inst*(256*NP) + (size_t)mblk*128*NP;
    const bf16* Wm = W + (size_t)mblk*128*KTOT;
    int tid = threadIdx.x, warp = tid >> 5, lane = tid & 31;
    int wm = warp >> 1, wn = warp & 1, qr = lane >> 2, qc = lane & 3;
    int laneRow = lane & 15, laneHi = lane >> 4;
    float acc[2][8][4];
    #pragma unroll
    for (int i = 0; i < 2; i++)
        #pragma unroll
        for (int j = 0; j < 8; j++)
            #pragma unroll
            for (int q = 0; q < 4; q++) acc[i][j][q] = 0.f;
    int ph = tid & 63, cc = tid >> 6;

    {
        #pragma unroll
        for (int q = 0; q < 4; q++){
            int idx = q*256 + tid;
            int row = idx >> 3, seg = idx & 7;
            cpa16(s2u(Wb[0] + row*72 + seg*8), Wm + (size_t)row*KTOT + seg*8);
        }
        CP_COMMIT();
        #pragma unroll
        for (int q = 0; q < 16; q++){
            int c = 4*q + cc;
            u32 v = *(const u32*)(Xg + (size_t)c*NP + ph*2);
            Bb[0][(2*ph)*72 + c]   = ((bf16*)&v)[0];
            Bb[0][(2*ph+1)*72 + c] = ((bf16*)&v)[1];
        }
    }
    u32 aWa[2], bBa[2];
    #pragma unroll
    for (int z = 0; z < 2; z++){
        aWa[z] = s2u(Wb[z]) + (u32)((wm*32 + laneRow)*144 + laneHi*16);
        bBa[z] = s2u(Bb[z]) + (u32)((wn*64 + laneRow)*144 + laneHi*16);
    }
    #pragma unroll 1
    for (int chn = 0; chn < 18; chn++){
        CP_WAIT0();
        __syncthreads();
        u32 vreg[16];
        if (chn < 17){
            int k0 = (chn+1)*64;
            #pragma unroll
            for (int q = 0; q < 16; q++)
                vreg[q] = *(const u32*)(Xg + (size_t)(k0 + 4*q + cc)*NP + ph*2);
            bf16* dstw = Wb[(chn+1) & 1];
            const bf16* srcw = Wm + k0;
            #pragma unroll
            for (int q = 0; q < 4; q++){
                int idx = q*256 + tid;
                int row = idx >> 3, seg = idx & 7;
                cpa16(s2u(dstw + row*72 + seg*8), srcw + (size_t)row*KTOT + seg*8);
            }
            CP_COMMIT();
        }
        u32 aA = aWa[chn & 1];
        u32 bA = bBa[chn & 1];
        #pragma unroll
        for (int cq = 0; cq < 4; cq++){
            u32 koff = (u32)(cq*32);
            u32 A0[4], A1[4], B0[4], B1[4];
            ldsm_x4(A0, aA + koff);
            ldsm_x4(A1, aA + 16*144 + koff);
            ldsm_x4(B0, bA + koff);
            ldsm_x4(B1, bA + 16*144 + koff);
            {
                u32 b0[2] = { B0[0], B0[2] }, b1[2] = { B0[1], B0[3] };
                u32 b2[2] = { B1[0], B1[2] }, b3[2] = { B1[1], B1[3] };
                mma16816(acc[0][0], A0, b0); mma16816(acc[0][1], A0, b1);
                mma16816(acc[0][2], A0, b2); mma16816(acc[0][3], A0, b3);
                mma16816(acc[1][0], A1, b0); mma16816(acc[1][1], A1, b1);
                mma16816(acc[1][2], A1, b2); mma16816(acc[1][3], A1, b3);
            }
            u32 B2[4], B3[4];
            ldsm_x4(B2, bA + 32*144 + koff);
            ldsm_x4(B3, bA + 48*144 + koff);
            {
                u32 b0[2] = { B2[0], B2[2] }, b1[2] = { B2[1], B2[3] };
                u32 b2[2] = { B3[0], B3[2] }, b3[2] = { B3[1], B3[3] };
                mma16816(acc[0][4], A0, b0); mma16816(acc[0][5], A0, b1);
                mma16816(acc[0][6], A0, b2); mma16816(acc[0][7], A0, b3);
                mma16816(acc[1][4], A1, b0); mma16816(acc[1][5], A1, b1);
                mma16816(acc[1][6], A1, b2); mma16816(acc[1][7], A1, b3);
            }
        }
        if (chn < 17){
            bf16* dstb = Bb[(chn+1) & 1];
            #pragma unroll
            for (int q = 0; q < 16; q++){
                int c = 4*q + cc;
                dstb[(2*ph)*72 + c]   = ((bf16*)&vreg[q])[0];
                dstb[(2*ph+1)*72 + c] = ((bf16*)&vreg[q])[1];
            }
        }
    }
    #pragma unroll
    for (int i = 0; i < 2; i++){
        #pragma unroll
        for (int j = 0; j < 8; j++){
            int row = wm*32 + i*16 + qr;
            int col = wn*64 + j*8 + qc*2;
            #pragma unroll
            for (int h = 0; h < 2; h++){
                int rr = row + h*8;
                float b0 = bias[mblk*128 + rr];
                float v0 = acc[i][j][2*h+0] + b0; v0 = v0 > 0.f ? v0 : 0.f;
                float v1 = acc[i][j][2*h+1] + b0; v1 = v1 > 0.f ? v1 : 0.f;
                Yg[rr*NP + col]     = __float2bfloat16(v0);
                Yg[rr*NP + col + 1] = __float2bfloat16(v1);
            }
        }
    }
}

// ---------------- p1: 256 -> 64 ----------------
__global__ void k_p1(const float* __restrict__ Wt, const float* __restrict__ bias){
    __shared__ float Xs[16*128];
    __shared__ float WsT[16*64];
    int inst = blockIdx.x;
    const bf16* Xg = g_fuse + (size_t)inst*256*NP;
    float* Yg = g_hbuf + (size_t)inst*64*NP;
    int tid = threadIdx.x;
    int tx = tid & 15, ty = tid >> 4;
    u64 acc[4][8];
    #pragma unroll
    for (int i = 0; i < 4; i++)
        #pragma unroll
        for (int j = 0; j < 8; j++) acc[i][j] = 0ULL;
    for (int k0 = 0; k0 < 256; k0 += 16){
        __syncthreads();
        for (int i = tid; i < 16*128; i += 128) Xs[i] = __bfloat162float(Xg[k0*128 + i]);
        for (int i = tid; i < 16*64; i += 128) WsT[i] = Wt[k0*64 + i];
        __syncthreads();
        for (int kk = 0; kk < 16; kk++){
            const u64* wr = (const u64*)(WsT + kk*64 + ty*8);
            u64 xv[8];
            #pragma unroll
            for (int j = 0; j < 8; j++) xv[j] = bcast2(Xs[kk*128 + tx + 16*j]);
            #pragma unroll
            for (int i = 0; i < 4; i++){
                u64 wv = wr[i];
                #pragma unroll
                for (int j = 0; j < 8; j++) ffma2(acc[i][j], wv, xv[j]);
            }
        }
    }
    #pragma unroll
    for (int i = 0; i < 4; i++){
        int o0 = ty*8 + 2*i;
        float b0 = bias[o0], b1 = bias[o0+1];
        #pragma unroll
        for (int j = 0; j < 8; j++){
            float2 v = unpack2(acc[i][j]);
            float v0 = v.x + b0; v0 = v0 > 0.f ? v0 : 0.f;
            float v1 = v.y + b1; v1 = v1 > 0.f ? v1 : 0.f;
            Yg[o0*128 + tx + 16*j] = v0;
            Yg[(o0+1)*128 + tx + 16*j] = v1;
        }
    }
}

// ---------------- p2: 64 -> 2 ----------------
__global__ void k_p2(const float* __restrict__ w, const float* __restrict__ b){
    int inst = blockIdx.x;
    int p = threadIdx.x;
    const float* X = g_hbuf + (size_t)inst*64*NP;
    float a0 = 0.f, a1 = 0.f;
    for (int c = 0; c < 64; c++){
        float xv = X[c*NP + p];
        a0 += w[c]*xv;
        a1 += w[64 + c]*xv;
    }
    g_off[inst*2*NP + p]      = a0 + b[0];
    g_off[inst*2*NP + NP + p] = a1 + b[1];
}

__global__ void k_update(){
    int i = blockIdx.x*blockDim.x + threadIdx.x;
    if (i >= NINST*NP) return;
    int inst = i >> 7, p = i & 127;
    g_pts[i*2+0] += g_off[inst*2*NP + p];
    g_pts[i*2+1] += g_off[inst*2*NP + NP + p];
}

// ---------------- output assembly ----------------
__global__ void k_out(float* __restrict__ out){
    int i = blockIdx.x*blockDim.x + threadIdx.x;
    const int n_det = NINST*6;
    const int n_ct  = NINST*2;
    const int n_pts = NINST*NP*2;
    if (i < n_det){ out[i] = g_det[i]; return; }
    int j = i - n_det;
    if (j < n_ct){ out[i] = g_ct[j]; return; }
    j -= n_ct;
    if (j < n_pts){
        int inst = j / (NP*2);
        out[i] = g_valid[inst] ? g_pts[j] : 0.0f;
        return;
    }
    j -= n_pts;
    if (j < NINST) out[i] = g_valid[j] ? 1.0f : 0.0f;
}

// ---------------- host launcher ----------------
extern "C" void kernel_launch(void* const* d_in, const int* in_sizes, int n_in,
                              void* d_out, int out_size)
{
    const float* pred   = (const float*)d_in[0];
    const float* feat   = (const float*)d_in[1];
    const float* conv_w = (const float*)d_in[2];
    const float* conv_b = (const float*)d_in[3];
    const float* b_head = (const float*)d_in[5];
    const float* b_res  = (const float*)d_in[7];
    const float* b_fuse = (const float*)d_in[9];
    const float* b_p1   = (const float*)d_in[11];
    const float* w_p2   = (const float*)d_in[12];
    const float* b_p2   = (const float*)d_in[13];

    cudaFuncSetAttribute(k_topk, cudaFuncAttributeMaxDynamicSharedMemorySize, 26400*8);
    cudaFuncSetAttribute(k_snake, cudaFuncAttributeMaxDynamicSharedMemorySize, 139264);
    cudaFuncSetAttribute(k_mma_fuse, cudaFuncAttributeMaxDynamicSharedMemorySize, 73728);

    void *pv;
    cudaGetSymbolAddress(&pv, g_states); bf16* p_states = (bf16*)pv;
    cudaGetSymbolAddress(&pv, g_fuse);   bf16* p_fuse = (bf16*)pv;
    cudaGetSymbolAddress(&pv, g_whb);    bf16* p_whb = (bf16*)pv;
    cudaGetSymbolAddress(&pv, g_wrb);    bf16* p_wrb = (bf16*)pv;
    cudaGetSymbolAddress(&pv, g_wfb);    bf16* p_wfb = (bf16*)pv;
    cudaGetSymbolAddress(&pv, g_wp1t);   float* p_wp1t = (float*)pv;

    {
        int n = 128*KTOT + 7*128*KTOT + 256*KTOT + 256*64;
        k_wtrans<<<(n + 255)/256, 256>>>((const float*)d_in[4], (const float*)d_in[6],
                                         (const float*)d_in[8], (const float*)d_in[10]);
    }
    k_scores<<<(NB*NPRED + 255)/256, 256>>>(pred);
    k_topk<<<NB, 1024, 26400*8>>>();
    k_prep<<<(NINST + 255)/256, 256>>>(pred);
    k_nms<<<NB, 256>>>();
    k_up<<<(int)(((long long)NB*128*160*160 + 255)/256), 256>>>(feat);
    k_conv3<<<dim3(400, NB), 512>>>(conv_w, conv_b);
    k_initpts<<<(NINST*NP + 255)/256, 256>>>();
    for (int it = 0; it < 2; it++){
        k_sample<<<NINST, 128>>>();
        k_snake<<<NINST/2, 512, 139264>>>(p_whb, p_wrb, b_head, b_res, p_states);
        k_mma_fuse<<<dim3(NINST, 2), 256, 73728>>>(p_wfb, b_fuse, p_states, p_fuse);
        k_p1<<<NINST, 128>>>(p_wp1t, b_p1);
        k_p2<<<NINST, 128>>>(w_p2, b_p2);
        k_update<<<(NINST*NP + 255)/256, 256>>>();
    }
    {
        int n = NINST*6 + NINST*2 + NINST*NP*2 + NINST;
        k_out<<<(n + 255)/256, 256>>>((float*)d_out);
    }
}

// round 13
// speedup vs baseline: 1.0196x; 1.0196x over previous
#include <cuda_runtime.h>
#include <cuda_bf16.h>
#include <cuda_fp16.h>
#include <math.h>

#define NB 16
#define NPRED 25200
#define NCLS 80
#define KDET 300
#define NP 128
#define NINST (NB*KDET)
#define ST_CH 1152
#define KTOT 1152

typedef unsigned long long u64;
typedef unsigned int u32;
typedef __nv_bfloat16 bf16;

__device__ __forceinline__ void ffma2(u64& acc, u64 a, u64 b){
    asm("fma.rn.f32x2 %0, %1, %2, %3;" : "=l"(acc) : "l"(a), "l"(b), "l"(acc));
}
__device__ __forceinline__ u64 bcast2(float x){
    u64 r;
    asm("mov.b64 %0, {%1, %1};" : "=l"(r) : "r"(__float_as_uint(x)));
    return r;
}
__device__ __forceinline__ float2 unpack2(u64 v){
    float2 f;
    asm("mov.b64 {%0, %1}, %2;" : "=f"(f.x), "=f"(f.y) : "l"(v));
    return f;
}
__device__ __forceinline__ u32 s2u(const void* p){
    u32 a; asm("{ .reg .u64 t; cvta.to.shared.u64 t, %1; cvt.u32.u64 %0, t; }" : "=r"(a) : "l"(p));
    return a;
}
__device__ __forceinline__ void cpa16(u32 dst, const void* src){
    asm volatile("cp.async.cg.shared.global [%0], [%1], 16;" :: "r"(dst), "l"(src));
}
#define CP_COMMIT() asm volatile("cp.async.commit_group;" ::: "memory")
#define CP_WAIT0()  asm volatile("cp.async.wait_group 0;" ::: "memory")

__device__ __forceinline__ void ldsm_x4(u32* r, u32 addr){
    asm volatile("ldmatrix.sync.aligned.m8n8.x4.shared.b16 {%0,%1,%2,%3}, [%4];"
        : "=r"(r[0]), "=r"(r[1]), "=r"(r[2]), "=r"(r[3]) : "r"(addr));
}

// ---------------- device scratch ----------------
__device__ float g_score[NB*NPRED];
__device__ int   g_cls[NB*NPRED];
__device__ int   g_topidx[NINST];
__device__ float g_tops[NINST];
__device__ float g_boxes[NINST*4];
__device__ float g_det[NINST*6];
__device__ float g_ct[NINST*2];
__device__ float g_half[NINST*2];
__device__ float g_clsf[NINST];
__device__ int   g_valid[NINST];
__device__ float g_up[(size_t)NB*128*160*160];
__device__ __half g_cfh[(size_t)NB*160*160*64];   // channel-last f16 features
__device__ float g_pts[NINST*NP*2];
__device__ float g_off[NINST*2*NP];
__device__ float g_hbuf[(size_t)NINST*64*NP];
__device__ bf16  g_states[(size_t)NINST*ST_CH*NP];   // [inst][ch][p]
__device__ bf16  g_fuse[(size_t)NINST*256*NP];
__device__ bf16  g_whb[128*KTOT];      // head W [o][k=t*128+c]
__device__ bf16  g_wrb[7*128*KTOT];    // res  W [l][o][k=t*128+c]
__device__ bf16  g_wfb[256*KTOT];      // fuse W [o][k]
__device__ float g_wp1t[256*64];       // p1 W [k][o]

// ---------------- weight transposition ----------------
__global__ void k_wtrans(const float* __restrict__ wh, const float* __restrict__ wr,
                         const float* __restrict__ wf, const float* __restrict__ wp1)
{
    int i = blockIdx.x*blockDim.x + threadIdx.x;
    const int n1 = 128*KTOT;
    const int n2 = 7*128*KTOT;
    const int n3 = 256*KTOT;
    const int n4 = 256*64;
    if (i < n1){
        int o = i / KTOT, k = i % KTOT, t = k >> 7, c = k & 127;
        g_whb[i] = __float2bfloat16(c < 66 ? wh[(o*66 + c)*9 + t] : 0.f);
        return;
    }
    i -= n1;
    if (i < n2){
        int l = i / (128*KTOT), r = i % (128*KTOT);
        int o = r / KTOT, k = r % KTOT, t = k >> 7, c = k & 127;
        g_wrb[i] = __float2bfloat16(wr[(((size_t)l*128 + o)*128 + c)*9 + t]);
        return;
    }
    i -= n2;
    if (i < n3){
        int o = i / KTOT, k = i % KTOT;
        float v = 0.f;
        if (k < 66) v = wf[o*1090 + k];
        else if (k >= 128) v = wf[o*1090 + k - 62];
        g_wfb[i] = __float2bfloat16(v);
        return;
    }
    i -= n3;
    if (i < n4){
        int o = i & 63, k = i >> 6;
        g_wp1t[i] = wp1[o*256 + k];
    }
}

// ---------------- stage 1: scores ----------------
__global__ void k_scores(const float* __restrict__ pred){
    int i = blockIdx.x*blockDim.x + threadIdx.x;
    if (i >= NB*NPRED) return;
    const float* r = pred + (size_t)i*85;
    float obj = r[4];
    float best = -1e30f; int bc = 0;
    for (int c = 0; c < NCLS; c++){
        float s = obj * r[5+c];
        if (s > best){ best = s; bc = c; }
    }
    g_score[i] = (best > 0.2f) ? best : 0.0f;
    g_cls[i] = bc;
}

// ---------------- stage 2: stable top-300 ----------------
__global__ void __launch_bounds__(1024) k_topk(){
    extern __shared__ unsigned long long smk[];
    unsigned long long* keys = smk;
    unsigned long long* l1   = smk + 25600;
    __shared__ unsigned long long red[32];
    int b = blockIdx.x, tid = threadIdx.x;
    for (int i = tid; i < 25600; i += 1024){
        unsigned long long k = 0ULL;
        if (i < NPRED){
            unsigned u = __float_as_uint(g_score[b*NPRED + i]);
            k = ((unsigned long long)u << 32) | (unsigned)(~i);
        }
        keys[i] = k;
    }
    __syncthreads();
    if (tid < 800){
        unsigned long long m = 0ULL;
        for (int j = 0; j < 32; j++){ unsigned long long v = keys[tid*32 + j]; if (v > m) m = v; }
        l1[tid] = m;
    }
    __syncthreads();
    for (int it = 0; it < KDET; it++){
        unsigned long long v = (tid < 800) ? l1[tid] : 0ULL;
        #pragma unroll
        for (int o = 16; o > 0; o >>= 1){
            unsigned long long t2 = __shfl_down_sync(0xffffffffu, v, o);
            if (t2 > v) v = t2;
        }
        if ((tid & 31) == 0) red[tid >> 5] = v;
        __syncthreads();
        if (tid < 32){
            v = red[tid];
            #pragma unroll
            for (int o = 16; o > 0; o >>= 1){
                unsigned long long t2 = __shfl_down_sync(0xffffffffu, v, o);
                if (t2 > v) v = t2;
            }
            if (tid == 0) red[0] = v;
        }
        __syncthreads();
        unsigned long long w = red[0];
        int idx = (int)(~(unsigned)w);
        if (tid < 32){
            int ch = idx >> 5;
            if (tid == 0) keys[idx] = 0ULL;
            __syncwarp();
            unsigned long long kv = keys[ch*32 + tid];
            #pragma unroll
            for (int o = 16; o > 0; o >>= 1){
                unsigned long long t2 = __shfl_down_sync(0xffffffffu, kv, o);
                if (t2 > kv) kv = t2;
            }
            if (tid == 0){
                l1[ch] = kv;
                g_topidx[b*KDET + it] = idx;
                g_tops[b*KDET + it] = __uint_as_float((unsigned)(w >> 32));
            }
        }
        __syncthreads();
    }
}

// ---------------- stage 3 ----------------
__global__ void k_prep(const float* __restrict__ pred){
    int i = blockIdx.x*blockDim.x + threadIdx.x;
    if (i >= NINST) return;
    int b = i / KDET;
    int src = g_topidx[i];
    const float* r = pred + ((size_t)b*NPRED + src)*85;
    float cx = r[0], cy = r[1], w = r[2], h = r[3];
    float hw = w*0.5f, hh = h*0.5f;
    float x1 = cx - hw, y1 = cy - hh, x2 = cx + hw, y2 = cy + hh;
    g_boxes[4*i+0] = x1; g_boxes[4*i+1] = y1; g_boxes[4*i+2] = x2; g_boxes[4*i+3] = y2;
    float cf = (float)g_cls[b*NPRED + src];
    g_clsf[i] = cf;
    float sc = g_tops[i];
    g_det[6*i+0] = x1; g_det[6*i+1] = y1; g_det[6*i+2] = x2; g_det[6*i+3] = y2;
    g_det[6*i+4] = sc; g_det[6*i+5] = cf;
    float b0 = x1*0.25f, b1 = y1*0.25f, b2 = x2*0.25f, b3 = y2*0.25f;
    g_ct[2*i+0] = (b0 + b2)*0.5f;
    g_ct[2*i+1] = (b1 + b3)*0.5f;
    g_half[2*i+0] = fmaxf((b2 - b0)*0.5f, 1e-3f);
    g_half[2*i+1] = fmaxf((b3 - b1)*0.5f, 1e-3f);
}

// ---------------- stage 4: NMS ----------------
__global__ void k_nms(){
    __shared__ float bx[KDET][4];
    __shared__ float ar[KDET];
    __shared__ float sc[KDET];
    __shared__ int keep[KDET];
    int b = blockIdx.x, tid = threadIdx.x;
    for (int i = tid; i < KDET; i += 256){
        int g = b*KDET + i;
        float off = g_clsf[g]*4096.0f;
        float x1 = g_boxes[4*g+0] + off, y1 = g_boxes[4*g+1] + off;
        float x2 = g_boxes[4*g+2] + off, y2 = g_boxes[4*g+3] + off;
        bx[i][0] = x1; bx[i][1] = y1; bx[i][2] = x2; bx[i][3] = y2;
        ar[i] = (x2 - x1)*(y2 - y1);
        sc[i] = g_tops[g];
        keep[i] = 1;
    }
    __syncthreads();
    for (int i = 0; i < KDET; i++){
        if (keep[i]){
            float ax1 = bx[i][0], ay1 = bx[i][1], ax2 = bx[i][2], ay2 = bx[i][3], aa = ar[i];
            for (int j = i + 1 + tid; j < KDET; j += 256){
                float iw = fminf(ax2, bx[j][2]) - fmaxf(ax1, bx[j][0]);
                float ih = fminf(ay2, bx[j][3]) - fmaxf(ay1, bx[j][1]);
                iw = fmaxf(iw, 0.f); ih = fmaxf(ih, 0.f);
                float inter = iw*ih;
                float iou = inter / (aa + ar[j] - inter + 1e-9f);
                if (iou > 0.3f) keep[j] = 0;
            }
        }
        __syncthreads();
    }
    for (int i = tid; i < KDET; i += 256)
        g_valid[b*KDET + i] = (keep[i] && (sc[i] > 0.2f)) ? 1 : 0;
}

// ---------------- stage 5: upsample ----------------
__global__ void k_up(const float* __restrict__ feat){
    long long idx = (long long)blockIdx.x*256 + threadIdx.x;
    if (idx >= (long long)NB*128*160*160) return;
    int ox = (int)(idx % 160); long long r = idx/160;
    int oy = (int)(r % 160); r /= 160;
    int c = (int)(r % 128); int b = (int)(r/128);
    int iy = oy >> 1, ix = ox >> 1;
    int ya, yb; float wya, wyb;
    if (oy & 1){ ya = iy; yb = iy+1; wya = 0.75f; wyb = 0.25f; }
    else       { ya = iy-1; yb = iy; wya = 0.25f; wyb = 0.75f; }
    int xa, xb; float wxa, wxb;
    if (ox & 1){ xa = ix; xb = ix+1; wxa = 0.75f; wxb = 0.25f; }
    else       { xa = ix-1; xb = ix; wxa = 0.25f; wxb = 0.75f; }
    ya = max(0, min(79, ya)); yb = max(0, min(79, yb));
    xa = max(0, min(79, xa)); xb = max(0, min(79, xb));
    const float* f = feat + ((size_t)b*128 + c)*6400;
    float v = wya*(wxa*f[ya*80+xa] + wxb*f[ya*80+xb])
            + wyb*(wxa*f[yb*80+xa] + wxb*f[yb*80+xb]);
    g_up[idx] = v;
}

// ---------------- stage 6: 3x3 conv + SiLU (FFMA2) -> channel-last f16 ----------------
__global__ void __launch_bounds__(512) k_conv3(const float* __restrict__ Wc, const float* __restrict__ Bc){
    __shared__ float Xs[16][10][10];
    __shared__ float Wsp[16][9][64];   // [c][t][o] -> o-contiguous pairs
    int b = blockIdx.y;
    int tile = blockIdx.x;
    int ty0 = (tile/20)*8, tx0 = (tile%20)*8;
    int tid = threadIdx.x;
    int px = tid & 7, py = (tid >> 3) & 7, og = tid >> 6;
    u64 acc2[4] = {0ULL, 0ULL, 0ULL, 0ULL};
    for (int c0 = 0; c0 < 128; c0 += 16){
        __syncthreads();
        for (int i = tid; i < 1600; i += 512){
            int c = i/100, r = i%100, yy = r/10, xx = r%10;
            int gy = ty0 - 1 + yy, gx = tx0 - 1 + xx;
            float v = 0.f;
            if (gy >= 0 && gy < 160 && gx >= 0 && gx < 160)
                v = g_up[(((size_t)b*128 + c0 + c)*160 + gy)*160 + gx];
            Xs[c][yy][xx] = v;
        }
        for (int i = tid; i < 9216; i += 512){
            int o = i & 63, r = i >> 6, c = r/9, t = r%9;
            Wsp[c][t][o] = Wc[(o*128 + c0 + c)*9 + t];
        }
        __syncthreads();
        for (int c = 0; c < 16; c++){
            #pragma unroll
            for (int t = 0; t < 9; t++){
                u64 xv = bcast2(Xs[c][py + t/3][px + t%3]);
                const u64* wr = (const u64*)(&Wsp[c][t][og*8]);
                #pragma unroll
                for (int i = 0; i < 4; i++) ffma2(acc2[i], wr[i], xv);
            }
        }
    }
    int oy = ty0 + py, ox = tx0 + px;
    __half hv[8];
    #pragma unroll
    for (int i = 0; i < 4; i++){
        float2 v2 = unpack2(acc2[i]);
        int o0 = og*8 + 2*i;
        float v0 = v2.x + Bc[o0];
        float v1 = v2.y + Bc[o0+1];
        v0 = v0 / (1.f + expf(-v0));
        v1 = v1 / (1.f + expf(-v1));
        hv[2*i]   = __float2half(v0);
        hv[2*i+1] = __float2half(v1);
    }
    *(uint4*)(g_cfh + (((size_t)b*160 + oy)*160 + ox)*64 + og*8) = *(uint4*)hv;
}

// ---------------- stage 7/8 ----------------
__global__ void k_initpts(){
    int i = blockIdx.x*blockDim.x + threadIdx.x;
    if (i >= NINST*NP) return;
    int inst = i >> 7, p = i & 127;
    float th = (float)p * 0.049087385212340517f;
    g_pts[i*2+0] = g_ct[inst*2+0] + g_half[inst*2+0]*cosf(th);
    g_pts[i*2+1] = g_ct[inst*2+1] + g_half[inst*2+1]*sinf(th);
}

__global__ void k_sample(){
    int inst = blockIdx.x;
    int p = threadIdx.x;
    int b = inst / KDET;
    float px = g_pts[(inst*NP + p)*2 + 0], py = g_pts[(inst*NP + p)*2 + 1];
    float x = fminf(fmaxf(px, 0.f), 159.f);
    float y = fminf(fmaxf(py, 0.f), 159.f);
    float x0f = fminf(fmaxf(floorf(x), 0.f), 158.f);
    float y0f = fminf(fmaxf(floorf(y), 0.f), 158.f);
    int x0 = (int)x0f, y0 = (int)y0f;
    float dx = x - x0f, dy = y - y0f;
    float w00 = (1.f-dx)*(1.f-dy), w10 = dx*(1.f-dy), w01 = (1.f-dx)*dy, w11 = dx*dy;
    const __half* f = g_cfh + (size_t)b*25600*64;
    size_t base = (size_t)(y0*160 + x0)*64;
    const uint4* c00 = (const uint4*)(f + base);
    const uint4* c01 = (const uint4*)(f + base + 64);
    const uint4* c10 = (const uint4*)(f + base + 160*64);
    const uint4* c11 = (const uint4*)(f + base + 160*64 + 64);
    bf16* Z = g_states + (size_t)inst*ST_CH*NP;
    #pragma unroll
    for (int q = 0; q < 8; q++){
        uint4 a = c00[q], bq = c01[q], cq = c10[q], dq = c11[q];
        const __half2* ah = (const __half2*)&a;
        const __half2* bh = (const __half2*)&bq;
        const __half2* ch = (const __half2*)&cq;
        const __half2* dh = (const __half2*)&dq;
        #pragma unroll
        for (int j = 0; j < 4; j++){
            float2 fa = __half22float2(ah[j]);
            float2 fb = __half22float2(bh[j]);
            float2 fc = __half22float2(ch[j]);
            float2 fd = __half22float2(dh[j]);
            float v0 = fa.x*w00 + fb.x*w10 + fc.x*w01 + fd.x*w11;
            float v1 = fa.y*w00 + fb.y*w10 + fc.y*w01 + fd.y*w11;
            int c = q*8 + j*2;
            Z[c*NP + p]     = __float2bfloat16(v0);
            Z[(c+1)*NP + p] = __float2bfloat16(v1);
        }
    }
    float cx = g_ct[inst*2+0], cy = g_ct[inst*2+1];
    float hx = g_half[inst*2+0], hy = g_half[inst*2+1];
    Z[64*NP + p] = __float2bfloat16((px - cx)/hx);
    Z[65*NP + p] = __float2bfloat16((py - cy)/hy);
    bf16 z0 = __float2bfloat16(0.f);
    for (int c = 66; c < 128; c++) Z[c*NP + p] = z0;
}

// ---------------- bf16 warp-MMA ----------------
__device__ __forceinline__ void mma16816(float* d, const u32* a, const u32* b){
    asm volatile("mma.sync.aligned.m16n8k16.row.col.f32.bf16.bf16.f32 "
        "{%0,%1,%2,%3}, {%4,%5,%6,%7}, {%8,%9}, {%0,%1,%2,%3};"
        : "+f"(d[0]), "+f"(d[1]), "+f"(d[2]), "+f"(d[3])
        : "r"(a[0]), "r"(a[1]), "r"(a[2]), "r"(a[3]), "r"(b[0]), "r"(b[1]));
}

// ---- fused snake stack: head + 7 res layers, Xt resident in smem ----
// smem: Xt[128*136] + Wb0[128*136] + Wb1[128*136]  (104448 B)
__global__ void __launch_bounds__(256, 2) k_snake(
    const bf16* __restrict__ Wh, const bf16* __restrict__ Wr,
    const float* __restrict__ bh, const float* __restrict__ br,
    bf16* __restrict__ Sbase)
{
    extern __shared__ bf16 sm[];
    bf16* Xt  = sm;
    bf16* Wb0 = sm + 128*136;
    bf16* Wb1 = Wb0 + 128*136;
    int inst = blockIdx.x;
    bf16* Sg = Sbase + (size_t)inst*(ST_CH*NP);
    int tid = threadIdx.x, warp = tid >> 5, lane = tid & 31;
    int wm = warp >> 1, wn = warp & 1, qr = lane >> 2, qc = lane & 3;
    int laneRow = lane & 15, laneHi = lane >> 4;

    #pragma unroll
    for (int q = 0; q < 8; q++){
        int idx = q*256 + tid;
        int row = idx >> 4, seg = idx & 15;
        cpa16(s2u(Wb0 + row*136 + seg*8), Wh + (size_t)row*KTOT + seg*8);
    }
    CP_COMMIT();
    {
        int ph = tid & 63, cc = tid >> 6;
        #pragma unroll
        for (int cb = 0; cb < 128; cb += 4){
            int c = cb + cc;
            u32 v = *(const u32*)(Sg + c*NP + ph*2);
            Xt[(2*ph)*136 + c]   = ((bf16*)&v)[0];
            Xt[(2*ph+1)*136 + c] = ((bf16*)&v)[1];
        }
    }
    u32 xtb = s2u(Xt);
    u32 aW0 = s2u(Wb0) + (u32)((wm*32 + laneRow)*272 + laneHi*16);
    u32 aW1 = s2u(Wb1) + (u32)((wm*32 + laneRow)*272 + laneHi*16);
    const int DILS[8] = {1,1,1,1,2,2,4,4};

    #pragma unroll 1
    for (int l = 0; l < 8; l++){
        int dil = DILS[l];
        int offs[9];
        #pragma unroll
        for (int t = 0; t < 9; t++) offs[t] = (dil*(t-4) + 128) & 127;
        float acc[2][8][4];
        #pragma unroll
        for (int i = 0; i < 2; i++)
            #pragma unroll
            for (int j = 0; j < 8; j++)
                #pragma unroll
                for (int q = 0; q < 4; q++) acc[i][j][q] = 0.f;

        #pragma unroll 1
        for (int t = 0; t < 9; t++){
            CP_WAIT0();
            __syncthreads();
            int g = l*9 + t;
            if (g < 71){
                int gn = g + 1, ln = gn/9, tn = gn - ln*9;
                const bf16* src = (ln ? (Wr + (size_t)(ln-1)*128*KTOT) : Wh) + tn*128;
                bf16* dstb = (gn & 1) ? Wb1 : Wb0;
                #pragma unroll
                for (int q = 0; q < 8; q++){
                    int idx = q*256 + tid;
                    int row = idx >> 4, seg = idx & 15;
                    cpa16(s2u(dstb + row*136 + seg*8), src + (size_t)row*KTOT + seg*8);
                }
                CP_COMMIT();
            }
            u32 aA = (g & 1) ? aW1 : aW0;
            u32 bAddr[4];
            #pragma unroll
            for (int jj = 0; jj < 4; jj++){
                int row = (wn*64 + jj*16 + laneRow + offs[t]) & 127;
                bAddr[jj] = xtb + (u32)(row*272 + laneHi*16);
            }
            #pragma unroll
            for (int cq2 = 0; cq2 < 8; cq2++){
                u32 koff = (u32)(cq2*32);
                u32 A0[4], A1[4], B[4][4];
                ldsm_x4(A0, aA + koff);
                ldsm_x4(A1, aA + 16*272 + koff);
                #pragma unroll
                for (int jj = 0; jj < 4; jj++) ldsm_x4(B[jj], bAddr[jj] + koff);
                #pragma unroll
                for (int jj = 0; jj < 4; jj++){
                    u32 b0[2] = { B[jj][0], B[jj][2] };
                    u32 b1[2] = { B[jj][1], B[jj][3] };
                    mma16816(acc[0][2*jj],   A0, b0);
                    mma16816(acc[0][2*jj+1], A0, b1);
                    mma16816(acc[1][2*jj],   A1, b0);
                    mma16816(acc[1][2*jj+1], A1, b1);
                }
            }
        }
        __syncthreads();
        const float* bl = l ? (br + (l-1)*128) : bh;
        const bf16* Xin = Sg + (size_t)(128*l)*NP;
        bf16* Yg = Sg + (size_t)(128*(l+1))*NP;
        #pragma unroll
        for (int i = 0; i < 2; i++){
            #pragma unroll
            for (int j = 0; j < 8; j++){
                int row = wm*32 + i*16 + qr;
                int col = wn*64 + j*8 + qc*2;
                #pragma unroll
                for (int h = 0; h < 2; h++){
                    int rr = row + h*8;
                    float b0 = bl[rr];
                    float v0 = acc[i][j][2*h+0] + b0; v0 = v0 > 0.f ? v0 : 0.f;
                    float v1 = acc[i][j][2*h+1] + b0; v1 = v1 > 0.f ? v1 : 0.f;
                    if (l > 0){
                        u32 xv = *(const u32*)(Xin + rr*NP + col);
                        v0 += __bfloat162float(((bf16*)&xv)[0]);
                        v1 += __bfloat162float(((bf16*)&xv)[1]);
                    }
                    bf16 h0 = __float2bfloat16(v0), h1 = __float2bfloat16(v1);
                    u32 pk = ((u32)*(unsigned short*)&h1 << 16) | (u32)*(unsigned short*)&h0;
                    *(u32*)(Yg + rr*NP + col) = pk;
                    Xt[col*136 + rr]     = h0;
                    Xt[(col+1)*136 + rr] = h1;
                }
            }
        }
    }
}

// ---- fuse GEMM ----
__global__ void __launch_bounds__(256, 2) k_mma_fuse(
    const bf16* __restrict__ W, const float* __restrict__ bias,
    const bf16* __restrict__ Xbase, bf16* __restrict__ Ybase)
{
    extern __shared__ bf16 sm[];
    bf16* Wb[2] = { sm, sm + 128*72 };
    bf16* Bb[2] = { sm + 2*128*72, sm + 3*128*72 };
    int inst = blockIdx.x, mblk = blockIdx.y;
    const bf16* Xg = Xbase + (size_t)inst*(ST_CH*NP);
    bf16* Yg = Ybase + (size_t)inst*(256*NP) + (size_t)mblk*128*NP;
    const bf16* Wm = W + (size_t)mblk*128*KTOT;
    int tid = threadIdx.x, warp = tid >> 5, lane = tid & 31;
    int wm = warp >> 1, wn = warp & 1, qr = lane >> 2, qc = lane & 3;
    int laneRow = lane & 15, laneHi = lane >> 4;
    float acc[2][8][4];
    #pragma unroll
    for (int i = 0; i < 2; i++)
        #pragma unroll
        for (int j = 0; j < 8; j++)
            #pragma unroll
            for (int q = 0; q < 4; q++) acc[i][j][q] = 0.f;
    int ph = tid & 63, cc = tid >> 6;

    {
        #pragma unroll
        for (int q = 0; q < 4; q++){
            int idx = q*256 + tid;
            int row = idx >> 3, seg = idx & 7;
            cpa16(s2u(Wb[0] + row*72 + seg*8), Wm + (size_t)row*KTOT + seg*8);
        }
        CP_COMMIT();
        #pragma unroll
        for (int q = 0; q < 16; q++){
            int c = 4*q + cc;
            u32 v = *(const u32*)(Xg + (size_t)c*NP + ph*2);
            Bb[0][(2*ph)*72 + c]   = ((bf16*)&v)[0];
            Bb[0][(2*ph+1)*72 + c] = ((bf16*)&v)[1];
        }
    }
    u32 aWa[2], bBa[2];
    #pragma unroll
    for (int z = 0; z < 2; z++){
        aWa[z] = s2u(Wb[z]) + (u32)((wm*32 + laneRow)*144 + laneHi*16);
        bBa[z] = s2u(Bb[z]) + (u32)((wn*64 + laneRow)*144 + laneHi*16);
    }
    #pragma unroll 1
    for (int chn = 0; chn < 18; chn++){
        CP_WAIT0();
        __syncthreads();
        u32 vreg[16];
        if (chn < 17){
            int k0 = (chn+1)*64;
            #pragma unroll
            for (int q = 0; q < 16; q++)
                vreg[q] = *(const u32*)(Xg + (size_t)(k0 + 4*q + cc)*NP + ph*2);
            bf16* dstw = Wb[(chn+1) & 1];
            const bf16* srcw = Wm + k0;
            #pragma unroll
            for (int q = 0; q < 4; q++){
                int idx = q*256 + tid;
                int row = idx >> 3, seg = idx & 7;
                cpa16(s2u(dstw + row*72 + seg*8), srcw + (size_t)row*KTOT + seg*8);
            }
            CP_COMMIT();
        }
        u32 aA = aWa[chn & 1];
        u32 bA = bBa[chn & 1];
        #pragma unroll
        for (int cq = 0; cq < 4; cq++){
            u32 koff = (u32)(cq*32);
            u32 A0[4], A1[4], B0[4], B1[4];
            ldsm_x4(A0, aA + koff);
            ldsm_x4(A1, aA + 16*144 + koff);
            ldsm_x4(B0, bA + koff);
            ldsm_x4(B1, bA + 16*144 + koff);
            {
                u32 b0[2] = { B0[0], B0[2] }, b1[2] = { B0[1], B0[3] };
                u32 b2[2] = { B1[0], B1[2] }, b3[2] = { B1[1], B1[3] };
                mma16816(acc[0][0], A0, b0); mma16816(acc[0][1], A0, b1);
                mma16816(acc[0][2], A0, b2); mma16816(acc[0][3], A0, b3);
                mma16816(acc[1][0], A1, b0); mma16816(acc[1][1], A1, b1);
                mma16816(acc[1][2], A1, b2); mma16816(acc[1][3], A1, b3);
            }
            u32 B2[4], B3[4];
            ldsm_x4(B2, bA + 32*144 + koff);
            ldsm_x4(B3, bA + 48*144 + koff);
            {
                u32 b0[2] = { B2[0], B2[2] }, b1[2] = { B2[1], B2[3] };
                u32 b2[2] = { B3[0], B3[2] }, b3[2] = { B3[1], B3[3] };
                mma16816(acc[0][4], A0, b0); mma16816(acc[0][5], A0, b1);
                mma16816(acc[0][6], A0, b2); mma16816(acc[0][7], A0, b3);
                mma16816(acc[1][4], A1, b0); mma16816(acc[1][5], A1, b1);
                mma16816(acc[1][6], A1, b2); mma16816(acc[1][7], A1, b3);
            }
        }
        if (chn < 17){
            bf16* dstb = Bb[(chn+1) & 1];
            #pragma unroll
            for (int q = 0; q < 16; q++){
                int c = 4*q + cc;
                dstb[(2*ph)*72 + c]   = ((bf16*)&vreg[q])[0];
                dstb[(2*ph+1)*72 + c] = ((bf16*)&vreg[q])[1];
            }
        }
    }
    #pragma unroll
    for (int i = 0; i < 2; i++){
        #pragma unroll
        for (int j = 0; j < 8; j++){
            int row = wm*32 + i*16 + qr;
            int col = wn*64 + j*8 + qc*2;
            #pragma unroll
            for (int h = 0; h < 2; h++){
                int rr = row + h*8;
                float b0 = bias[mblk*128 + rr];
                float v0 = acc[i][j][2*h+0] + b0; v0 = v0 > 0.f ? v0 : 0.f;
                float v1 = acc[i][j][2*h+1] + b0; v1 = v1 > 0.f ? v1 : 0.f;
                Yg[rr*NP + col]     = __float2bfloat16(v0);
                Yg[rr*NP + col + 1] = __float2bfloat16(v1);
            }
        }
    }
}

// ---------------- p1: 256 -> 64 ----------------
__global__ void k_p1(const float* __restrict__ Wt, const float* __restrict__ bias){
    __shared__ float Xs[16*128];
    __shared__ float WsT[16*64];
    int inst = blockIdx.x;
    const bf16* Xg = g_fuse + (size_t)inst*256*NP;
    float* Yg = g_hbuf + (size_t)inst*64*NP;
    int tid = threadIdx.x;
    int tx = tid & 15, ty = tid >> 4;
    u64 acc[4][8];
    #pragma unroll
    for (int i = 0; i < 4; i++)
        #pragma unroll
        for (int j = 0; j < 8; j++) acc[i][j] = 0ULL;
    for (int k0 = 0; k0 < 256; k0 += 16){
        __syncthreads();
        for (int i = tid; i < 16*128; i += 128) Xs[i] = __bfloat162float(Xg[k0*128 + i]);
        for (int i = tid; i < 16*64; i += 128) WsT[i] = Wt[k0*64 + i];
        __syncthreads();
        for (int kk = 0; kk < 16; kk++){
            const u64* wr = (const u64*)(WsT + kk*64 + ty*8);
            u64 xv[8];
            #pragma unroll
            for (int j = 0; j < 8; j++) xv[j] = bcast2(Xs[kk*128 + tx + 16*j]);
            #pragma unroll
            for (int i = 0; i < 4; i++){
                u64 wv = wr[i];
                #pragma unroll
                for (int j = 0; j < 8; j++) ffma2(acc[i][j], wv, xv[j]);
            }
        }
    }
    #pragma unroll
    for (int i = 0; i < 4; i++){
        int o0 = ty*8 + 2*i;
        float b0 = bias[o0], b1 = bias[o0+1];
        #pragma unroll
        for (int j = 0; j < 8; j++){
            float2 v = unpack2(acc[i][j]);
            float v0 = v.x + b0; v0 = v0 > 0.f ? v0 : 0.f;
            float v1 = v.y + b1; v1 = v1 > 0.f ? v1 : 0.f;
            Yg[o0*128 + tx + 16*j] = v0;
            Yg[(o0+1)*128 + tx + 16*j] = v1;
        }
    }
}

// ---------------- p2: 64 -> 2 ----------------
__global__ void k_p2(const float* __restrict__ w, const float* __restrict__ b){
    int inst = blockIdx.x;
    int p = threadIdx.x;
    const float* X = g_hbuf + (size_t)inst*64*NP;
    float a0 = 0.f, a1 = 0.f;
    for (int c = 0; c < 64; c++){
        float xv = X[c*NP + p];
        a0 += w[c]*xv;
        a1 += w[64 + c]*xv;
    }
    g_off[inst*2*NP + p]      = a0 + b[0];
    g_off[inst*2*NP + NP + p] = a1 + b[1];
}

__global__ void k_update(){
    int i = blockIdx.x*blockDim.x + threadIdx.x;
    if (i >= NINST*NP) return;
    int inst = i >> 7, p = i & 127;
    g_pts[i*2+0] += g_off[inst*2*NP + p];
    g_pts[i*2+1] += g_off[inst*2*NP + NP + p];
}

// ---------------- output assembly ----------------
__global__ void k_out(float* __restrict__ out){
    int i = blockIdx.x*blockDim.x + threadIdx.x;
    const int n_det = NINST*6;
    const int n_ct  = NINST*2;
    const int n_pts = NINST*NP*2;
    if (i < n_det){ out[i] = g_det[i]; return; }
    int j = i - n_det;
    if (j < n_ct){ out[i] = g_ct[j]; return; }
    j -= n_ct;
    if (j < n_pts){
        int inst = j / (NP*2);
        out[i] = g_valid[inst] ? g_pts[j] : 0.0f;
        return;
    }
    j -= n_pts;
    if (j < NINST) out[i] = g_valid[j] ? 1.0f : 0.0f;
}

// ---------------- host launcher ----------------
extern "C" void kernel_launch(void* const* d_in, const int* in_sizes, int n_in,
                              void* d_out, int out_size)
{
    const float* pred   = (const float*)d_in[0];
    const float* feat   = (const float*)d_in[1];
    const float* conv_w = (const float*)d_in[2];
    const float* conv_b = (const float*)d_in[3];
    const float* b_head = (const float*)d_in[5];
    const float* b_res  = (const float*)d_in[7];
    const float* b_fuse = (const float*)d_in[9];
    const float* b_p1   = (const float*)d_in[11];
    const float* w_p2   = (const float*)d_in[12];
    const float* b_p2   = (const float*)d_in[13];

    cudaFuncSetAttribute(k_topk, cudaFuncAttributeMaxDynamicSharedMemorySize, 26400*8);
    cudaFuncSetAttribute(k_snake, cudaFuncAttributeMaxDynamicSharedMemorySize, 104448);
    cudaFuncSetAttribute(k_mma_fuse, cudaFuncAttributeMaxDynamicSharedMemorySize, 73728);

    void *pv;
    cudaGetSymbolAddress(&pv, g_states); bf16* p_states = (bf16*)pv;
    cudaGetSymbolAddress(&pv, g_fuse);   bf16* p_fuse = (bf16*)pv;
    cudaGetSymbolAddress(&pv, g_whb);    bf16* p_whb = (bf16*)pv;
    cudaGetSymbolAddress(&pv, g_wrb);    bf16* p_wrb = (bf16*)pv;
    cudaGetSymbolAddress(&pv, g_wfb);    bf16* p_wfb = (bf16*)pv;
    cudaGetSymbolAddress(&pv, g_wp1t);   float* p_wp1t = (float*)pv;

    // side stream for the feature path (fork/join via events; created per call,
    // never destroyed mid-capture — only 2 calls total so no meaningful leak)
    cudaStream_t s1;
    cudaStreamCreate(&s1);
    cudaEvent_t e0, e1;
    cudaEventCreateWithFlags(&e0, cudaEventDisableTiming);
    cudaEventCreateWithFlags(&e1, cudaEventDisableTiming);

    // fork
    cudaEventRecord(e0, 0);
    cudaStreamWaitEvent(s1, e0, 0);
    // feature path on s1
    k_up<<<(int)(((long long)NB*128*160*160 + 255)/256), 256, 0, s1>>>(feat);
    k_conv3<<<dim3(400, NB), 512, 0, s1>>>(conv_w, conv_b);
    cudaEventRecord(e1, s1);

    // detection + weight path on default stream
    {
        int n = 128*KTOT + 7*128*KTOT + 256*KTOT + 256*64;
        k_wtrans<<<(n + 255)/256, 256>>>((const float*)d_in[4], (const float*)d_in[6],
                                         (const float*)d_in[8], (const float*)d_in[10]);
    }
    k_scores<<<(NB*NPRED + 255)/256, 256>>>(pred);
    k_topk<<<NB, 1024, 26400*8>>>();
    k_prep<<<(NINST + 255)/256, 256>>>(pred);
    k_nms<<<NB, 256>>>();
    k_initpts<<<(NINST*NP + 255)/256, 256>>>();

    // join: snake loop needs conv features
    cudaStreamWaitEvent(0, e1, 0);

    for (int it = 0; it < 2; it++){
        k_sample<<<NINST, 128>>>();
        k_snake<<<NINST, 256, 104448>>>(p_whb, p_wrb, b_head, b_res, p_states);
        k_mma_fuse<<<dim3(NINST, 2), 256, 73728>>>(p_wfb, b_fuse, p_states, p_fuse);
        k_p1<<<NINST, 128>>>(p_wp1t, b_p1);
        k_p2<<<NINST, 128>>>(w_p2, b_p2);
        k_update<<<(NINST*NP + 255)/256, 256>>>();
    }
    {
        int n = NINST*6 + NINST*2 + NINST*NP*2 + NINST;
        k_out<<<(n + 255)/256, 256>>>((float*)d_out);
    }
}

// round 14
// speedup vs baseline: 1.0536x; 1.0333x over previous
#include <cuda_runtime.h>
#include <cuda_bf16.h>
#include <cuda_fp16.h>
#include <math.h>

#define NB 16
#define NPRED 25200
#define NCLS 80
#define KDET 300
#define NP 128
#define NINST (NB*KDET)
#define ST_CH 1152
#define KTOT 1152

typedef unsigned long long u64;
typedef unsigned int u32;
typedef __nv_bfloat16 bf16;

__device__ __forceinline__ void ffma2(u64& acc, u64 a, u64 b){
    asm("fma.rn.f32x2 %0, %1, %2, %3;" : "=l"(acc) : "l"(a), "l"(b), "l"(acc));
}
__device__ __forceinline__ u64 bcast2(float x){
    u64 r;
    asm("mov.b64 %0, {%1, %1};" : "=l"(r) : "r"(__float_as_uint(x)));
    return r;
}
__device__ __forceinline__ float2 unpack2(u64 v){
    float2 f;
    asm("mov.b64 {%0, %1}, %2;" : "=f"(f.x), "=f"(f.y) : "l"(v));
    return f;
}
__device__ __forceinline__ u32 s2u(const void* p){
    u32 a; asm("{ .reg .u64 t; cvta.to.shared.u64 t, %1; cvt.u32.u64 %0, t; }" : "=r"(a) : "l"(p));
    return a;
}
__device__ __forceinline__ void cpa16(u32 dst, const void* src){
    asm volatile("cp.async.cg.shared.global [%0], [%1], 16;" :: "r"(dst), "l"(src));
}
#define CP_COMMIT() asm volatile("cp.async.commit_group;" ::: "memory")
#define CP_WAIT0()  asm volatile("cp.async.wait_group 0;" ::: "memory")

__device__ __forceinline__ void ldsm_x4(u32* r, u32 addr){
    asm volatile("ldmatrix.sync.aligned.m8n8.x4.shared.b16 {%0,%1,%2,%3}, [%4];"
        : "=r"(r[0]), "=r"(r[1]), "=r"(r[2]), "=r"(r[3]) : "r"(addr));
}

// ---------------- device scratch ----------------
__device__ float g_score[NB*NPRED];
__device__ int   g_cls[NB*NPRED];
__device__ int   g_topidx[NINST];
__device__ float g_tops[NINST];
__device__ float g_boxes[NINST*4];
__device__ float g_det[NINST*6];
__device__ float g_ct[NINST*2];
__device__ float g_half[NINST*2];
__device__ float g_clsf[NINST];
__device__ int   g_valid[NINST];
__device__ float g_up[(size_t)NB*128*160*160];
__device__ __half g_cfh[(size_t)NB*160*160*64];
__device__ float g_pts[NINST*NP*2];
__device__ float g_off[NINST*2*NP];
__device__ float g_hbuf[(size_t)NINST*64*NP];
__device__ bf16  g_states[(size_t)NINST*ST_CH*NP];
__device__ bf16  g_fuse[(size_t)NINST*256*NP];
__device__ bf16  g_whb[128*KTOT];      // head W [o][k=t*128+c]
__device__ bf16  g_wrb[7*128*KTOT];    // res  W [l][o][k=t*128+c]
__device__ bf16  g_wfb[256*KTOT];      // fuse W [o][k]
__device__ bf16  g_wp1b[64*256];       // p1 W [o][k] bf16

// ---------------- weight transposition ----------------
__global__ void k_wtrans(const float* __restrict__ wh, const float* __restrict__ wr,
                         const float* __restrict__ wf, const float* __restrict__ wp1)
{
    int i = blockIdx.x*blockDim.x + threadIdx.x;
    const int n1 = 128*KTOT;
    const int n2 = 7*128*KTOT;
    const int n3 = 256*KTOT;
    const int n4 = 64*256;
    if (i < n1){
        int o = i / KTOT, k = i % KTOT, t = k >> 7, c = k & 127;
        g_whb[i] = __float2bfloat16(c < 66 ? wh[(o*66 + c)*9 + t] : 0.f);
        return;
    }
    i -= n1;
    if (i < n2){
        int l = i / (128*KTOT), r = i % (128*KTOT);
        int o = r / KTOT, k = r % KTOT, t = k >> 7, c = k & 127;
        g_wrb[i] = __float2bfloat16(wr[(((size_t)l*128 + o)*128 + c)*9 + t]);
        return;
    }
    i -= n2;
    if (i < n3){
        int o = i / KTOT, k = i % KTOT;
        float v = 0.f;
        if (k < 66) v = wf[o*1090 + k];
        else if (k >= 128) v = wf[o*1090 + k - 62];
        g_wfb[i] = __float2bfloat16(v);
        return;
    }
    i -= n3;
    if (i < n4){
        g_wp1b[i] = __float2bfloat16(wp1[i]);   // [o][k] direct
    }
}

// ---------------- stage 1: scores ----------------
__global__ void k_scores(const float* __restrict__ pred){
    int i = blockIdx.x*blockDim.x + threadIdx.x;
    if (i >= NB*NPRED) return;
    const float* r = pred + (size_t)i*85;
    float obj = r[4];
    float best = -1e30f; int bc = 0;
    for (int c = 0; c < NCLS; c++){
        float s = obj * r[5+c];
        if (s > best){ best = s; bc = c; }
    }
    g_score[i] = (best > 0.2f) ? best : 0.0f;
    g_cls[i] = bc;
}

// ---------------- stage 2: stable top-300 ----------------
__global__ void __launch_bounds__(1024) k_topk(){
    extern __shared__ unsigned long long smk[];
    unsigned long long* keys = smk;
    unsigned long long* l1   = smk + 25600;
    __shared__ unsigned long long red[32];
    int b = blockIdx.x, tid = threadIdx.x;
    for (int i = tid; i < 25600; i += 1024){
        unsigned long long k = 0ULL;
        if (i < NPRED){
            unsigned u = __float_as_uint(g_score[b*NPRED + i]);
            k = ((unsigned long long)u << 32) | (unsigned)(~i);
        }
        keys[i] = k;
    }
    __syncthreads();
    if (tid < 800){
        unsigned long long m = 0ULL;
        for (int j = 0; j < 32; j++){ unsigned long long v = keys[tid*32 + j]; if (v > m) m = v; }
        l1[tid] = m;
    }
    __syncthreads();
    for (int it = 0; it < KDET; it++){
        unsigned long long v = (tid < 800) ? l1[tid] : 0ULL;
        #pragma unroll
        for (int o = 16; o > 0; o >>= 1){
            unsigned long long t2 = __shfl_down_sync(0xffffffffu, v, o);
            if (t2 > v) v = t2;
        }
        if ((tid & 31) == 0) red[tid >> 5] = v;
        __syncthreads();
        if (tid < 32){
            v = red[tid];
            #pragma unroll
            for (int o = 16; o > 0; o >>= 1){
                unsigned long long t2 = __shfl_down_sync(0xffffffffu, v, o);
                if (t2 > v) v = t2;
            }
            if (tid == 0) red[0] = v;
        }
        __syncthreads();
        unsigned long long w = red[0];
        int idx = (int)(~(unsigned)w);
        if (tid < 32){
            int ch = idx >> 5;
            if (tid == 0) keys[idx] = 0ULL;
            __syncwarp();
            unsigned long long kv = keys[ch*32 + tid];
            #pragma unroll
            for (int o = 16; o > 0; o >>= 1){
                unsigned long long t2 = __shfl_down_sync(0xffffffffu, kv, o);
                if (t2 > kv) kv = t2;
            }
            if (tid == 0){
                l1[ch] = kv;
                g_topidx[b*KDET + it] = idx;
                g_tops[b*KDET + it] = __uint_as_float((unsigned)(w >> 32));
            }
        }
        __syncthreads();
    }
}

// ---------------- stage 3 ----------------
__global__ void k_prep(const float* __restrict__ pred){
    int i = blockIdx.x*blockDim.x + threadIdx.x;
    if (i >= NINST) return;
    int b = i / KDET;
    int src = g_topidx[i];
    const float* r = pred + ((size_t)b*NPRED + src)*85;
    float cx = r[0], cy = r[1], w = r[2], h = r[3];
    float hw = w*0.5f, hh = h*0.5f;
    float x1 = cx - hw, y1 = cy - hh, x2 = cx + hw, y2 = cy + hh;
    g_boxes[4*i+0] = x1; g_boxes[4*i+1] = y1; g_boxes[4*i+2] = x2; g_boxes[4*i+3] = y2;
    float cf = (float)g_cls[b*NPRED + src];
    g_clsf[i] = cf;
    float sc = g_tops[i];
    g_det[6*i+0] = x1; g_det[6*i+1] = y1; g_det[6*i+2] = x2; g_det[6*i+3] = y2;
    g_det[6*i+4] = sc; g_det[6*i+5] = cf;
    float b0 = x1*0.25f, b1 = y1*0.25f, b2 = x2*0.25f, b3 = y2*0.25f;
    g_ct[2*i+0] = (b0 + b2)*0.5f;
    g_ct[2*i+1] = (b1 + b3)*0.5f;
    g_half[2*i+0] = fmaxf((b2 - b0)*0.5f, 1e-3f);
    g_half[2*i+1] = fmaxf((b3 - b1)*0.5f, 1e-3f);
}

// ---------------- stage 4: NMS ----------------
__global__ void k_nms(){
    __shared__ float bx[KDET][4];
    __shared__ float ar[KDET];
    __shared__ float sc[KDET];
    __shared__ int keep[KDET];
    int b = blockIdx.x, tid = threadIdx.x;
    for (int i = tid; i < KDET; i += 256){
        int g = b*KDET + i;
        float off = g_clsf[g]*4096.0f;
        float x1 = g_boxes[4*g+0] + off, y1 = g_boxes[4*g+1] + off;
        float x2 = g_boxes[4*g+2] + off, y2 = g_boxes[4*g+3] + off;
        bx[i][0] = x1; bx[i][1] = y1; bx[i][2] = x2; bx[i][3] = y2;
        ar[i] = (x2 - x1)*(y2 - y1);
        sc[i] = g_tops[g];
        keep[i] = 1;
    }
    __syncthreads();
    for (int i = 0; i < KDET; i++){
        if (keep[i]){
            float ax1 = bx[i][0], ay1 = bx[i][1], ax2 = bx[i][2], ay2 = bx[i][3], aa = ar[i];
            for (int j = i + 1 + tid; j < KDET; j += 256){
                float iw = fminf(ax2, bx[j][2]) - fmaxf(ax1, bx[j][0]);
                float ih = fminf(ay2, bx[j][3]) - fmaxf(ay1, bx[j][1]);
                iw = fmaxf(iw, 0.f); ih = fmaxf(ih, 0.f);
                float inter = iw*ih;
                float iou = inter / (aa + ar[j] - inter + 1e-9f);
                if (iou > 0.3f) keep[j] = 0;
            }
        }
        __syncthreads();
    }
    for (int i = tid; i < KDET; i += 256)
        g_valid[b*KDET + i] = (keep[i] && (sc[i] > 0.2f)) ? 1 : 0;
}

// ---------------- stage 5: upsample ----------------
__global__ void k_up(const float* __restrict__ feat){
    long long idx = (long long)blockIdx.x*256 + threadIdx.x;
    if (idx >= (long long)NB*128*160*160) return;
    int ox = (int)(idx % 160); long long r = idx/160;
    int oy = (int)(r % 160); r /= 160;
    int c = (int)(r % 128); int b = (int)(r/128);
    int iy = oy >> 1, ix = ox >> 1;
    int ya, yb; float wya, wyb;
    if (oy & 1){ ya = iy; yb = iy+1; wya = 0.75f; wyb = 0.25f; }
    else       { ya = iy-1; yb = iy; wya = 0.25f; wyb = 0.75f; }
    int xa, xb; float wxa, wxb;
    if (ox & 1){ xa = ix; xb = ix+1; wxa = 0.75f; wxb = 0.25f; }
    else       { xa = ix-1; xb = ix; wxa = 0.25f; wxb = 0.75f; }
    ya = max(0, min(79, ya)); yb = max(0, min(79, yb));
    xa = max(0, min(79, xa)); xb = max(0, min(79, xb));
    const float* f = feat + ((size_t)b*128 + c)*6400;
    float v = wya*(wxa*f[ya*80+xa] + wxb*f[ya*80+xb])
            + wyb*(wxa*f[yb*80+xa] + wxb*f[yb*80+xb]);
    g_up[idx] = v;
}

// ---------------- stage 6: 3x3 conv + SiLU (FFMA2) -> channel-last f16 ----------------
__global__ void __launch_bounds__(512) k_conv3(const float* __restrict__ Wc, const float* __restrict__ Bc){
    __shared__ float Xs[16][10][10];
    __shared__ float Wsp[16][9][64];
    int b = blockIdx.y;
    int tile = blockIdx.x;
    int ty0 = (tile/20)*8, tx0 = (tile%20)*8;
    int tid = threadIdx.x;
    int px = tid & 7, py = (tid >> 3) & 7, og = tid >> 6;
    u64 acc2[4] = {0ULL, 0ULL, 0ULL, 0ULL};
    for (int c0 = 0; c0 < 128; c0 += 16){
        __syncthreads();
        for (int i = tid; i < 1600; i += 512){
            int c = i/100, r = i%100, yy = r/10, xx = r%10;
            int gy = ty0 - 1 + yy, gx = tx0 - 1 + xx;
            float v = 0.f;
            if (gy >= 0 && gy < 160 && gx >= 0 && gx < 160)
                v = g_up[(((size_t)b*128 + c0 + c)*160 + gy)*160 + gx];
            Xs[c][yy][xx] = v;
        }
        for (int i = tid; i < 9216; i += 512){
            int o = i & 63, r = i >> 6, c = r/9, t = r%9;
            Wsp[c][t][o] = Wc[(o*128 + c0 + c)*9 + t];
        }
        __syncthreads();
        for (int c = 0; c < 16; c++){
            #pragma unroll
            for (int t = 0; t < 9; t++){
                u64 xv = bcast2(Xs[c][py + t/3][px + t%3]);
                const u64* wr = (const u64*)(&Wsp[c][t][og*8]);
                #pragma unroll
                for (int i = 0; i < 4; i++) ffma2(acc2[i], wr[i], xv);
            }
        }
    }
    int oy = ty0 + py, ox = tx0 + px;
    __half hv[8];
    #pragma unroll
    for (int i = 0; i < 4; i++){
        float2 v2 = unpack2(acc2[i]);
        int o0 = og*8 + 2*i;
        float v0 = v2.x + Bc[o0];
        float v1 = v2.y + Bc[o0+1];
        v0 = v0 / (1.f + expf(-v0));
        v1 = v1 / (1.f + expf(-v1));
        hv[2*i]   = __float2half(v0);
        hv[2*i+1] = __float2half(v1);
    }
    *(uint4*)(g_cfh + (((size_t)b*160 + oy)*160 + ox)*64 + og*8) = *(uint4*)hv;
}

// ---------------- stage 7/8 ----------------
__global__ void k_initpts(){
    int i = blockIdx.x*blockDim.x + threadIdx.x;
    if (i >= NINST*NP) return;
    int inst = i >> 7, p = i & 127;
    float th = (float)p * 0.049087385212340517f;
    g_pts[i*2+0] = g_ct[inst*2+0] + g_half[inst*2+0]*cosf(th);
    g_pts[i*2+1] = g_ct[inst*2+1] + g_half[inst*2+1]*sinf(th);
}

__global__ void k_sample(){
    int inst = blockIdx.x;
    int p = threadIdx.x;
    int b = inst / KDET;
    float px = g_pts[(inst*NP + p)*2 + 0], py = g_pts[(inst*NP + p)*2 + 1];
    float x = fminf(fmaxf(px, 0.f), 159.f);
    float y = fminf(fmaxf(py, 0.f), 159.f);
    float x0f = fminf(fmaxf(floorf(x), 0.f), 158.f);
    float y0f = fminf(fmaxf(floorf(y), 0.f), 158.f);
    int x0 = (int)x0f, y0 = (int)y0f;
    float dx = x - x0f, dy = y - y0f;
    float w00 = (1.f-dx)*(1.f-dy), w10 = dx*(1.f-dy), w01 = (1.f-dx)*dy, w11 = dx*dy;
    const __half* f = g_cfh + (size_t)b*25600*64;
    size_t base = (size_t)(y0*160 + x0)*64;
    const uint4* c00 = (const uint4*)(f + base);
    const uint4* c01 = (const uint4*)(f + base + 64);
    const uint4* c10 = (const uint4*)(f + base + 160*64);
    const uint4* c11 = (const uint4*)(f + base + 160*64 + 64);
    bf16* Z = g_states + (size_t)inst*ST_CH*NP;
    #pragma unroll
    for (int q = 0; q < 8; q++){
        uint4 a = c00[q], bq = c01[q], cq = c10[q], dq = c11[q];
        const __half2* ah = (const __half2*)&a;
        const __half2* bh = (const __half2*)&bq;
        const __half2* ch = (const __half2*)&cq;
        const __half2* dh = (const __half2*)&dq;
        #pragma unroll
        for (int j = 0; j < 4; j++){
            float2 fa = __half22float2(ah[j]);
            float2 fb = __half22float2(bh[j]);
            float2 fc = __half22float2(ch[j]);
            float2 fd = __half22float2(dh[j]);
            float v0 = fa.x*w00 + fb.x*w10 + fc.x*w01 + fd.x*w11;
            float v1 = fa.y*w00 + fb.y*w10 + fc.y*w01 + fd.y*w11;
            int c = q*8 + j*2;
            Z[c*NP + p]     = __float2bfloat16(v0);
            Z[(c+1)*NP + p] = __float2bfloat16(v1);
        }
    }
    float cx = g_ct[inst*2+0], cy = g_ct[inst*2+1];
    float hx = g_half[inst*2+0], hy = g_half[inst*2+1];
    Z[64*NP + p] = __float2bfloat16((px - cx)/hx);
    Z[65*NP + p] = __float2bfloat16((py - cy)/hy);
    bf16 z0 = __float2bfloat16(0.f);
    for (int c = 66; c < 128; c++) Z[c*NP + p] = z0;
}

// ---------------- bf16 warp-MMA ----------------
__device__ __forceinline__ void mma16816(float* d, const u32* a, const u32* b){
    asm volatile("mma.sync.aligned.m16n8k16.row.col.f32.bf16.bf16.f32 "
        "{%0,%1,%2,%3}, {%4,%5,%6,%7}, {%8,%9}, {%0,%1,%2,%3};"
        : "+f"(d[0]), "+f"(d[1]), "+f"(d[2]), "+f"(d[3])
        : "r"(a[0]), "r"(a[1]), "r"(a[2]), "r"(a[3]), "r"(b[0]), "r"(b[1]));
}

// ---- fused snake stack ----
__global__ void __launch_bounds__(256, 2) k_snake(
    const bf16* __restrict__ Wh, const bf16* __restrict__ Wr,
    const float* __restrict__ bh, const float* __restrict__ br,
    bf16* __restrict__ Sbase)
{
    extern __shared__ bf16 sm[];
    bf16* Xt  = sm;
    bf16* Wb0 = sm + 128*136;
    bf16* Wb1 = Wb0 + 128*136;
    int inst = blockIdx.x;
    bf16* Sg = Sbase + (size_t)inst*(ST_CH*NP);
    int tid = threadIdx.x, warp = tid >> 5, lane = tid & 31;
    int wm = warp >> 1, wn = warp & 1, qr = lane >> 2, qc = lane & 3;
    int laneRow = lane & 15, laneHi = lane >> 4;

    #pragma unroll
    for (int q = 0; q < 8; q++){
        int idx = q*256 + tid;
        int row = idx >> 4, seg = idx & 15;
        cpa16(s2u(Wb0 + row*136 + seg*8), Wh + (size_t)row*KTOT + seg*8);
    }
    CP_COMMIT();
    {
        int ph = tid & 63, cc = tid >> 6;
        #pragma unroll
        for (int cb = 0; cb < 128; cb += 4){
            int c = cb + cc;
            u32 v = *(const u32*)(Sg + c*NP + ph*2);
            Xt[(2*ph)*136 + c]   = ((bf16*)&v)[0];
            Xt[(2*ph+1)*136 + c] = ((bf16*)&v)[1];
        }
    }
    u32 xtb = s2u(Xt);
    u32 aW0 = s2u(Wb0) + (u32)((wm*32 + laneRow)*272 + laneHi*16);
    u32 aW1 = s2u(Wb1) + (u32)((wm*32 + laneRow)*272 + laneHi*16);
    const int DILS[8] = {1,1,1,1,2,2,4,4};

    #pragma unroll 1
    for (int l = 0; l < 8; l++){
        int dil = DILS[l];
        int offs[9];
        #pragma unroll
        for (int t = 0; t < 9; t++) offs[t] = (dil*(t-4) + 128) & 127;
        float acc[2][8][4];
        #pragma unroll
        for (int i = 0; i < 2; i++)
            #pragma unroll
            for (int j = 0; j < 8; j++)
                #pragma unroll
                for (int q = 0; q < 4; q++) acc[i][j][q] = 0.f;

        #pragma unroll 1
        for (int t = 0; t < 9; t++){
            CP_WAIT0();
            __syncthreads();
            int g = l*9 + t;
            if (g < 71){
                int gn = g + 1, ln = gn/9, tn = gn - ln*9;
                const bf16* src = (ln ? (Wr + (size_t)(ln-1)*128*KTOT) : Wh) + tn*128;
                bf16* dstb = (gn & 1) ? Wb1 : Wb0;
                #pragma unroll
                for (int q = 0; q < 8; q++){
                    int idx = q*256 + tid;
                    int row = idx >> 4, seg = idx & 15;
                    cpa16(s2u(dstb + row*136 + seg*8), src + (size_t)row*KTOT + seg*8);
                }
                CP_COMMIT();
            }
            u32 aA = (g & 1) ? aW1 : aW0;
            u32 bAddr[4];
            #pragma unroll
            for (int jj = 0; jj < 4; jj++){
                int row = (wn*64 + jj*16 + laneRow + offs[t]) & 127;
                bAddr[jj] = xtb + (u32)(row*272 + laneHi*16);
            }
            #pragma unroll
            for (int cq2 = 0; cq2 < 8; cq2++){
                if (l == 0 && cq2 >= 5) continue;   // channels 80..127 exactly zero in layer 0
                u32 koff = (u32)(cq2*32);
                u32 A0[4], A1[4], B[4][4];
                ldsm_x4(A0, aA + koff);
                ldsm_x4(A1, aA + 16*272 + koff);
                #pragma unroll
                for (int jj = 0; jj < 4; jj++) ldsm_x4(B[jj], bAddr[jj] + koff);
                #pragma unroll
                for (int jj = 0; jj < 4; jj++){
                    u32 b0[2] = { B[jj][0], B[jj][2] };
                    u32 b1[2] = { B[jj][1], B[jj][3] };
                    mma16816(acc[0][2*jj],   A0, b0);
                    mma16816(acc[0][2*jj+1], A0, b1);
                    mma16816(acc[1][2*jj],   A1, b0);
                    mma16816(acc[1][2*jj+1], A1, b1);
                }
            }
        }
        __syncthreads();
        const float* bl = l ? (br + (l-1)*128) : bh;
        const bf16* Xin = Sg + (size_t)(128*l)*NP;
        bf16* Yg = Sg + (size_t)(128*(l+1))*NP;
        #pragma unroll
        for (int i = 0; i < 2; i++){
            #pragma unroll
            for (int j = 0; j < 8; j++){
                int row = wm*32 + i*16 + qr;
                int col = wn*64 + j*8 + qc*2;
                #pragma unroll
                for (int h = 0; h < 2; h++){
                    int rr = row + h*8;
                    float b0 = bl[rr];
                    float v0 = acc[i][j][2*h+0] + b0; v0 = v0 > 0.f ? v0 : 0.f;
                    float v1 = acc[i][j][2*h+1] + b0; v1 = v1 > 0.f ? v1 : 0.f;
                    if (l > 0){
                        u32 xv = *(const u32*)(Xin + rr*NP + col);
                        v0 += __bfloat162float(((bf16*)&xv)[0]);
                        v1 += __bfloat162float(((bf16*)&xv)[1]);
                    }
                    bf16 h0 = __float2bfloat16(v0), h1 = __float2bfloat16(v1);
                    u32 pk = ((u32)*(unsigned short*)&h1 << 16) | (u32)*(unsigned short*)&h0;
                    *(u32*)(Yg + rr*NP + col) = pk;
                    Xt[col*136 + rr]     = h0;
                    Xt[(col+1)*136 + rr] = h1;
                }
            }
        }
    }
}

// ---- fuse GEMM ----
__global__ void __launch_bounds__(256, 2) k_mma_fuse(
    const bf16* __restrict__ W, const float* __restrict__ bias,
    const bf16* __restrict__ Xbase, bf16* __restrict__ Ybase)
{
    extern __shared__ bf16 sm[];
    bf16* Wb[2] = { sm, sm + 128*72 };
    bf16* Bb[2] = { sm + 2*128*72, sm + 3*128*72 };
    int inst = blockIdx.x, mblk = blockIdx.y;
    const bf16* Xg = Xbase + (size_t)inst*(ST_CH*NP);
    bf16* Yg = Ybase + (size_t)inst*(256*NP) + (size_t)mblk*128*NP;
    const bf16* Wm = W + (size_t)mblk*128*KTOT;
    int tid = threadIdx.x, warp = tid >> 5, lane = tid & 31;
    int wm = warp >> 1, wn = warp & 1, qr = lane >> 2, qc = lane & 3;
    int laneRow = lane & 15, laneHi = lane >> 4;
    float acc[2][8][4];
    #pragma unroll
    for (int i = 0; i < 2; i++)
        #pragma unroll
        for (int j = 0; j < 8; j++)
            #pragma unroll
            for (int q = 0; q < 4; q++) acc[i][j][q] = 0.f;
    int ph = tid & 63, cc = tid >> 6;

    {
        #pragma unroll
        for (int q = 0; q < 4; q++){
            int idx = q*256 + tid;
            int row = idx >> 3, seg = idx & 7;
            cpa16(s2u(Wb[0] + row*72 + seg*8), Wm + (size_t)row*KTOT + seg*8);
        }
        CP_COMMIT();
        #pragma unroll
        for (int q = 0; q < 16; q++){
            int c = 4*q + cc;
            u32 v = *(const u32*)(Xg + (size_t)c*NP + ph*2);
            Bb[0][(2*ph)*72 + c]   = ((bf16*)&v)[0];
            Bb[0][(2*ph+1)*72 + c] = ((bf16*)&v)[1];
        }
    }
    u32 aWa[2], bBa[2];
    #pragma unroll
    for (int z = 0; z < 2; z++){
        aWa[z] = s2u(Wb[z]) + (u32)((wm*32 + laneRow)*144 + laneHi*16);
        bBa[z] = s2u(Bb[z]) + (u32)((wn*64 + laneRow)*144 + laneHi*16);
    }
    #pragma unroll 1
    for (int chn = 0; chn < 18; chn++){
        CP_WAIT0();
        __syncthreads();
        u32 vreg[16];
        if (chn < 17){
            int k0 = (chn+1)*64;
            #pragma unroll
            for (int q = 0; q < 16; q++)
                vreg[q] = *(const u32*)(Xg + (size_t)(k0 + 4*q + cc)*NP + ph*2);
            bf16* dstw = Wb[(chn+1) & 1];
            const bf16* srcw = Wm + k0;
            #pragma unroll
            for (int q = 0; q < 4; q++){
                int idx = q*256 + tid;
                int row = idx >> 3, seg = idx & 7;
                cpa16(s2u(dstw + row*72 + seg*8), srcw + (size_t)row*KTOT + seg*8);
            }
            CP_COMMIT();
        }
        u32 aA = aWa[chn & 1];
        u32 bA = bBa[chn & 1];
        #pragma unroll
        for (int cq = 0; cq < 4; cq++){
            if (chn == 1 && cq >= 1) continue;   // k 80..127 exactly zero
            u32 koff = (u32)(cq*32);
            u32 A0[4], A1[4], B0[4], B1[4];
            ldsm_x4(A0, aA + koff);
            ldsm_x4(A1, aA + 16*144 + koff);
            ldsm_x4(B0, bA + koff);
            ldsm_x4(B1, bA + 16*144 + koff);
            {
                u32 b0[2] = { B0[0], B0[2] }, b1[2] = { B0[1], B0[3] };
                u32 b2[2] = { B1[0], B1[2] }, b3[2] = { B1[1], B1[3] };
                mma16816(acc[0][0], A0, b0); mma16816(acc[0][1], A0, b1);
                mma16816(acc[0][2], A0, b2); mma16816(acc[0][3], A0, b3);
                mma16816(acc[1][0], A1, b0); mma16816(acc[1][1], A1, b1);
                mma16816(acc[1][2], A1, b2); mma16816(acc[1][3], A1, b3);
            }
            u32 B2[4], B3[4];
            ldsm_x4(B2, bA + 32*144 + koff);
            ldsm_x4(B3, bA + 48*144 + koff);
            {
                u32 b0[2] = { B2[0], B2[2] }, b1[2] = { B2[1], B2[3] };
                u32 b2[2] = { B3[0], B3[2] }, b3[2] = { B3[1], B3[3] };
                mma16816(acc[0][4], A0, b0); mma16816(acc[0][5], A0, b1);
                mma16816(acc[0][6], A0, b2); mma16816(acc[0][7], A0, b3);
                mma16816(acc[1][4], A1, b0); mma16816(acc[1][5], A1, b1);
                mma16816(acc[1][6], A1, b2); mma16816(acc[1][7], A1, b3);
            }
        }
        if (chn < 17){
            bf16* dstb = Bb[(chn+1) & 1];
            #pragma unroll
            for (int q = 0; q < 16; q++){
                int c = 4*q + cc;
                dstb[(2*ph)*72 + c]   = ((bf16*)&vreg[q])[0];
                dstb[(2*ph+1)*72 + c] = ((bf16*)&vreg[q])[1];
            }
        }
    }
    #pragma unroll
    for (int i = 0; i < 2; i++){
        #pragma unroll
        for (int j = 0; j < 8; j++){
            int row = wm*32 + i*16 + qr;
            int col = wn*64 + j*8 + qc*2;
            #pragma unroll
            for (int h = 0; h < 2; h++){
                int rr = row + h*8;
                float b0 = bias[mblk*128 + rr];
                float v0 = acc[i][j][2*h+0] + b0; v0 = v0 > 0.f ? v0 : 0.f;
                float v1 = acc[i][j][2*h+1] + b0; v1 = v1 > 0.f ? v1 : 0.f;
                Yg[rr*NP + col]     = __float2bfloat16(v0);
                Yg[rr*NP + col + 1] = __float2bfloat16(v1);
            }
        }
    }
}

// ---------------- p1 via HMMA: 256 -> 64, M=64 N=128 K=256 ----------------
// smem: Wb0,Wb1 64*72, Bb0,Bb1 128*72  -> 55296 B
__global__ void __launch_bounds__(256, 2) k_p1m(
    const bf16* __restrict__ W, const float* __restrict__ bias)
{
    extern __shared__ bf16 sm[];
    bf16* Wb[2] = { sm, sm + 64*72 };
    bf16* Bb[2] = { sm + 2*64*72, sm + 2*64*72 + 128*72 };
    int inst = blockIdx.x;
    const bf16* Xg = g_fuse + (size_t)inst*(256*NP);
    float* Yg = g_hbuf + (size_t)inst*(64*NP);
    int tid = threadIdx.x, warp = tid >> 5, lane = tid & 31;
    int wm = warp >> 2, wn = warp & 3, qr = lane >> 2, qc = lane & 3;
    int laneRow = lane & 15, laneHi = lane >> 4;
    float acc[2][4][4];
    #pragma unroll
    for (int i = 0; i < 2; i++)
        #pragma unroll
        for (int j = 0; j < 4; j++)
            #pragma unroll
            for (int q = 0; q < 4; q++) acc[i][j][q] = 0.f;
    int ph = tid & 63, cc = tid >> 6;

    {
        #pragma unroll
        for (int q = 0; q < 2; q++){
            int idx = q*256 + tid;
            int row = idx >> 3, seg = idx & 7;
            cpa16(s2u(Wb[0] + row*72 + seg*8), W + (size_t)row*256 + seg*8);
        }
        CP_COMMIT();
        #pragma unroll
        for (int q = 0; q < 16; q++){
            int c = 4*q + cc;
            u32 v = *(const u32*)(Xg + (size_t)c*NP + ph*2);
            Bb[0][(2*ph)*72 + c]   = ((bf16*)&v)[0];
            Bb[0][(2*ph+1)*72 + c] = ((bf16*)&v)[1];
        }
    }
    u32 aWa[2], bBa[2];
    #pragma unroll
    for (int z = 0; z < 2; z++){
        aWa[z] = s2u(Wb[z]) + (u32)((wm*32 + laneRow)*144 + laneHi*16);
        bBa[z] = s2u(Bb[z]) + (u32)((wn*32 + laneRow)*144 + laneHi*16);
    }
    #pragma unroll 1
    for (int chn = 0; chn < 4; chn++){
        CP_WAIT0();
        __syncthreads();
        u32 vreg[16];
        if (chn < 3){
            int k0 = (chn+1)*64;
            #pragma unroll
            for (int q = 0; q < 16; q++)
                vreg[q] = *(const u32*)(Xg + (size_t)(k0 + 4*q + cc)*NP + ph*2);
            bf16* dstw = Wb[(chn+1) & 1];
            const bf16* srcw = W + k0;
            #pragma unroll
            for (int q = 0; q < 2; q++){
                int idx = q*256 + tid;
                int row = idx >> 3, seg = idx & 7;
                cpa16(s2u(dstw + row*72 + seg*8), srcw + (size_t)row*256 + seg*8);
            }
            CP_COMMIT();
        }
        u32 aA = aWa[chn & 1];
        u32 bA = bBa[chn & 1];
        #pragma unroll
        for (int cq = 0; cq < 4; cq++){
            u32 koff = (u32)(cq*32);
            u32 A0[4], A1[4], B0[4], B1[4];
            ldsm_x4(A0, aA + koff);
            ldsm_x4(A1, aA + 16*144 + koff);
            ldsm_x4(B0, bA + koff);
            ldsm_x4(B1, bA + 16*144 + koff);
            {
                u32 b0[2] = { B0[0], B0[2] }, b1[2] = { B0[1], B0[3] };
                u32 b2[2] = { B1[0], B1[2] }, b3[2] = { B1[1], B1[3] };
                mma16816(acc[0][0], A0, b0); mma16816(acc[0][1], A0, b1);
                mma16816(acc[0][2], A0, b2); mma16816(acc[0][3], A0, b3);
                mma16816(acc[1][0], A1, b0); mma16816(acc[1][1], A1, b1);
                mma16816(acc[1][2], A1, b2); mma16816(acc[1][3], A1, b3);
            }
        }
        if (chn < 3){
            bf16* dstb = Bb[(chn+1) & 1];
            #pragma unroll
            for (int q = 0; q < 16; q++){
                int c = 4*q + cc;
                dstb[(2*ph)*72 + c]   = ((bf16*)&vreg[q])[0];
                dstb[(2*ph+1)*72 + c] = ((bf16*)&vreg[q])[1];
            }
        }
    }
    #pragma unroll
    for (int i = 0; i < 2; i++){
        #pragma unroll
        for (int j = 0; j < 4; j++){
            int row = wm*32 + i*16 + qr;
            int col = wn*32 + j*8 + qc*2;
            #pragma unroll
            for (int h = 0; h < 2; h++){
                int rr = row + h*8;
                float b0 = bias[rr];
                float v0 = acc[i][j][2*h+0] + b0; v0 = v0 > 0.f ? v0 : 0.f;
                float v1 = acc[i][j][2*h+1] + b0; v1 = v1 > 0.f ? v1 : 0.f;
                *(float2*)(Yg + rr*NP + col) = make_float2(v0, v1);
            }
        }
    }
}

// ---------------- p2: 64 -> 2 ----------------
__global__ void k_p2(const float* __restrict__ w, const float* __restrict__ b){
    int inst = blockIdx.x;
    int p = threadIdx.x;
    const float* X = g_hbuf + (size_t)inst*64*NP;
    float a0 = 0.f, a1 = 0.f;
    for (int c = 0; c < 64; c++){
        float xv = X[c*NP + p];
        a0 += w[c]*xv;
        a1 += w[64 + c]*xv;
    }
    g_off[inst*2*NP + p]      = a0 + b[0];
    g_off[inst*2*NP + NP + p] = a1 + b[1];
}

__global__ void k_update(){
    int i = blockIdx.x*blockDim.x + threadIdx.x;
    if (i >= NINST*NP) return;
    int inst = i >> 7, p = i & 127;
    g_pts[i*2+0] += g_off[inst*2*NP + p];
    g_pts[i*2+1] += g_off[inst*2*NP + NP + p];
}

// ---------------- output assembly ----------------
__global__ void k_out(float* __restrict__ out){
    int i = blockIdx.x*blockDim.x + threadIdx.x;
    const int n_det = NINST*6;
    const int n_ct  = NINST*2;
    const int n_pts = NINST*NP*2;
    if (i < n_det){ out[i] = g_det[i]; return; }
    int j = i - n_det;
    if (j < n_ct){ out[i] = g_ct[j]; return; }
    j -= n_ct;
    if (j < n_pts){
        int inst = j / (NP*2);
        out[i] = g_valid[inst] ? g_pts[j] : 0.0f;
        return;
    }
    j -= n_pts;
    if (j < NINST) out[i] = g_valid[j] ? 1.0f : 0.0f;
}

// ---------------- host launcher ----------------
extern "C" void kernel_launch(void* const* d_in, const int* in_sizes, int n_in,
                              void* d_out, int out_size)
{
    const float* pred   = (const float*)d_in[0];
    const float* feat   = (const float*)d_in[1];
    const float* conv_w = (const float*)d_in[2];
    const float* conv_b = (const float*)d_in[3];
    const float* b_head = (const float*)d_in[5];
    const float* b_res  = (const float*)d_in[7];
    const float* b_fuse = (const float*)d_in[9];
    const float* b_p1   = (const float*)d_in[11];
    const float* w_p2   = (const float*)d_in[12];
    const float* b_p2   = (const float*)d_in[13];

    cudaFuncSetAttribute(k_topk, cudaFuncAttributeMaxDynamicSharedMemorySize, 26400*8);
    cudaFuncSetAttribute(k_snake, cudaFuncAttributeMaxDynamicSharedMemorySize, 104448);
    cudaFuncSetAttribute(k_mma_fuse, cudaFuncAttributeMaxDynamicSharedMemorySize, 73728);
    cudaFuncSetAttribute(k_p1m, cudaFuncAttributeMaxDynamicSharedMemorySize, 55296);

    void *pv;
    cudaGetSymbolAddress(&pv, g_states); bf16* p_states = (bf16*)pv;
    cudaGetSymbolAddress(&pv, g_fuse);   bf16* p_fuse = (bf16*)pv;
    cudaGetSymbolAddress(&pv, g_whb);    bf16* p_whb = (bf16*)pv;
    cudaGetSymbolAddress(&pv, g_wrb);    bf16* p_wrb = (bf16*)pv;
    cudaGetSymbolAddress(&pv, g_wfb);    bf16* p_wfb = (bf16*)pv;
    cudaGetSymbolAddress(&pv, g_wp1b);   bf16* p_wp1b = (bf16*)pv;

    cudaStream_t s1;
    cudaStreamCreate(&s1);
    cudaEvent_t e0, e1;
    cudaEventCreateWithFlags(&e0, cudaEventDisableTiming);
    cudaEventCreateWithFlags(&e1, cudaEventDisableTiming);

    cudaEventRecord(e0, 0);
    cudaStreamWaitEvent(s1, e0, 0);
    k_up<<<(int)(((long long)NB*128*160*160 + 255)/256), 256, 0, s1>>>(feat);
    k_conv3<<<dim3(400, NB), 512, 0, s1>>>(conv_w, conv_b);
    cudaEventRecord(e1, s1);

    {
        int n = 128*KTOT + 7*128*KTOT + 256*KTOT + 64*256;
        k_wtrans<<<(n + 255)/256, 256>>>((const float*)d_in[4], (const float*)d_in[6],
                                         (const float*)d_in[8], (const float*)d_in[10]);
    }
    k_scores<<<(NB*NPRED + 255)/256, 256>>>(pred);
    k_topk<<<NB, 1024, 26400*8>>>();
    k_prep<<<(NINST + 255)/256, 256>>>(pred);
    k_nms<<<NB, 256>>>();
    k_initpts<<<(NINST*NP + 255)/256, 256>>>();

    cudaStreamWaitEvent(0, e1, 0);

    for (int it = 0; it < 2; it++){
        k_sample<<<NINST, 128>>>();
        k_snake<<<NINST, 256, 104448>>>(p_whb, p_wrb, b_head, b_res, p_states);
        k_mma_fuse<<<dim3(NINST, 2), 256, 73728>>>(p_wfb, b_fuse, p_states, p_fuse);
        k_p1m<<<NINST, 256, 55296>>>(p_wp1b, b_p1);
        k_p2<<<NINST, 128>>>(w_p2, b_p2);
        k_update<<<(NINST*NP + 255)/256, 256>>>();
    }
    {
        int n = NINST*6 + NINST*2 + NINST*NP*2 + NINST;
        k_out<<<(n + 255)/256, 256>>>((float*)d_out);
    }
}

// round 15
// speedup vs baseline: 1.1001x; 1.0441x over previous
#include <cuda_runtime.h>
#include <cuda_fp16.h>
#include <math.h>

#define NB 16
#define NPRED 25200
#define NCLS 80
#define KDET 300
#define NP 128
#define NINST (NB*KDET)
#define ST_CH 1152
#define KTOT 1152

typedef unsigned long long u64;
typedef unsigned int u32;
typedef __half hlf;

__device__ __forceinline__ void ffma2(u64& acc, u64 a, u64 b){
    asm("fma.rn.f32x2 %0, %1, %2, %3;" : "=l"(acc) : "l"(a), "l"(b), "l"(acc));
}
__device__ __forceinline__ u64 bcast2(float x){
    u64 r;
    asm("mov.b64 %0, {%1, %1};" : "=l"(r) : "r"(__float_as_uint(x)));
    return r;
}
__device__ __forceinline__ float2 unpack2(u64 v){
    float2 f;
    asm("mov.b64 {%0, %1}, %2;" : "=f"(f.x), "=f"(f.y) : "l"(v));
    return f;
}
__device__ __forceinline__ u32 s2u(const void* p){
    u32 a; asm("{ .reg .u64 t; cvta.to.shared.u64 t, %1; cvt.u32.u64 %0, t; }" : "=r"(a) : "l"(p));
    return a;
}
__device__ __forceinline__ void cpa16(u32 dst, const void* src){
    asm volatile("cp.async.cg.shared.global [%0], [%1], 16;" :: "r"(dst), "l"(src));
}
#define CP_COMMIT() asm volatile("cp.async.commit_group;" ::: "memory")
#define CP_WAIT0()  asm volatile("cp.async.wait_group 0;" ::: "memory")

__device__ __forceinline__ void ldsm_x4(u32* r, u32 addr){
    asm volatile("ldmatrix.sync.aligned.m8n8.x4.shared.b16 {%0,%1,%2,%3}, [%4];"
        : "=r"(r[0]), "=r"(r[1]), "=r"(r[2]), "=r"(r[3]) : "r"(addr));
}
// f16 accumulate HMMA: D,C = {2 x u32} (4 halves)
__device__ __forceinline__ void mma16816h(u32* d, const u32* a, const u32* b){
    asm volatile("mma.sync.aligned.m16n8k16.row.col.f16.f16.f16.f16 "
        "{%0,%1}, {%2,%3,%4,%5}, {%6,%7}, {%0,%1};"
        : "+r"(d[0]), "+r"(d[1])
        : "r"(a[0]), "r"(a[1]), "r"(a[2]), "r"(a[3]), "r"(b[0]), "r"(b[1]));
}
__device__ __forceinline__ u32 packh(float v0, float v1){
    hlf h0 = __float2half(v0), h1 = __float2half(v1);
    return ((u32)*(unsigned short*)&h1 << 16) | (u32)*(unsigned short*)&h0;
}

// ---------------- device scratch ----------------
__device__ float g_score[NB*NPRED];
__device__ int   g_cls[NB*NPRED];
__device__ int   g_topidx[NINST];
__device__ float g_tops[NINST];
__device__ float g_boxes[NINST*4];
__device__ float g_det[NINST*6];
__device__ float g_ct[NINST*2];
__device__ float g_half[NINST*2];
__device__ float g_clsf[NINST];
__device__ int   g_valid[NINST];
__device__ float g_up[(size_t)NB*128*160*160];
__device__ hlf   g_cfh[(size_t)NB*160*160*64];
__device__ float g_pts[NINST*NP*2];
__device__ float g_hbuf[(size_t)NINST*64*NP];
__device__ hlf   g_states[(size_t)NINST*ST_CH*NP];
__device__ hlf   g_fuse[(size_t)NINST*256*NP];
__device__ hlf   g_whb[128*KTOT];
__device__ hlf   g_wrb[7*128*KTOT];
__device__ hlf   g_wfb[256*KTOT];
__device__ hlf   g_wp1b[64*256];

// ---------------- weight transposition ----------------
__global__ void k_wtrans(const float* __restrict__ wh, const float* __restrict__ wr,
                         const float* __restrict__ wf, const float* __restrict__ wp1)
{
    int i = blockIdx.x*blockDim.x + threadIdx.x;
    const int n1 = 128*KTOT;
    const int n2 = 7*128*KTOT;
    const int n3 = 256*KTOT;
    const int n4 = 64*256;
    if (i < n1){
        int o = i / KTOT, k = i % KTOT, t = k >> 7, c = k & 127;
        g_whb[i] = __float2half(c < 66 ? wh[(o*66 + c)*9 + t] : 0.f);
        return;
    }
    i -= n1;
    if (i < n2){
        int l = i / (128*KTOT), r = i % (128*KTOT);
        int o = r / KTOT, k = r % KTOT, t = k >> 7, c = k & 127;
        g_wrb[i] = __float2half(wr[(((size_t)l*128 + o)*128 + c)*9 + t]);
        return;
    }
    i -= n2;
    if (i < n3){
        int o = i / KTOT, k = i % KTOT;
        float v = 0.f;
        if (k < 66) v = wf[o*1090 + k];
        else if (k >= 128) v = wf[o*1090 + k - 62];
        g_wfb[i] = __float2half(v);
        return;
    }
    i -= n3;
    if (i < n4){
        g_wp1b[i] = __float2half(wp1[i]);
    }
}

// ---------------- stage 1: scores ----------------
__global__ void k_scores(const float* __restrict__ pred){
    int i = blockIdx.x*blockDim.x + threadIdx.x;
    if (i >= NB*NPRED) return;
    const float* r = pred + (size_t)i*85;
    float obj = r[4];
    float best = -1e30f; int bc = 0;
    for (int c = 0; c < NCLS; c++){
        float s = obj * r[5+c];
        if (s > best){ best = s; bc = c; }
    }
    g_score[i] = (best > 0.2f) ? best : 0.0f;
    g_cls[i] = bc;
}

// ---------------- stage 2: stable top-300 ----------------
__global__ void __launch_bounds__(1024) k_topk(){
    extern __shared__ unsigned long long smk[];
    unsigned long long* keys = smk;
    unsigned long long* l1   = smk + 25600;
    __shared__ unsigned long long red[32];
    int b = blockIdx.x, tid = threadIdx.x;
    for (int i = tid; i < 25600; i += 1024){
        unsigned long long k = 0ULL;
        if (i < NPRED){
            unsigned u = __float_as_uint(g_score[b*NPRED + i]);
            k = ((unsigned long long)u << 32) | (unsigned)(~i);
        }
        keys[i] = k;
    }
    __syncthreads();
    if (tid < 800){
        unsigned long long m = 0ULL;
        for (int j = 0; j < 32; j++){ unsigned long long v = keys[tid*32 + j]; if (v > m) m = v; }
        l1[tid] = m;
    }
    __syncthreads();
    for (int it = 0; it < KDET; it++){
        unsigned long long v = (tid < 800) ? l1[tid] : 0ULL;
        #pragma unroll
        for (int o = 16; o > 0; o >>= 1){
            unsigned long long t2 = __shfl_down_sync(0xffffffffu, v, o);
            if (t2 > v) v = t2;
        }
        if ((tid & 31) == 0) red[tid >> 5] = v;
        __syncthreads();
        if (tid < 32){
            v = red[tid];
            #pragma unroll
            for (int o = 16; o > 0; o >>= 1){
                unsigned long long t2 = __shfl_down_sync(0xffffffffu, v, o);
                if (t2 > v) v = t2;
            }
            if (tid == 0) red[0] = v;
        }
        __syncthreads();
        unsigned long long w = red[0];
        int idx = (int)(~(unsigned)w);
        if (tid < 32){
            int ch = idx >> 5;
            if (tid == 0) keys[idx] = 0ULL;
            __syncwarp();
            unsigned long long kv = keys[ch*32 + tid];
            #pragma unroll
            for (int o = 16; o > 0; o >>= 1){
                unsigned long long t2 = __shfl_down_sync(0xffffffffu, kv, o);
                if (t2 > kv) kv = t2;
            }
            if (tid == 0){
                l1[ch] = kv;
                g_topidx[b*KDET + it] = idx;
                g_tops[b*KDET + it] = __uint_as_float((unsigned)(w >> 32));
            }
        }
        __syncthreads();
    }
}

// ---------------- stage 3 ----------------
__global__ void k_prep(const float* __restrict__ pred){
    int i = blockIdx.x*blockDim.x + threadIdx.x;
    if (i >= NINST) return;
    int b = i / KDET;
    int src = g_topidx[i];
    const float* r = pred + ((size_t)b*NPRED + src)*85;
    float cx = r[0], cy = r[1], w = r[2], h = r[3];
    float hw = w*0.5f, hh = h*0.5f;
    float x1 = cx - hw, y1 = cy - hh, x2 = cx + hw, y2 = cy + hh;
    g_boxes[4*i+0] = x1; g_boxes[4*i+1] = y1; g_boxes[4*i+2] = x2; g_boxes[4*i+3] = y2;
    float cf = (float)g_cls[b*NPRED + src];
    g_clsf[i] = cf;
    float sc = g_tops[i];
    g_det[6*i+0] = x1; g_det[6*i+1] = y1; g_det[6*i+2] = x2; g_det[6*i+3] = y2;
    g_det[6*i+4] = sc; g_det[6*i+5] = cf;
    float b0 = x1*0.25f, b1 = y1*0.25f, b2 = x2*0.25f, b3 = y2*0.25f;
    g_ct[2*i+0] = (b0 + b2)*0.5f;
    g_ct[2*i+1] = (b1 + b3)*0.5f;
    g_half[2*i+0] = fmaxf((b2 - b0)*0.5f, 1e-3f);
    g_half[2*i+1] = fmaxf((b3 - b1)*0.5f, 1e-3f);
}

// ---------------- stage 4: NMS ----------------
__global__ void k_nms(){
    __shared__ float bx[KDET][4];
    __shared__ float ar[KDET];
    __shared__ float sc[KDET];
    __shared__ int keep[KDET];
    int b = blockIdx.x, tid = threadIdx.x;
    for (int i = tid; i < KDET; i += 256){
        int g = b*KDET + i;
        float off = g_clsf[g]*4096.0f;
        float x1 = g_boxes[4*g+0] + off, y1 = g_boxes[4*g+1] + off;
        float x2 = g_boxes[4*g+2] + off, y2 = g_boxes[4*g+3] + off;
        bx[i][0] = x1; bx[i][1] = y1; bx[i][2] = x2; bx[i][3] = y2;
        ar[i] = (x2 - x1)*(y2 - y1);
        sc[i] = g_tops[g];
        keep[i] = 1;
    }
    __syncthreads();
    for (int i = 0; i < KDET; i++){
        if (keep[i]){
            float ax1 = bx[i][0], ay1 = bx[i][1], ax2 = bx[i][2], ay2 = bx[i][3], aa = ar[i];
            for (int j = i + 1 + tid; j < KDET; j += 256){
                float iw = fminf(ax2, bx[j][2]) - fmaxf(ax1, bx[j][0]);
                float ih = fminf(ay2, bx[j][3]) - fmaxf(ay1, bx[j][1]);
                iw = fmaxf(iw, 0.f); ih = fmaxf(ih, 0.f);
                float inter = iw*ih;
                float iou = inter / (aa + ar[j] - inter + 1e-9f);
                if (iou > 0.3f) keep[j] = 0;
            }
        }
        __syncthreads();
    }
    for (int i = tid; i < KDET; i += 256)
        g_valid[b*KDET + i] = (keep[i] && (sc[i] > 0.2f)) ? 1 : 0;
}

// ---------------- stage 5: upsample ----------------
__global__ void k_up(const float* __restrict__ feat){
    long long idx = (long long)blockIdx.x*256 + threadIdx.x;
    if (idx >= (long long)NB*128*160*160) return;
    int ox = (int)(idx % 160); long long r = idx/160;
    int oy = (int)(r % 160); r /= 160;
    int c = (int)(r % 128); int b = (int)(r/128);
    int iy = oy >> 1, ix = ox >> 1;
    int ya, yb; float wya, wyb;
    if (oy & 1){ ya = iy; yb = iy+1; wya = 0.75f; wyb = 0.25f; }
    else       { ya = iy-1; yb = iy; wya = 0.25f; wyb = 0.75f; }
    int xa, xb; float wxa, wxb;
    if (ox & 1){ xa = ix; xb = ix+1; wxa = 0.75f; wxb = 0.25f; }
    else       { xa = ix-1; xb = ix; wxa = 0.25f; wxb = 0.75f; }
    ya = max(0, min(79, ya)); yb = max(0, min(79, yb));
    xa = max(0, min(79, xa)); xb = max(0, min(79, xb));
    const float* f = feat + ((size_t)b*128 + c)*6400;
    float v = wya*(wxa*f[ya*80+xa] + wxb*f[ya*80+xb])
            + wyb*(wxa*f[yb*80+xa] + wxb*f[yb*80+xb]);
    g_up[idx] = v;
}

// ---------------- stage 6: 3x3 conv + SiLU (FFMA2) -> channel-last f16 ----------------
__global__ void __launch_bounds__(512) k_conv3(const float* __restrict__ Wc, const float* __restrict__ Bc){
    __shared__ float Xs[16][10][10];
    __shared__ float Wsp[16][9][64];
    int b = blockIdx.y;
    int tile = blockIdx.x;
    int ty0 = (tile/20)*8, tx0 = (tile%20)*8;
    int tid = threadIdx.x;
    int px = tid & 7, py = (tid >> 3) & 7, og = tid >> 6;
    u64 acc2[4] = {0ULL, 0ULL, 0ULL, 0ULL};
    for (int c0 = 0; c0 < 128; c0 += 16){
        __syncthreads();
        for (int i = tid; i < 1600; i += 512){
            int c = i/100, r = i%100, yy = r/10, xx = r%10;
            int gy = ty0 - 1 + yy, gx = tx0 - 1 + xx;
            float v = 0.f;
            if (gy >= 0 && gy < 160 && gx >= 0 && gx < 160)
                v = g_up[(((size_t)b*128 + c0 + c)*160 + gy)*160 + gx];
            Xs[c][yy][xx] = v;
        }
        for (int i = tid; i < 9216; i += 512){
            int o = i & 63, r = i >> 6, c = r/9, t = r%9;
            Wsp[c][t][o] = Wc[(o*128 + c0 + c)*9 + t];
        }
        __syncthreads();
        for (int c = 0; c < 16; c++){
            #pragma unroll
            for (int t = 0; t < 9; t++){
                u64 xv = bcast2(Xs[c][py + t/3][px + t%3]);
                const u64* wr = (const u64*)(&Wsp[c][t][og*8]);
                #pragma unroll
                for (int i = 0; i < 4; i++) ffma2(acc2[i], wr[i], xv);
            }
        }
    }
    int oy = ty0 + py, ox = tx0 + px;
    hlf hv[8];
    #pragma unroll
    for (int i = 0; i < 4; i++){
        float2 v2 = unpack2(acc2[i]);
        int o0 = og*8 + 2*i;
        float v0 = v2.x + Bc[o0];
        float v1 = v2.y + Bc[o0+1];
        v0 = v0 / (1.f + expf(-v0));
        v1 = v1 / (1.f + expf(-v1));
        hv[2*i]   = __float2half(v0);
        hv[2*i+1] = __float2half(v1);
    }
    *(uint4*)(g_cfh + (((size_t)b*160 + oy)*160 + ox)*64 + og*8) = *(uint4*)hv;
}

// ---------------- stage 7/8 ----------------
__global__ void k_initpts(){
    int i = blockIdx.x*blockDim.x + threadIdx.x;
    if (i >= NINST*NP) return;
    int inst = i >> 7, p = i & 127;
    float th = (float)p * 0.049087385212340517f;
    g_pts[i*2+0] = g_ct[inst*2+0] + g_half[inst*2+0]*cosf(th);
    g_pts[i*2+1] = g_ct[inst*2+1] + g_half[inst*2+1]*sinf(th);
}

__global__ void k_sample(){
    int inst = blockIdx.x;
    int p = threadIdx.x;
    int b = inst / KDET;
    float px = g_pts[(inst*NP + p)*2 + 0], py = g_pts[(inst*NP + p)*2 + 1];
    float x = fminf(fmaxf(px, 0.f), 159.f);
    float y = fminf(fmaxf(py, 0.f), 159.f);
    float x0f = fminf(fmaxf(floorf(x), 0.f), 158.f);
    float y0f = fminf(fmaxf(floorf(y), 0.f), 158.f);
    int x0 = (int)x0f, y0 = (int)y0f;
    float dx = x - x0f, dy = y - y0f;
    float w00 = (1.f-dx)*(1.f-dy), w10 = dx*(1.f-dy), w01 = (1.f-dx)*dy, w11 = dx*dy;
    const hlf* f = g_cfh + (size_t)b*25600*64;
    size_t base = (size_t)(y0*160 + x0)*64;
    const uint4* c00 = (const uint4*)(f + base);
    const uint4* c01 = (const uint4*)(f + base + 64);
    const uint4* c10 = (const uint4*)(f + base + 160*64);
    const uint4* c11 = (const uint4*)(f + base + 160*64 + 64);
    hlf* Z = g_states + (size_t)inst*ST_CH*NP;
    #pragma unroll
    for (int q = 0; q < 8; q++){
        uint4 a = c00[q], bq = c01[q], cq = c10[q], dq = c11[q];
        const __half2* ah = (const __half2*)&a;
        const __half2* bh = (const __half2*)&bq;
        const __half2* ch = (const __half2*)&cq;
        const __half2* dh = (const __half2*)&dq;
        #pragma unroll
        for (int j = 0; j < 4; j++){
            float2 fa = __half22float2(ah[j]);
            float2 fb = __half22float2(bh[j]);
            float2 fc = __half22float2(ch[j]);
            float2 fd = __half22float2(dh[j]);
            float v0 = fa.x*w00 + fb.x*w10 + fc.x*w01 + fd.x*w11;
            float v1 = fa.y*w00 + fb.y*w10 + fc.y*w01 + fd.y*w11;
            int c = q*8 + j*2;
            Z[c*NP + p]     = __float2half(v0);
            Z[(c+1)*NP + p] = __float2half(v1);
        }
    }
    float cx = g_ct[inst*2+0], cy = g_ct[inst*2+1];
    float hx = g_half[inst*2+0], hy = g_half[inst*2+1];
    Z[64*NP + p] = __float2half((px - cx)/hx);
    Z[65*NP + p] = __float2half((py - cy)/hy);
    hlf z0 = __float2half(0.f);
    for (int c = 66; c < 128; c++) Z[c*NP + p] = z0;
}

// ---- fused snake stack (f16 accumulate) ----
__global__ void __launch_bounds__(256, 2) k_snake(
    const hlf* __restrict__ Wh, const hlf* __restrict__ Wr,
    const float* __restrict__ bh, const float* __restrict__ br,
    hlf* __restrict__ Sbase)
{
    extern __shared__ hlf sm[];
    hlf* Xt  = sm;
    hlf* Wb0 = sm + 128*136;
    hlf* Wb1 = Wb0 + 128*136;
    int inst = blockIdx.x;
    hlf* Sg = Sbase + (size_t)inst*(ST_CH*NP);
    int tid = threadIdx.x, warp = tid >> 5, lane = tid & 31;
    int wm = warp >> 1, wn = warp & 1, qr = lane >> 2, qc = lane & 3;
    int laneRow = lane & 15, laneHi = lane >> 4;

    #pragma unroll
    for (int q = 0; q < 8; q++){
        int idx = q*256 + tid;
        int row = idx >> 4, seg = idx & 15;
        cpa16(s2u(Wb0 + row*136 + seg*8), Wh + (size_t)row*KTOT + seg*8);
    }
    CP_COMMIT();
    {
        int ph = tid & 63, cc = tid >> 6;
        #pragma unroll
        for (int cb = 0; cb < 128; cb += 4){
            int c = cb + cc;
            u32 v = *(const u32*)(Sg + c*NP + ph*2);
            Xt[(2*ph)*136 + c]   = ((hlf*)&v)[0];
            Xt[(2*ph+1)*136 + c] = ((hlf*)&v)[1];
        }
    }
    u32 xtb = s2u(Xt);
    u32 aW0 = s2u(Wb0) + (u32)((wm*32 + laneRow)*272 + laneHi*16);
    u32 aW1 = s2u(Wb1) + (u32)((wm*32 + laneRow)*272 + laneHi*16);
    const int DILS[8] = {1,1,1,1,2,2,4,4};

    #pragma unroll 1
    for (int l = 0; l < 8; l++){
        int dil = DILS[l];
        int offs[9];
        #pragma unroll
        for (int t = 0; t < 9; t++) offs[t] = (dil*(t-4) + 128) & 127;
        u32 acc[2][8][2];
        #pragma unroll
        for (int i = 0; i < 2; i++)
            #pragma unroll
            for (int j = 0; j < 8; j++){ acc[i][j][0] = 0u; acc[i][j][1] = 0u; }

        #pragma unroll 1
        for (int t = 0; t < 9; t++){
            CP_WAIT0();
            __syncthreads();
            int g = l*9 + t;
            if (g < 71){
                int gn = g + 1, ln = gn/9, tn = gn - ln*9;
                const hlf* src = (ln ? (Wr + (size_t)(ln-1)*128*KTOT) : Wh) + tn*128;
                hlf* dstb = (gn & 1) ? Wb1 : Wb0;
                #pragma unroll
                for (int q = 0; q < 8; q++){
                    int idx = q*256 + tid;
                    int row = idx >> 4, seg = idx & 15;
                    cpa16(s2u(dstb + row*136 + seg*8), src + (size_t)row*KTOT + seg*8);
                }
                CP_COMMIT();
            }
            u32 aA = (g & 1) ? aW1 : aW0;
            u32 bAddr[4];
            #pragma unroll
            for (int jj = 0; jj < 4; jj++){
                int row = (wn*64 + jj*16 + laneRow + offs[t]) & 127;
                bAddr[jj] = xtb + (u32)(row*272 + laneHi*16);
            }
            #pragma unroll
            for (int cq2 = 0; cq2 < 8; cq2++){
                if (l == 0 && cq2 >= 5) continue;
                u32 koff = (u32)(cq2*32);
                u32 A0[4], A1[4], B[4][4];
                ldsm_x4(A0, aA + koff);
                ldsm_x4(A1, aA + 16*272 + koff);
                #pragma unroll
                for (int jj = 0; jj < 4; jj++) ldsm_x4(B[jj], bAddr[jj] + koff);
                #pragma unroll
                for (int jj = 0; jj < 4; jj++){
                    u32 b0[2] = { B[jj][0], B[jj][2] };
                    u32 b1[2] = { B[jj][1], B[jj][3] };
                    mma16816h(acc[0][2*jj],   A0, b0);
                    mma16816h(acc[0][2*jj+1], A0, b1);
                    mma16816h(acc[1][2*jj],   A1, b0);
                    mma16816h(acc[1][2*jj+1], A1, b1);
                }
            }
        }
        __syncthreads();
        const float* bl = l ? (br + (l-1)*128) : bh;
        const hlf* Xin = Sg + (size_t)(128*l)*NP;
        hlf* Yg = Sg + (size_t)(128*(l+1))*NP;
        #pragma unroll
        for (int i = 0; i < 2; i++){
            #pragma unroll
            for (int j = 0; j < 8; j++){
                int row = wm*32 + i*16 + qr;
                int col = wn*64 + j*8 + qc*2;
                #pragma unroll
                for (int h = 0; h < 2; h++){
                    int rr = row + h*8;
                    float b0 = bl[rr];
                    float2 av = __half22float2(*(__half2*)&acc[i][j][h]);
                    float v0 = av.x + b0; v0 = v0 > 0.f ? v0 : 0.f;
                    float v1 = av.y + b0; v1 = v1 > 0.f ? v1 : 0.f;
                    if (l > 0){
                        u32 xv = *(const u32*)(Xin + rr*NP + col);
                        float2 xf = __half22float2(*(__half2*)&xv);
                        v0 += xf.x; v1 += xf.y;
                    }
                    u32 pk = packh(v0, v1);
                    *(u32*)(Yg + rr*NP + col) = pk;
                    Xt[col*136 + rr]     = ((hlf*)&pk)[0];
                    Xt[(col+1)*136 + rr] = ((hlf*)&pk)[1];
                }
            }
        }
    }
}

// ---- fuse GEMM (f16 accumulate) ----
__global__ void __launch_bounds__(256, 2) k_mma_fuse(
    const hlf* __restrict__ W, const float* __restrict__ bias,
    const hlf* __restrict__ Xbase, hlf* __restrict__ Ybase)
{
    extern __shared__ hlf sm[];
    hlf* Wb[2] = { sm, sm + 128*72 };
    hlf* Bb[2] = { sm + 2*128*72, sm + 3*128*72 };
    int inst = blockIdx.x, mblk = blockIdx.y;
    const hlf* Xg = Xbase + (size_t)inst*(ST_CH*NP);
    hlf* Yg = Ybase + (size_t)inst*(256*NP) + (size_t)mblk*128*NP;
    const hlf* Wm = W + (size_t)mblk*128*KTOT;
    int tid = threadIdx.x, warp = tid >> 5, lane = tid & 31;
    int wm = warp >> 1, wn = warp & 1, qr = lane >> 2, qc = lane & 3;
    int laneRow = lane & 15, laneHi = lane >> 4;
    u32 acc[2][8][2];
    #pragma unroll
    for (int i = 0; i < 2; i++)
        #pragma unroll
        for (int j = 0; j < 8; j++){ acc[i][j][0] = 0u; acc[i][j][1] = 0u; }
    int ph = tid & 63, cc = tid >> 6;

    {
        #pragma unroll
        for (int q = 0; q < 4; q++){
            int idx = q*256 + tid;
            int row = idx >> 3, seg = idx & 7;
            cpa16(s2u(Wb[0] + row*72 + seg*8), Wm + (size_t)row*KTOT + seg*8);
        }
        CP_COMMIT();
        #pragma unroll
        for (int q = 0; q < 16; q++){
            int c = 4*q + cc;
            u32 v = *(const u32*)(Xg + (size_t)c*NP + ph*2);
            Bb[0][(2*ph)*72 + c]   = ((hlf*)&v)[0];
            Bb[0][(2*ph+1)*72 + c] = ((hlf*)&v)[1];
        }
    }
    u32 aWa[2], bBa[2];
    #pragma unroll
    for (int z = 0; z < 2; z++){
        aWa[z] = s2u(Wb[z]) + (u32)((wm*32 + laneRow)*144 + laneHi*16);
        bBa[z] = s2u(Bb[z]) + (u32)((wn*64 + laneRow)*144 + laneHi*16);
    }
    #pragma unroll 1
    for (int chn = 0; chn < 18; chn++){
        CP_WAIT0();
        __syncthreads();
        u32 vreg[16];
        if (chn < 17){
            int k0 = (chn+1)*64;
            #pragma unroll
            for (int q = 0; q < 16; q++)
                vreg[q] = *(const u32*)(Xg + (size_t)(k0 + 4*q + cc)*NP + ph*2);
            hlf* dstw = Wb[(chn+1) & 1];
            const hlf* srcw = Wm + k0;
            #pragma unroll
            for (int q = 0; q < 4; q++){
                int idx = q*256 + tid;
                int row = idx >> 3, seg = idx & 7;
                cpa16(s2u(dstw + row*72 + seg*8), srcw + (size_t)row*KTOT + seg*8);
            }
            CP_COMMIT();
        }
        u32 aA = aWa[chn & 1];
        u32 bA = bBa[chn & 1];
        #pragma unroll
        for (int cq = 0; cq < 4; cq++){
            if (chn == 1 && cq >= 1) continue;
            u32 koff = (u32)(cq*32);
            u32 A0[4], A1[4], B0[4], B1[4];
            ldsm_x4(A0, aA + koff);
            ldsm_x4(A1, aA + 16*144 + koff);
            ldsm_x4(B0, bA + koff);
            ldsm_x4(B1, bA + 16*144 + koff);
            {
                u32 b0[2] = { B0[0], B0[2] }, b1[2] = { B0[1], B0[3] };
                u32 b2[2] = { B1[0], B1[2] }, b3[2] = { B1[1], B1[3] };
                mma16816h(acc[0][0], A0, b0); mma16816h(acc[0][1], A0, b1);
                mma16816h(acc[0][2], A0, b2); mma16816h(acc[0][3], A0, b3);
                mma16816h(acc[1][0], A1, b0); mma16816h(acc[1][1], A1, b1);
                mma16816h(acc[1][2], A1, b2); mma16816h(acc[1][3], A1, b3);
            }
            u32 B2[4], B3[4];
            ldsm_x4(B2, bA + 32*144 + koff);
            ldsm_x4(B3, bA + 48*144 + koff);
            {
                u32 b0[2] = { B2[0], B2[2] }, b1[2] = { B2[1], B2[3] };
                u32 b2[2] = { B3[0], B3[2] }, b3[2] = { B3[1], B3[3] };
                mma16816h(acc[0][4], A0, b0); mma16816h(acc[0][5], A0, b1);
                mma16816h(acc[0][6], A0, b2); mma16816h(acc[0][7], A0, b3);
                mma16816h(acc[1][4], A1, b0); mma16816h(acc[1][5], A1, b1);
                mma16816h(acc[1][6], A1, b2); mma16816h(acc[1][7], A1, b3);
            }
        }
        if (chn < 17){
            hlf* dstb = Bb[(chn+1) & 1];
            #pragma unroll
            for (int q = 0; q < 16; q++){
                int c = 4*q + cc;
                dstb[(2*ph)*72 + c]   = ((hlf*)&vreg[q])[0];
                dstb[(2*ph+1)*72 + c] = ((hlf*)&vreg[q])[1];
            }
        }
    }
    #pragma unroll
    for (int i = 0; i < 2; i++){
        #pragma unroll
        for (int j = 0; j < 8; j++){
            int row = wm*32 + i*16 + qr;
            int col = wn*64 + j*8 + qc*2;
            #pragma unroll
            for (int h = 0; h < 2; h++){
                int rr = row + h*8;
                float b0 = bias[mblk*128 + rr];
                float2 av = __half22float2(*(__half2*)&acc[i][j][h]);
                float v0 = av.x + b0; v0 = v0 > 0.f ? v0 : 0.f;
                float v1 = av.y + b0; v1 = v1 > 0.f ? v1 : 0.f;
                *(u32*)(Yg + rr*NP + col) = packh(v0, v1);
            }
        }
    }
}

// ---------------- p1 via HMMA (f16 accumulate): 256 -> 64 ----------------
__global__ void __launch_bounds__(256, 2) k_p1m(
    const hlf* __restrict__ W, const float* __restrict__ bias)
{
    extern __shared__ hlf sm[];
    hlf* Wb[2] = { sm, sm + 64*72 };
    hlf* Bb[2] = { sm + 2*64*72, sm + 2*64*72 + 128*72 };
    int inst = blockIdx.x;
    const hlf* Xg = g_fuse + (size_t)inst*(256*NP);
    float* Yg = g_hbuf + (size_t)inst*(64*NP);
    int tid = threadIdx.x, warp = tid >> 5, lane = tid & 31;
    int wm = warp >> 2, wn = warp & 3, qr = lane >> 2, qc = lane & 3;
    int laneRow = lane & 15, laneHi = lane >> 4;
    u32 acc[2][4][2];
    #pragma unroll
    for (int i = 0; i < 2; i++)
        #pragma unroll
        for (int j = 0; j < 4; j++){ acc[i][j][0] = 0u; acc[i][j][1] = 0u; }
    int ph = tid & 63, cc = tid >> 6;

    {
        #pragma unroll
        for (int q = 0; q < 2; q++){
            int idx = q*256 + tid;
            int row = idx >> 3, seg = idx & 7;
            cpa16(s2u(Wb[0] + row*72 + seg*8), W + (size_t)row*256 + seg*8);
        }
        CP_COMMIT();
        #pragma unroll
        for (int q = 0; q < 16; q++){
            int c = 4*q + cc;
            u32 v = *(const u32*)(Xg + (size_t)c*NP + ph*2);
            Bb[0][(2*ph)*72 + c]   = ((hlf*)&v)[0];
            Bb[0][(2*ph+1)*72 + c] = ((hlf*)&v)[1];
        }
    }
    u32 aWa[2], bBa[2];
    #pragma unroll
    for (int z = 0; z < 2; z++){
        aWa[z] = s2u(Wb[z]) + (u32)((wm*32 + laneRow)*144 + laneHi*16);
        bBa[z] = s2u(Bb[z]) + (u32)((wn*32 + laneRow)*144 + laneHi*16);
    }
    #pragma unroll 1
    for (int chn = 0; chn < 4; chn++){
        CP_WAIT0();
        __syncthreads();
        u32 vreg[16];
        if (chn < 3){
            int k0 = (chn+1)*64;
            #pragma unroll
            for (int q = 0; q < 16; q++)
                vreg[q] = *(const u32*)(Xg + (size_t)(k0 + 4*q + cc)*NP + ph*2);
            hlf* dstw = Wb[(chn+1) & 1];
            const hlf* srcw = W + k0;
            #pragma unroll
            for (int q = 0; q < 2; q++){
                int idx = q*256 + tid;
                int row = idx >> 3, seg = idx & 7;
                cpa16(s2u(dstw + row*72 + seg*8), srcw + (size_t)row*256 + seg*8);
            }
            CP_COMMIT();
        }
        u32 aA = aWa[chn & 1];
        u32 bA = bBa[chn & 1];
        #pragma unroll
        for (int cq = 0; cq < 4; cq++){
            u32 koff = (u32)(cq*32);
            u32 A0[4], A1[4], B0[4], B1[4];
            ldsm_x4(A0, aA + koff);
            ldsm_x4(A1, aA + 16*144 + koff);
            ldsm_x4(B0, bA + koff);
            ldsm_x4(B1, bA + 16*144 + koff);
            {
                u32 b0[2] = { B0[0], B0[2] }, b1[2] = { B0[1], B0[3] };
                u32 b2[2] = { B1[0], B1[2] }, b3[2] = { B1[1], B1[3] };
                mma16816h(acc[0][0], A0, b0); mma16816h(acc[0][1], A0, b1);
                mma16816h(acc[0][2], A0, b2); mma16816h(acc[0][3], A0, b3);
                mma16816h(acc[1][0], A1, b0); mma16816h(acc[1][1], A1, b1);
                mma16816h(acc[1][2], A1, b2); mma16816h(acc[1][3], A1, b3);
            }
        }
        if (chn < 3){
            hlf* dstb = Bb[(chn+1) & 1];
            #pragma unroll
            for (int q = 0; q < 16; q++){
                int c = 4*q + cc;
                dstb[(2*ph)*72 + c]   = ((hlf*)&vreg[q])[0];
                dstb[(2*ph+1)*72 + c] = ((hlf*)&vreg[q])[1];
            }
        }
    }
    #pragma unroll
    for (int i = 0; i < 2; i++){
        #pragma unroll
        for (int j = 0; j < 4; j++){
            int row = wm*32 + i*16 + qr;
            int col = wn*32 + j*8 + qc*2;
            #pragma unroll
            for (int h = 0; h < 2; h++){
                int rr = row + h*8;
                float b0 = bias[rr];
                float2 av = __half22float2(*(__half2*)&acc[i][j][h]);
                float v0 = av.x + b0; v0 = v0 > 0.f ? v0 : 0.f;
                float v1 = av.y + b0; v1 = v1 > 0.f ? v1 : 0.f;
                *(float2*)(Yg + rr*NP + col) = make_float2(v0, v1);
            }
        }
    }
}

// ---------------- p2 (fused update): 64 -> 2, pts += off ----------------
__global__ void k_p2(const float* __restrict__ w, const float* __restrict__ b){
    int inst = blockIdx.x;
    int p = threadIdx.x;
    const float* X = g_hbuf + (size_t)inst*64*NP;
    float a0 = 0.f, a1 = 0.f;
    for (int c = 0; c < 64; c++){
        float xv = X[c*NP + p];
        a0 += w[c]*xv;
        a1 += w[64 + c]*xv;
    }
    g_pts[(inst*NP + p)*2 + 0] += a0 + b[0];
    g_pts[(inst*NP + p)*2 + 1] += a1 + b[1];
}

// ---------------- output assembly ----------------
__global__ void k_out(float* __restrict__ out){
    int i = blockIdx.x*blockDim.x + threadIdx.x;
    const int n_det = NINST*6;
    const int n_ct  = NINST*2;
    const int n_pts = NINST*NP*2;
    if (i < n_det){ out[i] = g_det[i]; return; }
    int j = i - n_det;
    if (j < n_ct){ out[i] = g_ct[j]; return; }
    j -= n_ct;
    if (j < n_pts){
        int inst = j / (NP*2);
        out[i] = g_valid[inst] ? g_pts[j] : 0.0f;
        return;
    }
    j -= n_pts;
    if (j < NINST) out[i] = g_valid[j] ? 1.0f : 0.0f;
}

// ---------------- host launcher ----------------
extern "C" void kernel_launch(void* const* d_in, const int* in_sizes, int n_in,
                              void* d_out, int out_size)
{
    const float* pred   = (const float*)d_in[0];
    const float* feat   = (const float*)d_in[1];
    const float* conv_w = (const float*)d_in[2];
    const float* conv_b = (const float*)d_in[3];
    const float* b_head = (const float*)d_in[5];
    const float* b_res  = (const float*)d_in[7];
    const float* b_fuse = (const float*)d_in[9];
    const float* b_p1   = (const float*)d_in[11];
    const float* w_p2   = (const float*)d_in[12];
    const float* b_p2   = (const float*)d_in[13];

    cudaFuncSetAttribute(k_topk, cudaFuncAttributeMaxDynamicSharedMemorySize, 26400*8);
    cudaFuncSetAttribute(k_snake, cudaFuncAttributeMaxDynamicSharedMemorySize, 104448);
    cudaFuncSetAttribute(k_mma_fuse, cudaFuncAttributeMaxDynamicSharedMemorySize, 73728);
    cudaFuncSetAttribute(k_p1m, cudaFuncAttributeMaxDynamicSharedMemorySize, 55296);

    void *pv;
    cudaGetSymbolAddress(&pv, g_states); hlf* p_states = (hlf*)pv;
    cudaGetSymbolAddress(&pv, g_fuse);   hlf* p_fuse = (hlf*)pv;
    cudaGetSymbolAddress(&pv, g_whb);    hlf* p_whb = (hlf*)pv;
    cudaGetSymbolAddress(&pv, g_wrb);    hlf* p_wrb = (hlf*)pv;
    cudaGetSymbolAddress(&pv, g_wfb);    hlf* p_wfb = (hlf*)pv;
    cudaGetSymbolAddress(&pv, g_wp1b);   hlf* p_wp1b = (hlf*)pv;

    cudaStream_t s1;
    cudaStreamCreate(&s1);
    cudaEvent_t e0, e1;
    cudaEventCreateWithFlags(&e0, cudaEventDisableTiming);
    cudaEventCreateWithFlags(&e1, cudaEventDisableTiming);

    cudaEventRecord(e0, 0);
    cudaStreamWaitEvent(s1, e0, 0);
    k_up<<<(int)(((long long)NB*128*160*160 + 255)/256), 256, 0, s1>>>(feat);
    k_conv3<<<dim3(400, NB), 512, 0, s1>>>(conv_w, conv_b);
    cudaEventRecord(e1, s1);

    {
        int n = 128*KTOT + 7*128*KTOT + 256*KTOT + 64*256;
        k_wtrans<<<(n + 255)/256, 256>>>((const float*)d_in[4], (const float*)d_in[6],
                                         (const float*)d_in[8], (const float*)d_in[10]);
    }
    k_scores<<<(NB*NPRED + 255)/256, 256>>>(pred);
    k_topk<<<NB, 1024, 26400*8>>>();
    k_prep<<<(NINST + 255)/256, 256>>>(pred);
    k_nms<<<NB, 256>>>();
    k_initpts<<<(NINST*NP + 255)/256, 256>>>();

    cudaStreamWaitEvent(0, e1, 0);

    for (int it = 0; it < 2; it++){
        k_sample<<<NINST, 128>>>();
        k_snake<<<NINST, 256, 104448>>>(p_whb, p_wrb, b_head, b_res, p_states);
        k_mma_fuse<<<dim3(NINST, 2), 256, 73728>>>(p_wfb, b_fuse, p_states, p_fuse);
        k_p1m<<<NINST, 256, 55296>>>(p_wp1b, b_p1);
        k_p2<<<NINST, 128>>>(w_p2, b_p2);
    }
    {
        int n = NINST*6 + NINST*2 + NINST*NP*2 + NINST;
        k_out<<<(n + 255)/256, 256>>>((float*)d_out);
    }
}

// round 16
// speedup vs baseline: 1.1455x; 1.0413x over previous
#include <cuda_runtime.h>
#include <cuda_fp16.h>
#include <math.h>

#define NB 16
#define NPRED 25200
#define NCLS 80
#define KDET 300
#define NP 128
#define NINST (NB*KDET)
#define ST_CH 1152
#define KTOT 1152

typedef unsigned long long u64;
typedef unsigned int u32;
typedef __half hlf;

__device__ __forceinline__ void ffma2(u64& acc, u64 a, u64 b){
    asm("fma.rn.f32x2 %0, %1, %2, %3;" : "=l"(acc) : "l"(a), "l"(b), "l"(acc));
}
__device__ __forceinline__ u64 bcast2(float x){
    u64 r;
    asm("mov.b64 %0, {%1, %1};" : "=l"(r) : "r"(__float_as_uint(x)));
    return r;
}
__device__ __forceinline__ float2 unpack2(u64 v){
    float2 f;
    asm("mov.b64 {%0, %1}, %2;" : "=f"(f.x), "=f"(f.y) : "l"(v));
    return f;
}
__device__ __forceinline__ u32 s2u(const void* p){
    u32 a; asm("{ .reg .u64 t; cvta.to.shared.u64 t, %1; cvt.u32.u64 %0, t; }" : "=r"(a) : "l"(p));
    return a;
}
__device__ __forceinline__ void cpa16(u32 dst, const void* src){
    asm volatile("cp.async.cg.shared.global [%0], [%1], 16;" :: "r"(dst), "l"(src));
}
#define CP_COMMIT() asm volatile("cp.async.commit_group;" ::: "memory")
#define CP_WAIT0()  asm volatile("cp.async.wait_group 0;" ::: "memory")

__device__ __forceinline__ void ldsm_x4(u32* r, u32 addr){
    asm volatile("ldmatrix.sync.aligned.m8n8.x4.shared.b16 {%0,%1,%2,%3}, [%4];"
        : "=r"(r[0]), "=r"(r[1]), "=r"(r[2]), "=r"(r[3]) : "r"(addr));
}
__device__ __forceinline__ void mma16816h(u32* d, const u32* a, const u32* b){
    asm volatile("mma.sync.aligned.m16n8k16.row.col.f16.f16.f16.f16 "
        "{%0,%1}, {%2,%3,%4,%5}, {%6,%7}, {%0,%1};"
        : "+r"(d[0]), "+r"(d[1])
        : "r"(a[0]), "r"(a[1]), "r"(a[2]), "r"(a[3]), "r"(b[0]), "r"(b[1]));
}
__device__ __forceinline__ u32 packh(float v0, float v1){
    hlf h0 = __float2half(v0), h1 = __float2half(v1);
    return ((u32)*(unsigned short*)&h1 << 16) | (u32)*(unsigned short*)&h0;
}

// ---------------- device scratch ----------------
__device__ float g_score[NB*NPRED];
__device__ int   g_cls[NB*NPRED];
__device__ int   g_topidx[NINST];
__device__ float g_tops[NINST];
__device__ float g_boxes[NINST*4];
__device__ float g_det[NINST*6];
__device__ float g_ct[NINST*2];
__device__ float g_half[NINST*2];
__device__ float g_clsf[NINST];
__device__ int   g_valid[NINST];
__device__ float g_up[(size_t)NB*128*160*160];
__device__ hlf   g_cfh[(size_t)NB*160*160*64];
__device__ float g_pts[NINST*NP*2];
__device__ hlf   g_states[(size_t)NINST*ST_CH*NP];
__device__ hlf   g_fuse[(size_t)NINST*256*NP];
__device__ hlf   g_whb[128*KTOT];
__device__ hlf   g_wrb[7*128*KTOT];
__device__ hlf   g_wfb[256*KTOT];
__device__ hlf   g_wp1b[64*256];

// ---------------- weight transposition ----------------
__global__ void k_wtrans(const float* __restrict__ wh, const float* __restrict__ wr,
                         const float* __restrict__ wf, const float* __restrict__ wp1)
{
    int i = blockIdx.x*blockDim.x + threadIdx.x;
    const int n1 = 128*KTOT;
    const int n2 = 7*128*KTOT;
    const int n3 = 256*KTOT;
    const int n4 = 64*256;
    if (i < n1){
        int o = i / KTOT, k = i % KTOT, t = k >> 7, c = k & 127;
        g_whb[i] = __float2half(c < 66 ? wh[(o*66 + c)*9 + t] : 0.f);
        return;
    }
    i -= n1;
    if (i < n2){
        int l = i / (128*KTOT), r = i % (128*KTOT);
        int o = r / KTOT, k = r % KTOT, t = k >> 7, c = k & 127;
        g_wrb[i] = __float2half(wr[(((size_t)l*128 + o)*128 + c)*9 + t]);
        return;
    }
    i -= n2;
    if (i < n3){
        int o = i / KTOT, k = i % KTOT;
        float v = 0.f;
        if (k < 66) v = wf[o*1090 + k];
        else if (k >= 128) v = wf[o*1090 + k - 62];
        g_wfb[i] = __float2half(v);
        return;
    }
    i -= n3;
    if (i < n4){
        g_wp1b[i] = __float2half(wp1[i]);
    }
}

// ---------------- one-time zero of state channels 66..127 ----------------
__global__ void k_zinit(){
    long long i = (long long)blockIdx.x*256 + threadIdx.x;
    const long long total = (long long)NINST*62*64;   // u32 count
    if (i >= total) return;
    int inst = (int)(i / (62*64));
    int r = (int)(i % (62*64));
    int c = 66 + r/64, pw = r%64;
    *(u32*)(g_states + (size_t)inst*ST_CH*NP + (size_t)c*NP + pw*2) = 0u;
}

// ---------------- stage 1: scores ----------------
__global__ void k_scores(const float* __restrict__ pred){
    int i = blockIdx.x*blockDim.x + threadIdx.x;
    if (i >= NB*NPRED) return;
    const float* r = pred + (size_t)i*85;
    float obj = r[4];
    float best = -1e30f; int bc = 0;
    for (int c = 0; c < NCLS; c++){
        float s = obj * r[5+c];
        if (s > best){ best = s; bc = c; }
    }
    g_score[i] = (best > 0.2f) ? best : 0.0f;
    g_cls[i] = bc;
}

// ---------------- stage 2: stable top-300 ----------------
__global__ void __launch_bounds__(1024) k_topk(){
    extern __shared__ unsigned long long smk[];
    unsigned long long* keys = smk;
    unsigned long long* l1   = smk + 25600;
    __shared__ unsigned long long red[32];
    int b = blockIdx.x, tid = threadIdx.x;
    for (int i = tid; i < 25600; i += 1024){
        unsigned long long k = 0ULL;
        if (i < NPRED){
            unsigned u = __float_as_uint(g_score[b*NPRED + i]);
            k = ((unsigned long long)u << 32) | (unsigned)(~i);
        }
        keys[i] = k;
    }
    __syncthreads();
    if (tid < 800){
        unsigned long long m = 0ULL;
        for (int j = 0; j < 32; j++){ unsigned long long v = keys[tid*32 + j]; if (v > m) m = v; }
        l1[tid] = m;
    }
    __syncthreads();
    for (int it = 0; it < KDET; it++){
        unsigned long long v = (tid < 800) ? l1[tid] : 0ULL;
        #pragma unroll
        for (int o = 16; o > 0; o >>= 1){
            unsigned long long t2 = __shfl_down_sync(0xffffffffu, v, o);
            if (t2 > v) v = t2;
        }
        if ((tid & 31) == 0) red[tid >> 5] = v;
        __syncthreads();
        if (tid < 32){
            v = red[tid];
            #pragma unroll
            for (int o = 16; o > 0; o >>= 1){
                unsigned long long t2 = __shfl_down_sync(0xffffffffu, v, o);
                if (t2 > v) v = t2;
            }
            if (tid == 0) red[0] = v;
        }
        __syncthreads();
        unsigned long long w = red[0];
        int idx = (int)(~(unsigned)w);
        if (tid < 32){
            int ch = idx >> 5;
            if (tid == 0) keys[idx] = 0ULL;
            __syncwarp();
            unsigned long long kv = keys[ch*32 + tid];
            #pragma unroll
            for (int o = 16; o > 0; o >>= 1){
                unsigned long long t2 = __shfl_down_sync(0xffffffffu, kv, o);
                if (t2 > kv) kv = t2;
            }
            if (tid == 0){
                l1[ch] = kv;
                g_topidx[b*KDET + it] = idx;
                g_tops[b*KDET + it] = __uint_as_float((unsigned)(w >> 32));
            }
        }
        __syncthreads();
    }
}

// ---------------- stage 3 ----------------
__global__ void k_prep(const float* __restrict__ pred){
    int i = blockIdx.x*blockDim.x + threadIdx.x;
    if (i >= NINST) return;
    int b = i / KDET;
    int src = g_topidx[i];
    const float* r = pred + ((size_t)b*NPRED + src)*85;
    float cx = r[0], cy = r[1], w = r[2], h = r[3];
    float hw = w*0.5f, hh = h*0.5f;
    float x1 = cx - hw, y1 = cy - hh, x2 = cx + hw, y2 = cy + hh;
    g_boxes[4*i+0] = x1; g_boxes[4*i+1] = y1; g_boxes[4*i+2] = x2; g_boxes[4*i+3] = y2;
    float cf = (float)g_cls[b*NPRED + src];
    g_clsf[i] = cf;
    float sc = g_tops[i];
    g_det[6*i+0] = x1; g_det[6*i+1] = y1; g_det[6*i+2] = x2; g_det[6*i+3] = y2;
    g_det[6*i+4] = sc; g_det[6*i+5] = cf;
    float b0 = x1*0.25f, b1 = y1*0.25f, b2 = x2*0.25f, b3 = y2*0.25f;
    g_ct[2*i+0] = (b0 + b2)*0.5f;
    g_ct[2*i+1] = (b1 + b3)*0.5f;
    g_half[2*i+0] = fmaxf((b2 - b0)*0.5f, 1e-3f);
    g_half[2*i+1] = fmaxf((b3 - b1)*0.5f, 1e-3f);
}

// ---------------- stage 4: NMS ----------------
__global__ void k_nms(){
    __shared__ float bx[KDET][4];
    __shared__ float ar[KDET];
    __shared__ float sc[KDET];
    __shared__ int keep[KDET];
    int b = blockIdx.x, tid = threadIdx.x;
    for (int i = tid; i < KDET; i += 256){
        int g = b*KDET + i;
        float off = g_clsf[g]*4096.0f;
        float x1 = g_boxes[4*g+0] + off, y1 = g_boxes[4*g+1] + off;
        float x2 = g_boxes[4*g+2] + off, y2 = g_boxes[4*g+3] + off;
        bx[i][0] = x1; bx[i][1] = y1; bx[i][2] = x2; bx[i][3] = y2;
        ar[i] = (x2 - x1)*(y2 - y1);
        sc[i] = g_tops[g];
        keep[i] = 1;
    }
    __syncthreads();
    for (int i = 0; i < KDET; i++){
        if (keep[i]){
            float ax1 = bx[i][0], ay1 = bx[i][1], ax2 = bx[i][2], ay2 = bx[i][3], aa = ar[i];
            for (int j = i + 1 + tid; j < KDET; j += 256){
                float iw = fminf(ax2, bx[j][2]) - fmaxf(ax1, bx[j][0]);
                float ih = fminf(ay2, bx[j][3]) - fmaxf(ay1, bx[j][1]);
                iw = fmaxf(iw, 0.f); ih = fmaxf(ih, 0.f);
                float inter = iw*ih;
                float iou = inter / (aa + ar[j] - inter + 1e-9f);
                if (iou > 0.3f) keep[j] = 0;
            }
        }
        __syncthreads();
    }
    for (int i = tid; i < KDET; i += 256)
        g_valid[b*KDET + i] = (keep[i] && (sc[i] > 0.2f)) ? 1 : 0;
}

// ---------------- stage 5: upsample ----------------
__global__ void k_up(const float* __restrict__ feat){
    long long idx = (long long)blockIdx.x*256 + threadIdx.x;
    if (idx >= (long long)NB*128*160*160) return;
    int ox = (int)(idx % 160); long long r = idx/160;
    int oy = (int)(r % 160); r /= 160;
    int c = (int)(r % 128); int b = (int)(r/128);
    int iy = oy >> 1, ix = ox >> 1;
    int ya, yb; float wya, wyb;
    if (oy & 1){ ya = iy; yb = iy+1; wya = 0.75f; wyb = 0.25f; }
    else       { ya = iy-1; yb = iy; wya = 0.25f; wyb = 0.75f; }
    int xa, xb; float wxa, wxb;
    if (ox & 1){ xa = ix; xb = ix+1; wxa = 0.75f; wxb = 0.25f; }
    else       { xa = ix-1; xb = ix; wxa = 0.25f; wxb = 0.75f; }
    ya = max(0, min(79, ya)); yb = max(0, min(79, yb));
    xa = max(0, min(79, xa)); xb = max(0, min(79, xb));
    const float* f = feat + ((size_t)b*128 + c)*6400;
    float v = wya*(wxa*f[ya*80+xa] + wxb*f[ya*80+xb])
            + wyb*(wxa*f[yb*80+xa] + wxb*f[yb*80+xb]);
    g_up[idx] = v;
}

// ---------------- stage 6: 3x3 conv + SiLU (FFMA2) -> channel-last f16 ----------------
__global__ void __launch_bounds__(512) k_conv3(const float* __restrict__ Wc, const float* __restrict__ Bc){
    __shared__ float Xs[16][10][10];
    __shared__ float Wsp[16][9][64];
    int b = blockIdx.y;
    int tile = blockIdx.x;
    int ty0 = (tile/20)*8, tx0 = (tile%20)*8;
    int tid = threadIdx.x;
    int px = tid & 7, py = (tid >> 3) & 7, og = tid >> 6;
    u64 acc2[4] = {0ULL, 0ULL, 0ULL, 0ULL};
    for (int c0 = 0; c0 < 128; c0 += 16){
        __syncthreads();
        for (int i = tid; i < 1600; i += 512){
            int c = i/100, r = i%100, yy = r/10, xx = r%10;
            int gy = ty0 - 1 + yy, gx = tx0 - 1 + xx;
            float v = 0.f;
            if (gy >= 0 && gy < 160 && gx >= 0 && gx < 160)
                v = g_up[(((size_t)b*128 + c0 + c)*160 + gy)*160 + gx];
            Xs[c][yy][xx] = v;
        }
        for (int i = tid; i < 9216; i += 512){
            int o = i & 63, r = i >> 6, c = r/9, t = r%9;
            Wsp[c][t][o] = Wc[(o*128 + c0 + c)*9 + t];
        }
        __syncthreads();
        for (int c = 0; c < 16; c++){
            #pragma unroll
            for (int t = 0; t < 9; t++){
                u64 xv = bcast2(Xs[c][py + t/3][px + t%3]);
                const u64* wr = (const u64*)(&Wsp[c][t][og*8]);
                #pragma unroll
                for (int i = 0; i < 4; i++) ffma2(acc2[i], wr[i], xv);
            }
        }
    }
    int oy = ty0 + py, ox = tx0 + px;
    hlf hv[8];
    #pragma unroll
    for (int i = 0; i < 4; i++){
        float2 v2 = unpack2(acc2[i]);
        int o0 = og*8 + 2*i;
        float v0 = v2.x + Bc[o0];
        float v1 = v2.y + Bc[o0+1];
        v0 = v0 / (1.f + expf(-v0));
        v1 = v1 / (1.f + expf(-v1));
        hv[2*i]   = __float2half(v0);
        hv[2*i+1] = __float2half(v1);
    }
    *(uint4*)(g_cfh + (((size_t)b*160 + oy)*160 + ox)*64 + og*8) = *(uint4*)hv;
}

// ---------------- stage 7/8 ----------------
__global__ void k_initpts(){
    int i = blockIdx.x*blockDim.x + threadIdx.x;
    if (i >= NINST*NP) return;
    int inst = i >> 7, p = i & 127;
    float th = (float)p * 0.049087385212340517f;
    g_pts[i*2+0] = g_ct[inst*2+0] + g_half[inst*2+0]*cosf(th);
    g_pts[i*2+1] = g_ct[inst*2+1] + g_half[inst*2+1]*sinf(th);
}

__global__ void k_sample(){
    int inst = blockIdx.x;
    int p = threadIdx.x;
    int b = inst / KDET;
    float px = g_pts[(inst*NP + p)*2 + 0], py = g_pts[(inst*NP + p)*2 + 1];
    float x = fminf(fmaxf(px, 0.f), 159.f);
    float y = fminf(fmaxf(py, 0.f), 159.f);
    float x0f = fminf(fmaxf(floorf(x), 0.f), 158.f);
    float y0f = fminf(fmaxf(floorf(y), 0.f), 158.f);
    int x0 = (int)x0f, y0 = (int)y0f;
    float dx = x - x0f, dy = y - y0f;
    float w00 = (1.f-dx)*(1.f-dy), w10 = dx*(1.f-dy), w01 = (1.f-dx)*dy, w11 = dx*dy;
    const hlf* f = g_cfh + (size_t)b*25600*64;
    size_t base = (size_t)(y0*160 + x0)*64;
    const uint4* c00 = (const uint4*)(f + base);
    const uint4* c01 = (const uint4*)(f + base + 64);
    const uint4* c10 = (const uint4*)(f + base + 160*64);
    const uint4* c11 = (const uint4*)(f + base + 160*64 + 64);
    hlf* Z = g_states + (size_t)inst*ST_CH*NP;
    #pragma unroll
    for (int q = 0; q < 8; q++){
        uint4 a = c00[q], bq = c01[q], cq = c10[q], dq = c11[q];
        const __half2* ah = (const __half2*)&a;
        const __half2* bh = (const __half2*)&bq;
        const __half2* ch = (const __half2*)&cq;
        const __half2* dh = (const __half2*)&dq;
        #pragma unroll
        for (int j = 0; j < 4; j++){
            float2 fa = __half22float2(ah[j]);
            float2 fb = __half22float2(bh[j]);
            float2 fc = __half22float2(ch[j]);
            float2 fd = __half22float2(dh[j]);
            float v0 = fa.x*w00 + fb.x*w10 + fc.x*w01 + fd.x*w11;
            float v1 = fa.y*w00 + fb.y*w10 + fc.y*w01 + fd.y*w11;
            int c = q*8 + j*2;
            Z[c*NP + p]     = __float2half(v0);
            Z[(c+1)*NP + p] = __float2half(v1);
        }
    }
    float cx = g_ct[inst*2+0], cy = g_ct[inst*2+1];
    float hx = g_half[inst*2+0], hy = g_half[inst*2+1];
    Z[64*NP + p] = __float2half((px - cx)/hx);
    Z[65*NP + p] = __float2half((py - cy)/hy);
}

// ---- fused snake stack (f16 accumulate, skip-add from resident Xt) ----
__global__ void __launch_bounds__(256, 2) k_snake(
    const hlf* __restrict__ Wh, const hlf* __restrict__ Wr,
    const float* __restrict__ bh, const float* __restrict__ br,
    hlf* __restrict__ Sbase)
{
    extern __shared__ hlf sm[];
    hlf* Xt  = sm;
    hlf* Wb0 = sm + 128*136;
    hlf* Wb1 = Wb0 + 128*136;
    int inst = blockIdx.x;
    hlf* Sg = Sbase + (size_t)inst*(ST_CH*NP);
    int tid = threadIdx.x, warp = tid >> 5, lane = tid & 31;
    int wm = warp >> 1, wn = warp & 1, qr = lane >> 2, qc = lane & 3;
    int laneRow = lane & 15, laneHi = lane >> 4;

    #pragma unroll
    for (int q = 0; q < 8; q++){
        int idx = q*256 + tid;
        int row = idx >> 4, seg = idx & 15;
        cpa16(s2u(Wb0 + row*136 + seg*8), Wh + (size_t)row*KTOT + seg*8);
    }
    CP_COMMIT();
    {
        int ph = tid & 63, cc = tid >> 6;
        #pragma unroll
        for (int cb = 0; cb < 128; cb += 4){
            int c = cb + cc;
            u32 v = *(const u32*)(Sg + c*NP + ph*2);
            Xt[(2*ph)*136 + c]   = ((hlf*)&v)[0];
            Xt[(2*ph+1)*136 + c] = ((hlf*)&v)[1];
        }
    }
    u32 xtb = s2u(Xt);
    u32 aW0 = s2u(Wb0) + (u32)((wm*32 + laneRow)*272 + laneHi*16);
    u32 aW1 = s2u(Wb1) + (u32)((wm*32 + laneRow)*272 + laneHi*16);
    const int DILS[8] = {1,1,1,1,2,2,4,4};

    #pragma unroll 1
    for (int l = 0; l < 8; l++){
        int dil = DILS[l];
        int offs[9];
        #pragma unroll
        for (int t = 0; t < 9; t++) offs[t] = (dil*(t-4) + 128) & 127;
        u32 acc[2][8][2];
        #pragma unroll
        for (int i = 0; i < 2; i++)
            #pragma unroll
            for (int j = 0; j < 8; j++){ acc[i][j][0] = 0u; acc[i][j][1] = 0u; }

        #pragma unroll 1
        for (int t = 0; t < 9; t++){
            CP_WAIT0();
            __syncthreads();
            int g = l*9 + t;
            if (g < 71){
                int gn = g + 1, ln = gn/9, tn = gn - ln*9;
                const hlf* src = (ln ? (Wr + (size_t)(ln-1)*128*KTOT) : Wh) + tn*128;
                hlf* dstb = (gn & 1) ? Wb1 : Wb0;
                #pragma unroll
                for (int q = 0; q < 8; q++){
                    int idx = q*256 + tid;
                    int row = idx >> 4, seg = idx & 15;
                    cpa16(s2u(dstb + row*136 + seg*8), src + (size_t)row*KTOT + seg*8);
                }
                CP_COMMIT();
            }
            u32 aA = (g & 1) ? aW1 : aW0;
            u32 bAddr[4];
            #pragma unroll
            for (int jj = 0; jj < 4; jj++){
                int row = (wn*64 + jj*16 + laneRow + offs[t]) & 127;
                bAddr[jj] = xtb + (u32)(row*272 + laneHi*16);
            }
            #pragma unroll
            for (int cq2 = 0; cq2 < 8; cq2++){
                if (l == 0 && cq2 >= 5) continue;
                u32 koff = (u32)(cq2*32);
                u32 A0[4], A1[4], B[4][4];
                ldsm_x4(A0, aA + koff);
                ldsm_x4(A1, aA + 16*272 + koff);
                #pragma unroll
                for (int jj = 0; jj < 4; jj++) ldsm_x4(B[jj], bAddr[jj] + koff);
                #pragma unroll
                for (int jj = 0; jj < 4; jj++){
                    u32 b0[2] = { B[jj][0], B[jj][2] };
                    u32 b1[2] = { B[jj][1], B[jj][3] };
                    mma16816h(acc[0][2*jj],   A0, b0);
                    mma16816h(acc[0][2*jj+1], A0, b1);
                    mma16816h(acc[1][2*jj],   A1, b0);
                    mma16816h(acc[1][2*jj+1], A1, b1);
                }
            }
        }
        __syncthreads();
        const float* bl = l ? (br + (l-1)*128) : bh;
        hlf* Yg = Sg + (size_t)(128*(l+1))*NP;
        #pragma unroll
        for (int i = 0; i < 2; i++){
            #pragma unroll
            for (int j = 0; j < 8; j++){
                int row = wm*32 + i*16 + qr;
                int col = wn*64 + j*8 + qc*2;
                #pragma unroll
                for (int h = 0; h < 2; h++){
                    int rr = row + h*8;
                    float b0 = bl[rr];
                    float2 av = __half22float2(*(__half2*)&acc[i][j][h]);
                    float v0 = av.x + b0; v0 = v0 > 0.f ? v0 : 0.f;
                    float v1 = av.y + b0; v1 = v1 > 0.f ? v1 : 0.f;
                    if (l > 0){
                        // skip-add from resident transposed input (owner-exclusive slots)
                        v0 += __half2float(Xt[col*136 + rr]);
                        v1 += __half2float(Xt[(col+1)*136 + rr]);
                    }
                    u32 pk = packh(v0, v1);
                    *(u32*)(Yg + rr*NP + col) = pk;
                    Xt[col*136 + rr]     = ((hlf*)&pk)[0];
                    Xt[(col+1)*136 + rr] = ((hlf*)&pk)[1];
                }
            }
        }
    }
}

// ---- fuse GEMM (f16 accumulate) ----
__global__ void __launch_bounds__(256, 2) k_mma_fuse(
    const hlf* __restrict__ W, const float* __restrict__ bias,
    const hlf* __restrict__ Xbase, hlf* __restrict__ Ybase)
{
    extern __shared__ hlf sm[];
    hlf* Wb[2] = { sm, sm + 128*72 };
    hlf* Bb[2] = { sm + 2*128*72, sm + 3*128*72 };
    int inst = blockIdx.x, mblk = blockIdx.y;
    const hlf* Xg = Xbase + (size_t)inst*(ST_CH*NP);
    hlf* Yg = Ybase + (size_t)inst*(256*NP) + (size_t)mblk*128*NP;
    const hlf* Wm = W + (size_t)mblk*128*KTOT;
    int tid = threadIdx.x, warp = tid >> 5, lane = tid & 31;
    int wm = warp >> 1, wn = warp & 1, qr = lane >> 2, qc = lane & 3;
    int laneRow = lane & 15, laneHi = lane >> 4;
    u32 acc[2][8][2];
    #pragma unroll
    for (int i = 0; i < 2; i++)
        #pragma unroll
        for (int j = 0; j < 8; j++){ acc[i][j][0] = 0u; acc[i][j][1] = 0u; }
    int ph = tid & 63, cc = tid >> 6;

    {
        #pragma unroll
        for (int q = 0; q < 4; q++){
            int idx = q*256 + tid;
            int row = idx >> 3, seg = idx & 7;
            cpa16(s2u(Wb[0] + row*72 + seg*8), Wm + (size_t)row*KTOT + seg*8);
        }
        CP_COMMIT();
        #pragma unroll
        for (int q = 0; q < 16; q++){
            int c = 4*q + cc;
            u32 v = *(const u32*)(Xg + (size_t)c*NP + ph*2);
            Bb[0][(2*ph)*72 + c]   = ((hlf*)&v)[0];
            Bb[0][(2*ph+1)*72 + c] = ((hlf*)&v)[1];
        }
    }
    u32 aWa[2], bBa[2];
    #pragma unroll
    for (int z = 0; z < 2; z++){
        aWa[z] = s2u(Wb[z]) + (u32)((wm*32 + laneRow)*144 + laneHi*16);
        bBa[z] = s2u(Bb[z]) + (u32)((wn*64 + laneRow)*144 + laneHi*16);
    }
    #pragma unroll 1
    for (int chn = 0; chn < 18; chn++){
        CP_WAIT0();
        __syncthreads();
        u32 vreg[16];
        if (chn < 17){
            int k0 = (chn+1)*64;
            #pragma unroll
            for (int q = 0; q < 16; q++)
                vreg[q] = *(const u32*)(Xg + (size_t)(k0 + 4*q + cc)*NP + ph*2);
            hlf* dstw = Wb[(chn+1) & 1];
            const hlf* srcw = Wm + k0;
            #pragma unroll
            for (int q = 0; q < 4; q++){
                int idx = q*256 + tid;
                int row = idx >> 3, seg = idx & 7;
                cpa16(s2u(dstw + row*72 + seg*8), srcw + (size_t)row*KTOT + seg*8);
            }
            CP_COMMIT();
        }
        u32 aA = aWa[chn & 1];
        u32 bA = bBa[chn & 1];
        #pragma unroll
        for (int cq = 0; cq < 4; cq++){
            if (chn == 1 && cq >= 1) continue;
            u32 koff = (u32)(cq*32);
            u32 A0[4], A1[4], B0[4], B1[4];
            ldsm_x4(A0, aA + koff);
            ldsm_x4(A1, aA + 16*144 + koff);
            ldsm_x4(B0, bA + koff);
            ldsm_x4(B1, bA + 16*144 + koff);
            {
                u32 b0[2] = { B0[0], B0[2] }, b1[2] = { B0[1], B0[3] };
                u32 b2[2] = { B1[0], B1[2] }, b3[2] = { B1[1], B1[3] };
                mma16816h(acc[0][0], A0, b0); mma16816h(acc[0][1], A0, b1);
                mma16816h(acc[0][2], A0, b2); mma16816h(acc[0][3], A0, b3);
                mma16816h(acc[1][0], A1, b0); mma16816h(acc[1][1], A1, b1);
                mma16816h(acc[1][2], A1, b2); mma16816h(acc[1][3], A1, b3);
            }
            u32 B2[4], B3[4];
            ldsm_x4(B2, bA + 32*144 + koff);
            ldsm_x4(B3, bA + 48*144 + koff);
            {
                u32 b0[2] = { B2[0], B2[2] }, b1[2] = { B2[1], B2[3] };
                u32 b2[2] = { B3[0], B3[2] }, b3[2] = { B3[1], B3[3] };
                mma16816h(acc[0][4], A0, b0); mma16816h(acc[0][5], A0, b1);
                mma16816h(acc[0][6], A0, b2); mma16816h(acc[0][7], A0, b3);
                mma16816h(acc[1][4], A1, b0); mma16816h(acc[1][5], A1, b1);
                mma16816h(acc[1][6], A1, b2); mma16816h(acc[1][7], A1, b3);
            }
        }
        if (chn < 17){
            hlf* dstb = Bb[(chn+1) & 1];
            #pragma unroll
            for (int q = 0; q < 16; q++){
                int c = 4*q + cc;
                dstb[(2*ph)*72 + c]   = ((hlf*)&vreg[q])[0];
                dstb[(2*ph+1)*72 + c] = ((hlf*)&vreg[q])[1];
            }
        }
    }
    #pragma unroll
    for (int i = 0; i < 2; i++){
        #pragma unroll
        for (int j = 0; j < 8; j++){
            int row = wm*32 + i*16 + qr;
            int col = wn*64 + j*8 + qc*2;
            #pragma unroll
            for (int h = 0; h < 2; h++){
                int rr = row + h*8;
                float b0 = bias[mblk*128 + rr];
                float2 av = __half22float2(*(__half2*)&acc[i][j][h]);
                float v0 = av.x + b0; v0 = v0 > 0.f ? v0 : 0.f;
                float v1 = av.y + b0; v1 = v1 > 0.f ? v1 : 0.f;
                *(u32*)(Yg + rr*NP + col) = packh(v0, v1);
            }
        }
    }
}

// ---------------- fused tail: p1 (HMMA 256->64) + p2 (64->2) + pts update ----------------
// smem: Wb0,Wb1 64*72 | Bb0,Bb1 128*72  (55296 B); hbufS aliases sm after compute (64*132 f32)
__global__ void __launch_bounds__(256, 2) k_tail(
    const hlf* __restrict__ W, const float* __restrict__ bias,
    const float* __restrict__ w2, const float* __restrict__ b2)
{
    extern __shared__ hlf sm[];
    hlf* Wb[2] = { sm, sm + 64*72 };
    hlf* Bb[2] = { sm + 2*64*72, sm + 2*64*72 + 128*72 };
    float* hbufS = (float*)sm;   // aliased after mainloop (33792 B < 55296 B)
    int inst = blockIdx.x;
    const hlf* Xg = g_fuse + (size_t)inst*(256*NP);
    int tid = threadIdx.x, warp = tid >> 5, lane = tid & 31;
    int wm = warp >> 2, wn = warp & 3, qr = lane >> 2, qc = lane & 3;
    int laneRow = lane & 15, laneHi = lane >> 4;
    u32 acc[2][4][2];
    #pragma unroll
    for (int i = 0; i < 2; i++)
        #pragma unroll
        for (int j = 0; j < 4; j++){ acc[i][j][0] = 0u; acc[i][j][1] = 0u; }
    int ph = tid & 63, cc = tid >> 6;

    {
        #pragma unroll
        for (int q = 0; q < 2; q++){
            int idx = q*256 + tid;
            int row = idx >> 3, seg = idx & 7;
            cpa16(s2u(Wb[0] + row*72 + seg*8), W + (size_t)row*256 + seg*8);
        }
        CP_COMMIT();
        #pragma unroll
        for (int q = 0; q < 16; q++){
            int c = 4*q + cc;
            u32 v = *(const u32*)(Xg + (size_t)c*NP + ph*2);
            Bb[0][(2*ph)*72 + c]   = ((hlf*)&v)[0];
            Bb[0][(2*ph+1)*72 + c] = ((hlf*)&v)[1];
        }
    }
    u32 aWa[2], bBa[2];
    #pragma unroll
    for (int z = 0; z < 2; z++){
        aWa[z] = s2u(Wb[z]) + (u32)((wm*32 + laneRow)*144 + laneHi*16);
        bBa[z] = s2u(Bb[z]) + (u32)((wn*32 + laneRow)*144 + laneHi*16);
    }
    #pragma unroll 1
    for (int chn = 0; chn < 4; chn++){
        CP_WAIT0();
        __syncthreads();
        u32 vreg[16];
        if (chn < 3){
            int k0 = (chn+1)*64;
            #pragma unroll
            for (int q = 0; q < 16; q++)
                vreg[q] = *(const u32*)(Xg + (size_t)(k0 + 4*q + cc)*NP + ph*2);
            hlf* dstw = Wb[(chn+1) & 1];
            const hlf* srcw = W + k0;
            #pragma unroll
            for (int q = 0; q < 2; q++){
                int idx = q*256 + tid;
                int row = idx >> 3, seg = idx & 7;
                cpa16(s2u(dstw + row*72 + seg*8), srcw + (size_t)row*256 + seg*8);
            }
            CP_COMMIT();
        }
        u32 aA = aWa[chn & 1];
        u32 bA = bBa[chn & 1];
        #pragma unroll
        for (int cq = 0; cq < 4; cq++){
            u32 koff = (u32)(cq*32);
            u32 A0[4], A1[4], B0[4], B1[4];
            ldsm_x4(A0, aA + koff);
            ldsm_x4(A1, aA + 16*144 + koff);
            ldsm_x4(B0, bA + koff);
            ldsm_x4(B1, bA + 16*144 + koff);
            {
                u32 b0[2] = { B0[0], B0[2] }, b1[2] = { B0[1], B0[3] };
                u32 b2[2] = { B1[0], B1[2] }, b3[2] = { B1[1], B1[3] };
                mma16816h(acc[0][0], A0, b0); mma16816h(acc[0][1], A0, b1);
                mma16816h(acc[0][2], A0, b2); mma16816h(acc[0][3], A0, b3);
                mma16816h(acc[1][0], A1, b0); mma16816h(acc[1][1], A1, b1);
                mma16816h(acc[1][2], A1, b2); mma16816h(acc[1][3], A1, b3);
            }
        }
        if (chn < 3){
            hlf* dstb = Bb[(chn+1) & 1];
            #pragma unroll
            for (int q = 0; q < 16; q++){
                int c = 4*q + cc;
                dstb[(2*ph)*72 + c]   = ((hlf*)&vreg[q])[0];
                dstb[(2*ph+1)*72 + c] = ((hlf*)&vreg[q])[1];
            }
        }
    }
    // p1 epilogue -> smem (alias; all compute reads of Wb/Bb are complete)
    __syncthreads();
    #pragma unroll
    for (int i = 0; i < 2; i++){
        #pragma unroll
        for (int j = 0; j < 4; j++){
            int row = wm*32 + i*16 + qr;
            int col = wn*32 + j*8 + qc*2;
            #pragma unroll
            for (int h = 0; h < 2; h++){
                int rr = row + h*8;
                float b0 = bias[rr];
                float2 av = __half22float2(*(__half2*)&acc[i][j][h]);
                float v0 = av.x + b0; v0 = v0 > 0.f ? v0 : 0.f;
                float v1 = av.y + b0; v1 = v1 > 0.f ? v1 : 0.f;
                *(float2*)(hbufS + rr*132 + col) = make_float2(v0, v1);
            }
        }
    }
    __syncthreads();
    // p2: tid<128 -> x-offset of point tid; tid>=128 -> y-offset of point tid-128
    {
        int p = tid & 127, which = tid >> 7;
        const float* w = w2 + which*64;
        float a = 0.f;
        for (int c = 0; c < 64; c++)
            a += w[c]*hbufS[c*132 + p];
        g_pts[(inst*NP + p)*2 + which] += a + b2[which];
    }
}

// ---------------- output assembly ----------------
__global__ void k_out(float* __restrict__ out){
    int i = blockIdx.x*blockDim.x + threadIdx.x;
    const int n_det = NINST*6;
    const int n_ct  = NINST*2;
    const int n_pts = NINST*NP*2;
    if (i < n_det){ out[i] = g_det[i]; return; }
    int j = i - n_det;
    if (j < n_ct){ out[i] = g_ct[j]; return; }
    j -= n_ct;
    if (j < n_pts){
        int inst = j / (NP*2);
        out[i] = g_valid[inst] ? g_pts[j] : 0.0f;
        return;
    }
    j -= n_pts;
    if (j < NINST) out[i] = g_valid[j] ? 1.0f : 0.0f;
}

// ---------------- host launcher ----------------
extern "C" void kernel_launch(void* const* d_in, const int* in_sizes, int n_in,
                              void* d_out, int out_size)
{
    const float* pred   = (const float*)d_in[0];
    const float* feat   = (const float*)d_in[1];
    const float* conv_w = (const float*)d_in[2];
    const float* conv_b = (const float*)d_in[3];
    const float* b_head = (const float*)d_in[5];
    const float* b_res  = (const float*)d_in[7];
    const float* b_fuse = (const float*)d_in[9];
    const float* b_p1   = (const float*)d_in[11];
    const float* w_p2   = (const float*)d_in[12];
    const float* b_p2   = (const float*)d_in[13];

    cudaFuncSetAttribute(k_topk, cudaFuncAttributeMaxDynamicSharedMemorySize, 26400*8);
    cudaFuncSetAttribute(k_snake, cudaFuncAttributeMaxDynamicSharedMemorySize, 104448);
    cudaFuncSetAttribute(k_mma_fuse, cudaFuncAttributeMaxDynamicSharedMemorySize, 73728);
    cudaFuncSetAttribute(k_tail, cudaFuncAttributeMaxDynamicSharedMemorySize, 55296);

    void *pv;
    cudaGetSymbolAddress(&pv, g_states); hlf* p_states = (hlf*)pv;
    cudaGetSymbolAddress(&pv, g_fuse);   hlf* p_fuse = (hlf*)pv;
    cudaGetSymbolAddress(&pv, g_whb);    hlf* p_whb = (hlf*)pv;
    cudaGetSymbolAddress(&pv, g_wrb);    hlf* p_wrb = (hlf*)pv;
    cudaGetSymbolAddress(&pv, g_wfb);    hlf* p_wfb = (hlf*)pv;
    cudaGetSymbolAddress(&pv, g_wp1b);   hlf* p_wp1b = (hlf*)pv;

    cudaStream_t s1;
    cudaStreamCreate(&s1);
    cudaEvent_t e0, e1;
    cudaEventCreateWithFlags(&e0, cudaEventDisableTiming);
    cudaEventCreateWithFlags(&e1, cudaEventDisableTiming);

    cudaEventRecord(e0, 0);
    cudaStreamWaitEvent(s1, e0, 0);
    k_up<<<(int)(((long long)NB*128*160*160 + 255)/256), 256, 0, s1>>>(feat);
    k_conv3<<<dim3(400, NB), 512, 0, s1>>>(conv_w, conv_b);
    cudaEventRecord(e1, s1);

    {
        int n = 128*KTOT + 7*128*KTOT + 256*KTOT + 64*256;
        k_wtrans<<<(n + 255)/256, 256>>>((const float*)d_in[4], (const float*)d_in[6],
                                         (const float*)d_in[8], (const float*)d_in[10]);
    }
    {
        long long n = (long long)NINST*62*64;
        k_zinit<<<(int)((n + 255)/256), 256>>>();
    }
    k_scores<<<(NB*NPRED + 255)/256, 256>>>(pred);
    k_topk<<<NB, 1024, 26400*8>>>();
    k_prep<<<(NINST + 255)/256, 256>>>(pred);
    k_nms<<<NB, 256>>>();
    k_initpts<<<(NINST*NP + 255)/256, 256>>>();

    cudaStreamWaitEvent(0, e1, 0);

    for (int it = 0; it < 2; it++){
        k_sample<<<NINST, 128>>>();
        k_snake<<<NINST, 256, 104448>>>(p_whb, p_wrb, b_head, b_res, p_states);
        k_mma_fuse<<<dim3(NINST, 2), 256, 73728>>>(p_wfb, b_fuse, p_states, p_fuse);
        k_tail<<<NINST, 256, 55296>>>(p_wp1b, b_p1, w_p2, b_p2);
    }
    {
        int n = NINST*6 + NINST*2 + NINST*NP*2 + NINST;
        k_out<<<(n + 255)/256, 256>>>((float*)d_out);
    }
}

// round 17
// speedup vs baseline: 1.1576x; 1.0106x over previous
#include <cuda_runtime.h>
#include <cuda_fp16.h>
#include <math.h>

#define NB 16
#define NPRED 25200
#define NCLS 80
#define KDET 300
#define NP 128
#define NINST (NB*KDET)
#define ST_CH 1152
#define KTOT 1152

typedef unsigned long long u64;
typedef unsigned int u32;
typedef __half hlf;

__device__ __forceinline__ void ffma2(u64& acc, u64 a, u64 b){
    asm("fma.rn.f32x2 %0, %1, %2, %3;" : "=l"(acc) : "l"(a), "l"(b), "l"(acc));
}
__device__ __forceinline__ u64 bcast2(float x){
    u64 r;
    asm("mov.b64 %0, {%1, %1};" : "=l"(r) : "r"(__float_as_uint(x)));
    return r;
}
__device__ __forceinline__ float2 unpack2(u64 v){
    float2 f;
    asm("mov.b64 {%0, %1}, %2;" : "=f"(f.x), "=f"(f.y) : "l"(v));
    return f;
}
__device__ __forceinline__ u32 s2u(const void* p){
    u32 a; asm("{ .reg .u64 t; cvta.to.shared.u64 t, %1; cvt.u32.u64 %0, t; }" : "=r"(a) : "l"(p));
    return a;
}
__device__ __forceinline__ void cpa16(u32 dst, const void* src){
    asm volatile("cp.async.cg.shared.global [%0], [%1], 16;" :: "r"(dst), "l"(src));
}
#define CP_COMMIT() asm volatile("cp.async.commit_group;" ::: "memory")
#define CP_WAIT0()  asm volatile("cp.async.wait_group 0;" ::: "memory")

__device__ __forceinline__ void ldsm_x4(u32* r, u32 addr){
    asm volatile("ldmatrix.sync.aligned.m8n8.x4.shared.b16 {%0,%1,%2,%3}, [%4];"
        : "=r"(r[0]), "=r"(r[1]), "=r"(r[2]), "=r"(r[3]) : "r"(addr));
}
__device__ __forceinline__ void mma16816h(u32* d, const u32* a, const u32* b){
    asm volatile("mma.sync.aligned.m16n8k16.row.col.f16.f16.f16.f16 "
        "{%0,%1}, {%2,%3,%4,%5}, {%6,%7}, {%0,%1};"
        : "+r"(d[0]), "+r"(d[1])
        : "r"(a[0]), "r"(a[1]), "r"(a[2]), "r"(a[3]), "r"(b[0]), "r"(b[1]));
}
__device__ __forceinline__ u32 packh(float v0, float v1){
    hlf h0 = __float2half(v0), h1 = __float2half(v1);
    return ((u32)*(unsigned short*)&h1 << 16) | (u32)*(unsigned short*)&h0;
}

// ---------------- device scratch ----------------
__device__ float g_score[NB*NPRED];
__device__ int   g_cls[NB*NPRED];
__device__ int   g_topidx[NINST];
__device__ float g_tops[NINST];
__device__ float g_boxes[NINST*4];
__device__ float g_det[NINST*6];
__device__ float g_ct[NINST*2];
__device__ float g_half[NINST*2];
__device__ float g_clsf[NINST];
__device__ int   g_valid[NINST];
__device__ float g_up[(size_t)NB*128*160*160];
__device__ hlf   g_cfh[(size_t)NB*160*160*64];
__device__ float g_pts[NINST*NP*2];
__device__ hlf   g_states[(size_t)NINST*ST_CH*NP];
__device__ hlf   g_fuse[(size_t)NINST*256*NP];
__device__ hlf   g_whb[128*KTOT];
__device__ hlf   g_wrb[7*128*KTOT];
__device__ hlf   g_wfb[256*KTOT];
__device__ hlf   g_wp1b[64*256];

// ---------------- weight transposition ----------------
__global__ void k_wtrans(const float* __restrict__ wh, const float* __restrict__ wr,
                         const float* __restrict__ wf, const float* __restrict__ wp1)
{
    int i = blockIdx.x*blockDim.x + threadIdx.x;
    const int n1 = 128*KTOT;
    const int n2 = 7*128*KTOT;
    const int n3 = 256*KTOT;
    const int n4 = 64*256;
    if (i < n1){
        int o = i / KTOT, k = i % KTOT, t = k >> 7, c = k & 127;
        g_whb[i] = __float2half(c < 66 ? wh[(o*66 + c)*9 + t] : 0.f);
        return;
    }
    i -= n1;
    if (i < n2){
        int l = i / (128*KTOT), r = i % (128*KTOT);
        int o = r / KTOT, k = r % KTOT, t = k >> 7, c = k & 127;
        g_wrb[i] = __float2half(wr[(((size_t)l*128 + o)*128 + c)*9 + t]);
        return;
    }
    i -= n2;
    if (i < n3){
        int o = i / KTOT, k = i % KTOT;
        float v = 0.f;
        if (k < 66) v = wf[o*1090 + k];
        else if (k >= 128) v = wf[o*1090 + k - 62];
        g_wfb[i] = __float2half(v);
        return;
    }
    i -= n3;
    if (i < n4){
        g_wp1b[i] = __float2half(wp1[i]);
    }
}

// ---------------- one-time zero of state channels 66..127 ----------------
__global__ void k_zinit(){
    long long i = (long long)blockIdx.x*256 + threadIdx.x;
    const long long total = (long long)NINST*62*64;
    if (i >= total) return;
    int inst = (int)(i / (62*64));
    int r = (int)(i % (62*64));
    int c = 66 + r/64, pw = r%64;
    *(u32*)(g_states + (size_t)inst*ST_CH*NP + (size_t)c*NP + pw*2) = 0u;
}

// ---------------- stage 1: scores ----------------
__global__ void k_scores(const float* __restrict__ pred){
    int i = blockIdx.x*blockDim.x + threadIdx.x;
    if (i >= NB*NPRED) return;
    const float* r = pred + (size_t)i*85;
    float obj = r[4];
    float best = -1e30f; int bc = 0;
    for (int c = 0; c < NCLS; c++){
        float s = obj * r[5+c];
        if (s > best){ best = s; bc = c; }
    }
    g_score[i] = (best > 0.2f) ? best : 0.0f;
    g_cls[i] = bc;
}

// ---------------- stage 2: stable top-300 ----------------
__global__ void __launch_bounds__(1024) k_topk(){
    extern __shared__ unsigned long long smk[];
    unsigned long long* keys = smk;
    unsigned long long* l1   = smk + 25600;
    __shared__ unsigned long long red[32];
    int b = blockIdx.x, tid = threadIdx.x;
    for (int i = tid; i < 25600; i += 1024){
        unsigned long long k = 0ULL;
        if (i < NPRED){
            unsigned u = __float_as_uint(g_score[b*NPRED + i]);
            k = ((unsigned long long)u << 32) | (unsigned)(~i);
        }
        keys[i] = k;
    }
    __syncthreads();
    if (tid < 800){
        unsigned long long m = 0ULL;
        for (int j = 0; j < 32; j++){ unsigned long long v = keys[tid*32 + j]; if (v > m) m = v; }
        l1[tid] = m;
    }
    __syncthreads();
    for (int it = 0; it < KDET; it++){
        unsigned long long v = (tid < 800) ? l1[tid] : 0ULL;
        #pragma unroll
        for (int o = 16; o > 0; o >>= 1){
            unsigned long long t2 = __shfl_down_sync(0xffffffffu, v, o);
            if (t2 > v) v = t2;
        }
        if ((tid & 31) == 0) red[tid >> 5] = v;
        __syncthreads();
        if (tid < 32){
            v = red[tid];
            #pragma unroll
            for (int o = 16; o > 0; o >>= 1){
                unsigned long long t2 = __shfl_down_sync(0xffffffffu, v, o);
                if (t2 > v) v = t2;
            }
            if (tid == 0) red[0] = v;
        }
        __syncthreads();
        unsigned long long w = red[0];
        int idx = (int)(~(unsigned)w);
        if (tid < 32){
            int ch = idx >> 5;
            if (tid == 0) keys[idx] = 0ULL;
            __syncwarp();
            unsigned long long kv = keys[ch*32 + tid];
            #pragma unroll
            for (int o = 16; o > 0; o >>= 1){
                unsigned long long t2 = __shfl_down_sync(0xffffffffu, kv, o);
                if (t2 > kv) kv = t2;
            }
            if (tid == 0){
                l1[ch] = kv;
                g_topidx[b*KDET + it] = idx;
                g_tops[b*KDET + it] = __uint_as_float((unsigned)(w >> 32));
            }
        }
        __syncthreads();
    }
}

// ---------------- stage 3 ----------------
__global__ void k_prep(const float* __restrict__ pred){
    int i = blockIdx.x*blockDim.x + threadIdx.x;
    if (i >= NINST) return;
    int b = i / KDET;
    int src = g_topidx[i];
    const float* r = pred + ((size_t)b*NPRED + src)*85;
    float cx = r[0], cy = r[1], w = r[2], h = r[3];
    float hw = w*0.5f, hh = h*0.5f;
    float x1 = cx - hw, y1 = cy - hh, x2 = cx + hw, y2 = cy + hh;
    g_boxes[4*i+0] = x1; g_boxes[4*i+1] = y1; g_boxes[4*i+2] = x2; g_boxes[4*i+3] = y2;
    float cf = (float)g_cls[b*NPRED + src];
    g_clsf[i] = cf;
    float sc = g_tops[i];
    g_det[6*i+0] = x1; g_det[6*i+1] = y1; g_det[6*i+2] = x2; g_det[6*i+3] = y2;
    g_det[6*i+4] = sc; g_det[6*i+5] = cf;
    float b0 = x1*0.25f, b1 = y1*0.25f, b2 = x2*0.25f, b3 = y2*0.25f;
    g_ct[2*i+0] = (b0 + b2)*0.5f;
    g_ct[2*i+1] = (b1 + b3)*0.5f;
    g_half[2*i+0] = fmaxf((b2 - b0)*0.5f, 1e-3f);
    g_half[2*i+1] = fmaxf((b3 - b1)*0.5f, 1e-3f);
}

// ---------------- stage 4: NMS ----------------
__global__ void k_nms(){
    __shared__ float bx[KDET][4];
    __shared__ float ar[KDET];
    __shared__ float sc[KDET];
    __shared__ int keep[KDET];
    int b = blockIdx.x, tid = threadIdx.x;
    for (int i = tid; i < KDET; i += 256){
        int g = b*KDET + i;
        float off = g_clsf[g]*4096.0f;
        float x1 = g_boxes[4*g+0] + off, y1 = g_boxes[4*g+1] + off;
        float x2 = g_boxes[4*g+2] + off, y2 = g_boxes[4*g+3] + off;
        bx[i][0] = x1; bx[i][1] = y1; bx[i][2] = x2; bx[i][3] = y2;
        ar[i] = (x2 - x1)*(y2 - y1);
        sc[i] = g_tops[g];
        keep[i] = 1;
    }
    __syncthreads();
    for (int i = 0; i < KDET; i++){
        if (keep[i]){
            float ax1 = bx[i][0], ay1 = bx[i][1], ax2 = bx[i][2], ay2 = bx[i][3], aa = ar[i];
            for (int j = i + 1 + tid; j < KDET; j += 256){
                float iw = fminf(ax2, bx[j][2]) - fmaxf(ax1, bx[j][0]);
                float ih = fminf(ay2, bx[j][3]) - fmaxf(ay1, bx[j][1]);
                iw = fmaxf(iw, 0.f); ih = fmaxf(ih, 0.f);
                float inter = iw*ih;
                float iou = inter / (aa + ar[j] - inter + 1e-9f);
                if (iou > 0.3f) keep[j] = 0;
            }
        }
        __syncthreads();
    }
    for (int i = tid; i < KDET; i += 256)
        g_valid[b*KDET + i] = (keep[i] && (sc[i] > 0.2f)) ? 1 : 0;
}

// ---------------- stage 5: upsample ----------------
__global__ void k_up(const float* __restrict__ feat){
    long long idx = (long long)blockIdx.x*256 + threadIdx.x;
    if (idx >= (long long)NB*128*160*160) return;
    int ox = (int)(idx % 160); long long r = idx/160;
    int oy = (int)(r % 160); r /= 160;
    int c = (int)(r % 128); int b = (int)(r/128);
    int iy = oy >> 1, ix = ox >> 1;
    int ya, yb; float wya, wyb;
    if (oy & 1){ ya = iy; yb = iy+1; wya = 0.75f; wyb = 0.25f; }
    else       { ya = iy-1; yb = iy; wya = 0.25f; wyb = 0.75f; }
    int xa, xb; float wxa, wxb;
    if (ox & 1){ xa = ix; xb = ix+1; wxa = 0.75f; wxb = 0.25f; }
    else       { xa = ix-1; xb = ix; wxa = 0.25f; wxb = 0.75f; }
    ya = max(0, min(79, ya)); yb = max(0, min(79, yb));
    xa = max(0, min(79, xa)); xb = max(0, min(79, xb));
    const float* f = feat + ((size_t)b*128 + c)*6400;
    float v = wya*(wxa*f[ya*80+xa] + wxb*f[ya*80+xb])
            + wyb*(wxa*f[yb*80+xa] + wxb*f[yb*80+xb]);
    g_up[idx] = v;
}

// ---------------- stage 6: 3x3 conv + SiLU (FFMA2) -> channel-last f16 ----------------
__global__ void __launch_bounds__(512) k_conv3(const float* __restrict__ Wc, const float* __restrict__ Bc){
    __shared__ float Xs[16][10][10];
    __shared__ float Wsp[16][9][64];
    int b = blockIdx.y;
    int tile = blockIdx.x;
    int ty0 = (tile/20)*8, tx0 = (tile%20)*8;
    int tid = threadIdx.x;
    int px = tid & 7, py = (tid >> 3) & 7, og = tid >> 6;
    u64 acc2[4] = {0ULL, 0ULL, 0ULL, 0ULL};
    for (int c0 = 0; c0 < 128; c0 += 16){
        __syncthreads();
        for (int i = tid; i < 1600; i += 512){
            int c = i/100, r = i%100, yy = r/10, xx = r%10;
            int gy = ty0 - 1 + yy, gx = tx0 - 1 + xx;
            float v = 0.f;
            if (gy >= 0 && gy < 160 && gx >= 0 && gx < 160)
                v = g_up[(((size_t)b*128 + c0 + c)*160 + gy)*160 + gx];
            Xs[c][yy][xx] = v;
        }
        for (int i = tid; i < 9216; i += 512){
            int o = i & 63, r = i >> 6, c = r/9, t = r%9;
            Wsp[c][t][o] = Wc[(o*128 + c0 + c)*9 + t];
        }
        __syncthreads();
        for (int c = 0; c < 16; c++){
            #pragma unroll
            for (int t = 0; t < 9; t++){
                u64 xv = bcast2(Xs[c][py + t/3][px + t%3]);
                const u64* wr = (const u64*)(&Wsp[c][t][og*8]);
                #pragma unroll
                for (int i = 0; i < 4; i++) ffma2(acc2[i], wr[i], xv);
            }
        }
    }
    int oy = ty0 + py, ox = tx0 + px;
    hlf hv[8];
    #pragma unroll
    for (int i = 0; i < 4; i++){
        float2 v2 = unpack2(acc2[i]);
        int o0 = og*8 + 2*i;
        float v0 = v2.x + Bc[o0];
        float v1 = v2.y + Bc[o0+1];
        v0 = v0 / (1.f + expf(-v0));
        v1 = v1 / (1.f + expf(-v1));
        hv[2*i]   = __float2half(v0);
        hv[2*i+1] = __float2half(v1);
    }
    *(uint4*)(g_cfh + (((size_t)b*160 + oy)*160 + ox)*64 + og*8) = *(uint4*)hv;
}

// ---------------- contour init ----------------
__global__ void k_initpts(){
    int i = blockIdx.x*blockDim.x + threadIdx.x;
    if (i >= NINST*NP) return;
    int inst = i >> 7, p = i & 127;
    float th = (float)p * 0.049087385212340517f;
    g_pts[i*2+0] = g_ct[inst*2+0] + g_half[inst*2+0]*cosf(th);
    g_pts[i*2+1] = g_ct[inst*2+1] + g_half[inst*2+1]*sinf(th);
}

// ---- fused sample + snake stack (f16 accumulate) ----
__global__ void __launch_bounds__(256, 2) k_snake(
    const hlf* __restrict__ Wh, const hlf* __restrict__ Wr,
    const float* __restrict__ bh, const float* __restrict__ br,
    hlf* __restrict__ Sbase)
{
    extern __shared__ hlf sm[];
    hlf* Xt  = sm;
    hlf* Wb0 = sm + 128*136;
    hlf* Wb1 = Wb0 + 128*136;
    int inst = blockIdx.x;
    hlf* Sg = Sbase + (size_t)inst*(ST_CH*NP);
    int tid = threadIdx.x, warp = tid >> 5, lane = tid & 31;
    int wm = warp >> 1, wn = warp & 1, qr = lane >> 2, qc = lane & 3;
    int laneRow = lane & 15, laneHi = lane >> 4;

    // ---- prologue: warps 4-7 prefetch W tap0; warps 0-3 bilinear-sample into Xt ----
    if (tid >= 128){
        int t2 = tid - 128;
        #pragma unroll
        for (int q = 0; q < 16; q++){
            int idx = q*128 + t2;
            int row = idx >> 4, seg = idx & 15;
            cpa16(s2u(Wb0 + row*136 + seg*8), Wh + (size_t)row*KTOT + seg*8);
        }
    }
    CP_COMMIT();
    if (tid < 128){
        int p = tid;
        int b = inst / KDET;
        float px = g_pts[(inst*NP + p)*2 + 0], py = g_pts[(inst*NP + p)*2 + 1];
        float x = fminf(fmaxf(px, 0.f), 159.f);
        float y = fminf(fmaxf(py, 0.f), 159.f);
        float x0f = fminf(fmaxf(floorf(x), 0.f), 158.f);
        float y0f = fminf(fmaxf(floorf(y), 0.f), 158.f);
        int x0 = (int)x0f, y0 = (int)y0f;
        float dx = x - x0f, dy = y - y0f;
        float w00 = (1.f-dx)*(1.f-dy), w10 = dx*(1.f-dy), w01 = (1.f-dx)*dy, w11 = dx*dy;
        const hlf* f = g_cfh + (size_t)b*25600*64;
        size_t base = (size_t)(y0*160 + x0)*64;
        const uint4* c00 = (const uint4*)(f + base);
        const uint4* c01 = (const uint4*)(f + base + 64);
        const uint4* c10 = (const uint4*)(f + base + 160*64);
        const uint4* c11 = (const uint4*)(f + base + 160*64 + 64);
        hlf* xrow = Xt + p*136;
        #pragma unroll
        for (int q = 0; q < 8; q++){
            uint4 a = c00[q], bq = c01[q], cq = c10[q], dq = c11[q];
            const __half2* ah = (const __half2*)&a;
            const __half2* bhh = (const __half2*)&bq;
            const __half2* chh = (const __half2*)&cq;
            const __half2* dhh = (const __half2*)&dq;
            #pragma unroll
            for (int j = 0; j < 4; j++){
                float2 fa = __half22float2(ah[j]);
                float2 fb = __half22float2(bhh[j]);
                float2 fc = __half22float2(chh[j]);
                float2 fd = __half22float2(dhh[j]);
                float v0 = fa.x*w00 + fb.x*w10 + fc.x*w01 + fd.x*w11;
                float v1 = fa.y*w00 + fb.y*w10 + fc.y*w01 + fd.y*w11;
                int c = q*8 + j*2;
                u32 pk = packh(v0, v1);
                *(u32*)(xrow + c) = pk;
                Sg[c*NP + p]     = ((hlf*)&pk)[0];
                Sg[(c+1)*NP + p] = ((hlf*)&pk)[1];
            }
        }
        float cx = g_ct[inst*2+0], cy = g_ct[inst*2+1];
        float hx = g_half[inst*2+0], hy = g_half[inst*2+1];
        float r0 = (px - cx)/hx, r1 = (py - cy)/hy;
        u32 pk = packh(r0, r1);
        *(u32*)(xrow + 64) = pk;
        Sg[64*NP + p] = ((hlf*)&pk)[0];
        Sg[65*NP + p] = ((hlf*)&pk)[1];
        #pragma unroll
        for (int c = 66; c < 128; c += 2) *(u32*)(xrow + c) = 0u;
    }
    u32 xtb = s2u(Xt);
    u32 aW0 = s2u(Wb0) + (u32)((wm*32 + laneRow)*272 + laneHi*16);
    u32 aW1 = s2u(Wb1) + (u32)((wm*32 + laneRow)*272 + laneHi*16);
    const int DILS[8] = {1,1,1,1,2,2,4,4};

    #pragma unroll 1
    for (int l = 0; l < 8; l++){
        int dil = DILS[l];
        int offs[9];
        #pragma unroll
        for (int t = 0; t < 9; t++) offs[t] = (dil*(t-4) + 128) & 127;
        u32 acc[2][8][2];
        #pragma unroll
        for (int i = 0; i < 2; i++)
            #pragma unroll
            for (int j = 0; j < 8; j++){ acc[i][j][0] = 0u; acc[i][j][1] = 0u; }

        #pragma unroll 1
        for (int t = 0; t < 9; t++){
            CP_WAIT0();
            __syncthreads();
            int g = l*9 + t;
            if (g < 71){
                int gn = g + 1, ln = gn/9, tn = gn - ln*9;
                const hlf* src = (ln ? (Wr + (size_t)(ln-1)*128*KTOT) : Wh) + tn*128;
                hlf* dstb = (gn & 1) ? Wb1 : Wb0;
                #pragma unroll
                for (int q = 0; q < 8; q++){
                    int idx = q*256 + tid;
                    int row = idx >> 4, seg = idx & 15;
                    cpa16(s2u(dstb + row*136 + seg*8), src + (size_t)row*KTOT + seg*8);
                }
                CP_COMMIT();
            }
            u32 aA = (g & 1) ? aW1 : aW0;
            u32 bAddr[4];
            #pragma unroll
            for (int jj = 0; jj < 4; jj++){
                int row = (wn*64 + jj*16 + laneRow + offs[t]) & 127;
                bAddr[jj] = xtb + (u32)(row*272 + laneHi*16);
            }
            #pragma unroll
            for (int cq2 = 0; cq2 < 8; cq2++){
                if (l == 0 && cq2 >= 5) continue;
                u32 koff = (u32)(cq2*32);
                u32 A0[4], A1[4], B[4][4];
                ldsm_x4(A0, aA + koff);
                ldsm_x4(A1, aA + 16*272 + koff);
                #pragma unroll
                for (int jj = 0; jj < 4; jj++) ldsm_x4(B[jj], bAddr[jj] + koff);
                #pragma unroll
                for (int jj = 0; jj < 4; jj++){
                    u32 b0[2] = { B[jj][0], B[jj][2] };
                    u32 b1[2] = { B[jj][1], B[jj][3] };
                    mma16816h(acc[0][2*jj],   A0, b0);
                    mma16816h(acc[0][2*jj+1], A0, b1);
                    mma16816h(acc[1][2*jj],   A1, b0);
                    mma16816h(acc[1][2*jj+1], A1, b1);
                }
            }
        }
        __syncthreads();
        const float* bl = l ? (br + (l-1)*128) : bh;
        hlf* Yg = Sg + (size_t)(128*(l+1))*NP;
        #pragma unroll
        for (int i = 0; i < 2; i++){
            #pragma unroll
            for (int j = 0; j < 8; j++){
                int row = wm*32 + i*16 + qr;
                int col = wn*64 + j*8 + qc*2;
                #pragma unroll
                for (int h = 0; h < 2; h++){
                    int rr = row + h*8;
                    float b0 = bl[rr];
                    float2 av = __half22float2(*(__half2*)&acc[i][j][h]);
                    float v0 = av.x + b0; v0 = v0 > 0.f ? v0 : 0.f;
                    float v1 = av.y + b0; v1 = v1 > 0.f ? v1 : 0.f;
                    if (l > 0){
                        v0 += __half2float(Xt[col*136 + rr]);
                        v1 += __half2float(Xt[(col+1)*136 + rr]);
                    }
                    u32 pk = packh(v0, v1);
                    *(u32*)(Yg + rr*NP + col) = pk;
                    Xt[col*136 + rr]     = ((hlf*)&pk)[0];
                    Xt[(col+1)*136 + rr] = ((hlf*)&pk)[1];
                }
            }
        }
    }
}

// ---- fuse GEMM (f16 accumulate) ----
__global__ void __launch_bounds__(256, 2) k_mma_fuse(
    const hlf* __restrict__ W, const float* __restrict__ bias,
    const hlf* __restrict__ Xbase, hlf* __restrict__ Ybase)
{
    extern __shared__ hlf sm[];
    hlf* Wb[2] = { sm, sm + 128*72 };
    hlf* Bb[2] = { sm + 2*128*72, sm + 3*128*72 };
    int inst = blockIdx.x, mblk = blockIdx.y;
    const hlf* Xg = Xbase + (size_t)inst*(ST_CH*NP);
    hlf* Yg = Ybase + (size_t)inst*(256*NP) + (size_t)mblk*128*NP;
    const hlf* Wm = W + (size_t)mblk*128*KTOT;
    int tid = threadIdx.x, warp = tid >> 5, lane = tid & 31;
    int wm = warp >> 1, wn = warp & 1, qr = lane >> 2, qc = lane & 3;
    int laneRow = lane & 15, laneHi = lane >> 4;
    u32 acc[2][8][2];
    #pragma unroll
    for (int i = 0; i < 2; i++)
        #pragma unroll
        for (int j = 0; j < 8; j++){ acc[i][j][0] = 0u; acc[i][j][1] = 0u; }
    int ph = tid & 63, cc = tid >> 6;

    {
        #pragma unroll
        for (int q = 0; q < 4; q++){
            int idx = q*256 + tid;
            int row = idx >> 3, seg = idx & 7;
            cpa16(s2u(Wb[0] + row*72 + seg*8), Wm + (size_t)row*KTOT + seg*8);
        }
        CP_COMMIT();
        #pragma unroll
        for (int q = 0; q < 16; q++){
            int c = 4*q + cc;
            u32 v = *(const u32*)(Xg + (size_t)c*NP + ph*2);
            Bb[0][(2*ph)*72 + c]   = ((hlf*)&v)[0];
            Bb[0][(2*ph+1)*72 + c] = ((hlf*)&v)[1];
        }
    }
    u32 aWa[2], bBa[2];
    #pragma unroll
    for (int z = 0; z < 2; z++){
        aWa[z] = s2u(Wb[z]) + (u32)((wm*32 + laneRow)*144 + laneHi*16);
        bBa[z] = s2u(Bb[z]) + (u32)((wn*64 + laneRow)*144 + laneHi*16);
    }
    #pragma unroll 1
    for (int chn = 0; chn < 18; chn++){
        CP_WAIT0();
        __syncthreads();
        u32 vreg[16];
        if (chn < 17){
            int k0 = (chn+1)*64;
            #pragma unroll
            for (int q = 0; q < 16; q++)
                vreg[q] = *(const u32*)(Xg + (size_t)(k0 + 4*q + cc)*NP + ph*2);
            hlf* dstw = Wb[(chn+1) & 1];
            const hlf* srcw = Wm + k0;
            #pragma unroll
            for (int q = 0; q < 4; q++){
                int idx = q*256 + tid;
                int row = idx >> 3, seg = idx & 7;
                cpa16(s2u(dstw + row*72 + seg*8), srcw + (size_t)row*KTOT + seg*8);
            }
            CP_COMMIT();
        }
        u32 aA = aWa[chn & 1];
        u32 bA = bBa[chn & 1];
        #pragma unroll
        for (int cq = 0; cq < 4; cq++){
            if (chn == 1 && cq >= 1) continue;
            u32 koff = (u32)(cq*32);
            u32 A0[4], A1[4], B0[4], B1[4];
            ldsm_x4(A0, aA + koff);
            ldsm_x4(A1, aA + 16*144 + koff);
            ldsm_x4(B0, bA + koff);
            ldsm_x4(B1, bA + 16*144 + koff);
            {
                u32 b0[2] = { B0[0], B0[2] }, b1[2] = { B0[1], B0[3] };
                u32 b2[2] = { B1[0], B1[2] }, b3[2] = { B1[1], B1[3] };
                mma16816h(acc[0][0], A0, b0); mma16816h(acc[0][1], A0, b1);
                mma16816h(acc[0][2], A0, b2); mma16816h(acc[0][3], A0, b3);
                mma16816h(acc[1][0], A1, b0); mma16816h(acc[1][1], A1, b1);
                mma16816h(acc[1][2], A1, b2); mma16816h(acc[1][3], A1, b3);
            }
            u32 B2[4], B3[4];
            ldsm_x4(B2, bA + 32*144 + koff);
            ldsm_x4(B3, bA + 48*144 + koff);
            {
                u32 b0[2] = { B2[0], B2[2] }, b1[2] = { B2[1], B2[3] };
                u32 b2[2] = { B3[0], B3[2] }, b3[2] = { B3[1], B3[3] };
                mma16816h(acc[0][4], A0, b0); mma16816h(acc[0][5], A0, b1);
                mma16816h(acc[0][6], A0, b2); mma16816h(acc[0][7], A0, b3);
                mma16816h(acc[1][4], A1, b0); mma16816h(acc[1][5], A1, b1);
                mma16816h(acc[1][6], A1, b2); mma16816h(acc[1][7], A1, b3);
            }
        }
        if (chn < 17){
            hlf* dstb = Bb[(chn+1) & 1];
            #pragma unroll
            for (int q = 0; q < 16; q++){
                int c = 4*q + cc;
                dstb[(2*ph)*72 + c]   = ((hlf*)&vreg[q])[0];
                dstb[(2*ph+1)*72 + c] = ((hlf*)&vreg[q])[1];
            }
        }
    }
    #pragma unroll
    for (int i = 0; i < 2; i++){
        #pragma unroll
        for (int j = 0; j < 8; j++){
            int row = wm*32 + i*16 + qr;
            int col = wn*64 + j*8 + qc*2;
            #pragma unroll
            for (int h = 0; h < 2; h++){
                int rr = row + h*8;
                float b0 = bias[mblk*128 + rr];
                float2 av = __half22float2(*(__half2*)&acc[i][j][h]);
                float v0 = av.x + b0; v0 = v0 > 0.f ? v0 : 0.f;
                float v1 = av.y + b0; v1 = v1 > 0.f ? v1 : 0.f;
                *(u32*)(Yg + rr*NP + col) = packh(v0, v1);
            }
        }
    }
}

// ---------------- fused tail: p1 (HMMA 256->64) + p2 (64->2) + pts update ----------------
__global__ void __launch_bounds__(256, 2) k_tail(
    const hlf* __restrict__ W, const float* __restrict__ bias,
    const float* __restrict__ w2, const float* __restrict__ b2)
{
    extern __shared__ hlf sm[];
    hlf* Wb[2] = { sm, sm + 64*72 };
    hlf* Bb[2] = { sm + 2*64*72, sm + 2*64*72 + 128*72 };
    float* hbufS = (float*)sm;
    int inst = blockIdx.x;
    const hlf* Xg = g_fuse + (size_t)inst*(256*NP);
    int tid = threadIdx.x, warp = tid >> 5, lane = tid & 31;
    int wm = warp >> 2, wn = warp & 3, qr = lane >> 2, qc = lane & 3;
    int laneRow = lane & 15, laneHi = lane >> 4;
    u32 acc[2][4][2];
    #pragma unroll
    for (int i = 0; i < 2; i++)
        #pragma unroll
        for (int j = 0; j < 4; j++){ acc[i][j][0] = 0u; acc[i][j][1] = 0u; }
    int ph = tid & 63, cc = tid >> 6;

    {
        #pragma unroll
        for (int q = 0; q < 2; q++){
            int idx = q*256 + tid;
            int row = idx >> 3, seg = idx & 7;
            cpa16(s2u(Wb[0] + row*72 + seg*8), W + (size_t)row*256 + seg*8);
        }
        CP_COMMIT();
        #pragma unroll
        for (int q = 0; q < 16; q++){
            int c = 4*q + cc;
            u32 v = *(const u32*)(Xg + (size_t)c*NP + ph*2);
            Bb[0][(2*ph)*72 + c]   = ((hlf*)&v)[0];
            Bb[0][(2*ph+1)*72 + c] = ((hlf*)&v)[1];
        }
    }
    u32 aWa[2], bBa[2];
    #pragma unroll
    for (int z = 0; z < 2; z++){
        aWa[z] = s2u(Wb[z]) + (u32)((wm*32 + laneRow)*144 + laneHi*16);
        bBa[z] = s2u(Bb[z]) + (u32)((wn*32 + laneRow)*144 + laneHi*16);
    }
    #pragma unroll 1
    for (int chn = 0; chn < 4; chn++){
        CP_WAIT0();
        __syncthreads();
        u32 vreg[16];
        if (chn < 3){
            int k0 = (chn+1)*64;
            #pragma unroll
            for (int q = 0; q < 16; q++)
                vreg[q] = *(const u32*)(Xg + (size_t)(k0 + 4*q + cc)*NP + ph*2);
            hlf* dstw = Wb[(chn+1) & 1];
            const hlf* srcw = W + k0;
            #pragma unroll
            for (int q = 0; q < 2; q++){
                int idx = q*256 + tid;
                int row = idx >> 3, seg = idx & 7;
                cpa16(s2u(dstw + row*72 + seg*8), srcw + (size_t)row*256 + seg*8);
            }
            CP_COMMIT();
        }
        u32 aA = aWa[chn & 1];
        u32 bA = bBa[chn & 1];
        #pragma unroll
        for (int cq = 0; cq < 4; cq++){
            u32 koff = (u32)(cq*32);
            u32 A0[4], A1[4], B0[4], B1[4];
            ldsm_x4(A0, aA + koff);
            ldsm_x4(A1, aA + 16*144 + koff);
            ldsm_x4(B0, bA + koff);
            ldsm_x4(B1, bA + 16*144 + koff);
            {
                u32 b0[2] = { B0[0], B0[2] }, b1[2] = { B0[1], B0[3] };
                u32 b2[2] = { B1[0], B1[2] }, b3[2] = { B1[1], B1[3] };
                mma16816h(acc[0][0], A0, b0); mma16816h(acc[0][1], A0, b1);
                mma16816h(acc[0][2], A0, b2); mma16816h(acc[0][3], A0, b3);
                mma16816h(acc[1][0], A1, b0); mma16816h(acc[1][1], A1, b1);
                mma16816h(acc[1][2], A1, b2); mma16816h(acc[1][3], A1, b3);
            }
        }
        if (chn < 3){
            hlf* dstb = Bb[(chn+1) & 1];
            #pragma unroll
            for (int q = 0; q < 16; q++){
                int c = 4*q + cc;
                dstb[(2*ph)*72 + c]   = ((hlf*)&vreg[q])[0];
                dstb[(2*ph+1)*72 + c] = ((hlf*)&vreg[q])[1];
            }
        }
    }
    __syncthreads();
    #pragma unroll
    for (int i = 0; i < 2; i++){
        #pragma unroll
        for (int j = 0; j < 4; j++){
            int row = wm*32 + i*16 + qr;
            int col = wn*32 + j*8 + qc*2;
            #pragma unroll
            for (int h = 0; h < 2; h++){
                int rr = row + h*8;
                float b0 = bias[rr];
                float2 av = __half22float2(*(__half2*)&acc[i][j][h]);
                float v0 = av.x + b0; v0 = v0 > 0.f ? v0 : 0.f;
                float v1 = av.y + b0; v1 = v1 > 0.f ? v1 : 0.f;
                *(float2*)(hbufS + rr*132 + col) = make_float2(v0, v1);
            }
        }
    }
    __syncthreads();
    {
        int p = tid & 127, which = tid >> 7;
        const float* w = w2 + which*64;
        float a = 0.f;
        for (int c = 0; c < 64; c++)
            a += w[c]*hbufS[c*132 + p];
        g_pts[(inst*NP + p)*2 + which] += a + b2[which];
    }
}

// ---------------- output assembly ----------------
__global__ void k_out(float* __restrict__ out){
    int i = blockIdx.x*blockDim.x + threadIdx.x;
    const int n_det = NINST*6;
    const int n_ct  = NINST*2;
    const int n_pts = NINST*NP*2;
    if (i < n_det){ out[i] = g_det[i]; return; }
    int j = i - n_det;
    if (j < n_ct){ out[i] = g_ct[j]; return; }
    j -= n_ct;
    if (j < n_pts){
        int inst = j / (NP*2);
        out[i] = g_valid[inst] ? g_pts[j] : 0.0f;
        return;
    }
    j -= n_pts;
    if (j < NINST) out[i] = g_valid[j] ? 1.0f : 0.0f;
}

// ---------------- host launcher ----------------
extern "C" void kernel_launch(void* const* d_in, const int* in_sizes, int n_in,
                              void* d_out, int out_size)
{
    const float* pred   = (const float*)d_in[0];
    const float* feat   = (const float*)d_in[1];
    const float* conv_w = (const float*)d_in[2];
    const float* conv_b = (const float*)d_in[3];
    const float* b_head = (const float*)d_in[5];
    const float* b_res  = (const float*)d_in[7];
    const float* b_fuse = (const float*)d_in[9];
    const float* b_p1   = (const float*)d_in[11];
    const float* w_p2   = (const float*)d_in[12];
    const float* b_p2   = (const float*)d_in[13];

    cudaFuncSetAttribute(k_topk, cudaFuncAttributeMaxDynamicSharedMemorySize, 26400*8);
    cudaFuncSetAttribute(k_snake, cudaFuncAttributeMaxDynamicSharedMemorySize, 104448);
    cudaFuncSetAttribute(k_mma_fuse, cudaFuncAttributeMaxDynamicSharedMemorySize, 73728);
    cudaFuncSetAttribute(k_tail, cudaFuncAttributeMaxDynamicSharedMemorySize, 55296);

    void *pv;
    cudaGetSymbolAddress(&pv, g_states); hlf* p_states = (hlf*)pv;
    cudaGetSymbolAddress(&pv, g_fuse);   hlf* p_fuse = (hlf*)pv;
    cudaGetSymbolAddress(&pv, g_whb);    hlf* p_whb = (hlf*)pv;
    cudaGetSymbolAddress(&pv, g_wrb);    hlf* p_wrb = (hlf*)pv;
    cudaGetSymbolAddress(&pv, g_wfb);    hlf* p_wfb = (hlf*)pv;
    cudaGetSymbolAddress(&pv, g_wp1b);   hlf* p_wp1b = (hlf*)pv;

    cudaStream_t s1;
    cudaStreamCreate(&s1);
    cudaEvent_t e0, e1;
    cudaEventCreateWithFlags(&e0, cudaEventDisableTiming);
    cudaEventCreateWithFlags(&e1, cudaEventDisableTiming);

    cudaEventRecord(e0, 0);
    cudaStreamWaitEvent(s1, e0, 0);
    k_up<<<(int)(((long long)NB*128*160*160 + 255)/256), 256, 0, s1>>>(feat);
    k_conv3<<<dim3(400, NB), 512, 0, s1>>>(conv_w, conv_b);
    cudaEventRecord(e1, s1);

    {
        int n = 128*KTOT + 7*128*KTOT + 256*KTOT + 64*256;
        k_wtrans<<<(n + 255)/256, 256>>>((const float*)d_in[4], (const float*)d_in[6],
                                         (const float*)d_in[8], (const float*)d_in[10]);
    }
    {
        long long n = (long long)NINST*62*64;
        k_zinit<<<(int)((n + 255)/256), 256>>>();
    }
    k_scores<<<(NB*NPRED + 255)/256, 256>>>(pred);
    k_topk<<<NB, 1024, 26400*8>>>();
    k_prep<<<(NINST + 255)/256, 256>>>(pred);
    k_nms<<<NB, 256>>>();
    k_initpts<<<(NINST*NP + 255)/256, 256>>>();

    cudaStreamWaitEvent(0, e1, 0);

    for (int it = 0; it < 2; it++){
        k_snake<<<NINST, 256, 104448>>>(p_whb, p_wrb, b_head, b_res, p_states);
        k_mma_fuse<<<dim3(NINST, 2), 256, 73728>>>(p_wfb, b_fuse, p_states, p_fuse);
        k_tail<<<NINST, 256, 55296>>>(p_wp1b, b_p1, w_p2, b_p2);
    }
    {
        int n = NINST*6 + NINST*2 + NINST*NP*2 + NINST;
        k_out<<<(n + 255)/256, 256>>>((float*)d_out);
    }
}